// round 1
// baseline (speedup 1.0000x reference)
#include <cuda_runtime.h>

#define HW 65536          // 256*256 tokens
#define C_FULL 256
#define C_HALF 128

// Scratch (device globals; allocation-free rule)
__device__ float g_xn[HW * C_FULL];          // LN1 output, NHWC
__device__ float g_x1[HW * C_FULL];          // branch outputs (xn_half + proj(attn)), NHWC
__device__ float g_bias[2 * 2 * 64 * 64];    // [branch][head][n][m] rel-pos bias

// ---------------------------------------------------------------------------
// LN1: read x NCHW, write normalized NHWC to g_xn
// ---------------------------------------------------------------------------
__global__ void __launch_bounds__(256) ln1_kernel(const float* __restrict__ x,
                                                  const float* __restrict__ g,
                                                  const float* __restrict__ b) {
    __shared__ float s[256][33];
    __shared__ float mu[32], rs[32];
    int t0 = blockIdx.x * 32;
    int tid = threadIdx.x, lane = tid & 31, wid = tid >> 5;

    #pragma unroll
    for (int c = wid; c < 256; c += 8)
        s[c][lane] = x[c * HW + t0 + lane];
    __syncthreads();

    for (int it = 0; it < 4; it++) {
        int tok = wid * 4 + it;
        float sum = 0.f, sq = 0.f;
        #pragma unroll
        for (int j = 0; j < 8; j++) { float v = s[lane + 32 * j][tok]; sum += v; sq += v * v; }
        #pragma unroll
        for (int o = 16; o; o >>= 1) {
            sum += __shfl_down_sync(~0u, sum, o);
            sq  += __shfl_down_sync(~0u, sq, o);
        }
        if (lane == 0) {
            float m = sum * (1.f / 256.f);
            float var = sq * (1.f / 256.f) - m * m;
            mu[tok] = m; rs[tok] = rsqrtf(var + 1e-5f);
        }
    }
    __syncthreads();

    int c = tid;
    float gc = g[c], bc = b[c];
    for (int k = 0; k < 32; k++)
        g_xn[(t0 + k) * 256 + c] = (s[c][k] - mu[k]) * rs[k] * gc + bc;
}

// ---------------------------------------------------------------------------
// Precompute relative-position bias tables: g_bias[br][h][n][m]
// ---------------------------------------------------------------------------
__global__ void bias_kernel(const float* __restrict__ tr, const float* __restrict__ ta) {
    for (int idx = threadIdx.x; idx < 16384; idx += blockDim.x) {
        int br = idx >> 13, rem = idx & 8191;
        int h = rem >> 12, n = (rem >> 6) & 63, m = rem & 63;
        int Wh = br ? 4 : 16, Ww = br ? 16 : 4, lg = br ? 4 : 2;
        int r1 = n >> lg, c1 = n & (Ww - 1);
        int r2 = m >> lg, c2 = m & (Ww - 1);
        int ridx = (r1 - r2 + Wh - 1) * (2 * Ww - 1) + (c1 - c2 + Ww - 1);
        const float* t = br ? ta : tr;
        g_bias[idx] = t[ridx * 2 + h];
    }
}

// ---------------------------------------------------------------------------
// Window attention, both branches (blockIdx.y selects branch), 1 block/window
// ---------------------------------------------------------------------------
__global__ void __launch_bounds__(256) attn_kernel(
    const float* __restrict__ Wq_r, const float* __restrict__ Wp_r, const float* __restrict__ bp_r,
    const float* __restrict__ Wq_a, const float* __restrict__ Wp_a, const float* __restrict__ bp_a)
{
    extern __shared__ float sm[];
    float* xsT = sm;                 // [128][68] xn half, transposed (k-major)
    float* qT  = sm + 8704;          // [128][68] q[hd][n]
    float* kT  = sm + 2 * 8704;      // [128][68] k[hd][m]
    float* OT  = sm + 3 * 8704;      // [128][68] attn out transposed
    float* PT  = sm + 4 * 8704;      // [2*64][68] P[h*64+m][n]
    float* vR  = sm + 5 * 8704;      // [64][128] v[m][col]

    int br = blockIdx.y;
    int co  = br ? 128 : 0;
    int lg  = br ? 4 : 2;            // log2 Ww
    int Ww  = 1 << lg;
    int nWb = br ? 16 : 64;          // windows along W
    int Wh  = br ? 4 : 16;
    const float* Wq = br ? Wq_a : Wq_r;
    const float* Wp = br ? Wp_a : Wp_r;
    const float* bp = br ? bp_a : bp_r;

    int wi = blockIdx.x;
    int hb = wi / nWb, wb = wi - hb * nWb;
    int h0 = hb * Wh, w0 = wb * Ww;
    int tid = threadIdx.x;

    // ---- load window tile transposed ----
    for (int idx = tid; idx < 64 * 128; idx += 256) {
        int n = idx >> 7, k = idx & 127;
        int t = ((h0 + (n >> lg)) << 8) + w0 + (n & (Ww - 1));
        xsT[k * 68 + n] = g_xn[t * 256 + co + k];
    }
    __syncthreads();

    // ---- QKV: qkv[n][col] = sum_k xs[n][k]*Wq[k][col], 384 cols in 2 passes ----
    for (int p = 0; p < 2; p++) {
        int col = p ? 256 + tid : tid;
        if (col < 384) {
            float acc[64];
            #pragma unroll
            for (int r = 0; r < 64; r++) acc[r] = 0.f;
            const float* wptr = Wq + col;
            for (int k = 0; k < 128; k++) {
                float w = wptr[k * 384];
                const float4* xr = (const float4*)(xsT + k * 68);
                #pragma unroll
                for (int r4 = 0; r4 < 16; r4++) {
                    float4 xv = xr[r4];
                    acc[4 * r4 + 0] += xv.x * w; acc[4 * r4 + 1] += xv.y * w;
                    acc[4 * r4 + 2] += xv.z * w; acc[4 * r4 + 3] += xv.w * w;
                }
            }
            if (col < 128) {
                #pragma unroll
                for (int n = 0; n < 64; n++) qT[col * 68 + n] = acc[n];
            } else if (col < 256) {
                #pragma unroll
                for (int n = 0; n < 64; n++) kT[(col - 128) * 68 + n] = acc[n];
            } else {
                #pragma unroll
                for (int n = 0; n < 64; n++) vR[n * 128 + (col - 256)] = acc[n];
            }
        }
    }
    __syncthreads();

    // ---- S = q k^T * scale + bias; softmax; write P transposed ----
    if (tid < 128) {
        int h = tid >> 6, n = tid & 63;
        float acc[64];
        #pragma unroll
        for (int m = 0; m < 64; m++) acc[m] = 0.f;
        for (int d = 0; d < 64; d++) {
            float qv = qT[(h * 64 + d) * 68 + n];
            const float4* kr = (const float4*)(kT + (h * 64 + d) * 68);
            #pragma unroll
            for (int m4 = 0; m4 < 16; m4++) {
                float4 kv = kr[m4];
                acc[4 * m4 + 0] += qv * kv.x; acc[4 * m4 + 1] += qv * kv.y;
                acc[4 * m4 + 2] += qv * kv.z; acc[4 * m4 + 3] += qv * kv.w;
            }
        }
        const float4* bptr = (const float4*)(g_bias + ((br * 2 + h) * 64 + n) * 64);
        #pragma unroll
        for (int m4 = 0; m4 < 16; m4++) {
            float4 bv = bptr[m4];
            acc[4 * m4 + 0] = acc[4 * m4 + 0] * 0.125f + bv.x;
            acc[4 * m4 + 1] = acc[4 * m4 + 1] * 0.125f + bv.y;
            acc[4 * m4 + 2] = acc[4 * m4 + 2] * 0.125f + bv.z;
            acc[4 * m4 + 3] = acc[4 * m4 + 3] * 0.125f + bv.w;
        }
        float mx = -1e30f;
        #pragma unroll
        for (int m = 0; m < 64; m++) mx = fmaxf(mx, acc[m]);
        float ssum = 0.f;
        #pragma unroll
        for (int m = 0; m < 64; m++) { float e = expf(acc[m] - mx); acc[m] = e; ssum += e; }
        float inv = 1.f / ssum;
        #pragma unroll
        for (int m = 0; m < 64; m++) PT[(h * 64 + m) * 68 + n] = acc[m] * inv;
    }
    __syncthreads();

    // ---- O = P @ V (per head), write transposed ----
    if (tid < 128) {
        int j = tid, h = j >> 6;
        float acc[64];
        #pragma unroll
        for (int n = 0; n < 64; n++) acc[n] = 0.f;
        for (int m = 0; m < 64; m++) {
            float vv = vR[m * 128 + j];
            const float4* pr = (const float4*)(PT + (h * 64 + m) * 68);
            #pragma unroll
            for (int n4 = 0; n4 < 16; n4++) {
                float4 pv = pr[n4];
                acc[4 * n4 + 0] += pv.x * vv; acc[4 * n4 + 1] += pv.y * vv;
                acc[4 * n4 + 2] += pv.z * vv; acc[4 * n4 + 3] += pv.w * vv;
            }
        }
        #pragma unroll
        for (int n = 0; n < 64; n++) OT[j * 68 + n] = acc[n];
    }
    __syncthreads();

    // ---- proj + in-branch residual, write to g_x1 ----
    if (tid < 128) {
        int cc = tid;
        float acc[64];
        #pragma unroll
        for (int n = 0; n < 64; n++) acc[n] = 0.f;
        for (int k = 0; k < 128; k++) {
            float w = Wp[k * 128 + cc];
            const float4* orow = (const float4*)(OT + k * 68);
            #pragma unroll
            for (int n4 = 0; n4 < 16; n4++) {
                float4 ov = orow[n4];
                acc[4 * n4 + 0] += ov.x * w; acc[4 * n4 + 1] += ov.y * w;
                acc[4 * n4 + 2] += ov.z * w; acc[4 * n4 + 3] += ov.w * w;
            }
        }
        float bb = bp[cc];
        for (int n = 0; n < 64; n++) {
            int t = ((h0 + (n >> lg)) << 8) + w0 + (n & (Ww - 1));
            g_x1[t * 256 + co + cc] = acc[n] + bb + xsT[cc * 68 + n];
        }
    }
}

// ---------------------------------------------------------------------------
// Fused: x_full = idt + branch_out; LN2; MLP(1024, exact GELU); residual;
// write final output NCHW.  64 tokens per block.
// ---------------------------------------------------------------------------
__global__ void __launch_bounds__(256) mlp_kernel(
    const float* __restrict__ x, const float* __restrict__ g2, const float* __restrict__ b2,
    const float* __restrict__ W1, const float* __restrict__ b1,
    const float* __restrict__ W2, const float* __restrict__ b2o, float* __restrict__ out)
{
    extern __shared__ float sm[];
    float* xfT = sm;                     // [256][68] x_full transposed
    float* xnT = sm + 17408;             // [256][68] LN2 output transposed
    float* HsT = sm + 2 * 17408;         // [128][68] hidden chunk (gelu'd)
    float* HsP = sm + 2 * 17408 + 8704;  // [128][68] seg-1 partials
    float* mu  = sm + 2 * 17408 + 2 * 8704;
    float* rs  = mu + 64;

    int t0 = blockIdx.x * 64;
    int tid = threadIdx.x;

    // x_full = x (NCHW) + g_x1 (NHWC)
    for (int idx = tid; idx < 16384; idx += 256) {
        int c = idx >> 6, n = idx & 63;
        xfT[c * 68 + n] = x[c * HW + t0 + n];
    }
    __syncthreads();
    for (int k = 0; k < 64; k++)
        xfT[tid * 68 + k] += g_x1[(t0 + k) * 256 + tid];
    __syncthreads();

    // LN2 stats (4 threads per token)
    {
        int tok = tid >> 2, part = tid & 3;
        float sum = 0.f, sq = 0.f;
        for (int i = 0; i < 64; i++) {
            float v = xfT[(part * 64 + i) * 68 + tok];
            sum += v; sq += v * v;
        }
        sum += __shfl_down_sync(~0u, sum, 2); sq += __shfl_down_sync(~0u, sq, 2);
        sum += __shfl_down_sync(~0u, sum, 1); sq += __shfl_down_sync(~0u, sq, 1);
        if (part == 0) {
            float m = sum * (1.f / 256.f);
            mu[tok] = m;
            rs[tok] = rsqrtf(sq * (1.f / 256.f) - m * m + 1e-5f);
        }
    }
    __syncthreads();

    for (int idx = tid; idx < 16384; idx += 256) {
        int c = idx >> 6, n = idx & 63;
        xnT[c * 68 + n] = (xfT[c * 68 + n] - mu[n]) * rs[n] * g2[c] + b2[c];
    }
    __syncthreads();

    float accO[64];
    #pragma unroll
    for (int n = 0; n < 64; n++) accO[n] = 0.f;
    int jloc = tid & 127, seg = tid >> 7;

    for (int hb = 0; hb < 8; hb++) {
        // GEMM1 half-K per seg
        float accH[64];
        #pragma unroll
        for (int n = 0; n < 64; n++) accH[n] = 0.f;
        int jg = hb * 128 + jloc;
        const float* w1p = W1 + jg + (seg * 128) * 1024;
        for (int kk = 0; kk < 128; kk++) {
            float w = w1p[kk * 1024];
            const float4* xr = (const float4*)(xnT + (seg * 128 + kk) * 68);
            #pragma unroll
            for (int n4 = 0; n4 < 16; n4++) {
                float4 xv = xr[n4];
                accH[4 * n4 + 0] += xv.x * w; accH[4 * n4 + 1] += xv.y * w;
                accH[4 * n4 + 2] += xv.z * w; accH[4 * n4 + 3] += xv.w * w;
            }
        }
        float* dst = seg ? HsP : HsT;
        #pragma unroll
        for (int n = 0; n < 64; n++) dst[jloc * 68 + n] = accH[n];
        __syncthreads();

        // combine + bias + exact GELU
        for (int idx = tid; idx < 8192; idx += 256) {
            int j = idx >> 6, n = idx & 63;
            float hv = HsT[j * 68 + n] + HsP[j * 68 + n] + b1[hb * 128 + j];
            hv = 0.5f * hv * (1.f + erff(hv * 0.70710678118f));
            HsT[j * 68 + n] = hv;
        }
        __syncthreads();

        // GEMM2 accumulate (one output column per thread)
        const float* w2p = W2 + hb * 128 * 256 + tid;
        for (int j = 0; j < 128; j++) {
            float w = w2p[j * 256];
            const float4* hr = (const float4*)(HsT + j * 68);
            #pragma unroll
            for (int n4 = 0; n4 < 16; n4++) {
                float4 hv = hr[n4];
                accO[4 * n4 + 0] += hv.x * w; accO[4 * n4 + 1] += hv.y * w;
                accO[4 * n4 + 2] += hv.z * w; accO[4 * n4 + 3] += hv.w * w;
            }
        }
        __syncthreads();
    }

    // epilogue: residual, stage through smem for coalesced NCHW writes
    {
        float bb = b2o[tid];
        #pragma unroll
        for (int n = 0; n < 64; n++)
            xnT[tid * 68 + n] = accO[n] + bb + xfT[tid * 68 + n];
    }
    __syncthreads();
    for (int idx = tid; idx < 16384; idx += 256) {
        int c = idx >> 6, n = idx & 63;
        out[c * HW + t0 + n] = xnT[c * 68 + n];
    }
}

// ---------------------------------------------------------------------------
extern "C" void kernel_launch(void* const* d_in, const int* in_sizes, int n_in,
                              void* d_out, int out_size) {
    const float* x        = (const float*)d_in[0];
    const float* norm1_g  = (const float*)d_in[1];
    const float* norm1_b  = (const float*)d_in[2];
    const float* qkv_r    = (const float*)d_in[3];
    const float* proj_r_w = (const float*)d_in[4];
    const float* proj_r_b = (const float*)d_in[5];
    const float* table_r  = (const float*)d_in[6];
    const float* qkv_a    = (const float*)d_in[7];
    const float* proj_a_w = (const float*)d_in[8];
    const float* proj_a_b = (const float*)d_in[9];
    const float* table_a  = (const float*)d_in[10];
    const float* norm2_g  = (const float*)d_in[11];
    const float* norm2_b  = (const float*)d_in[12];
    const float* mlp_w1   = (const float*)d_in[13];
    const float* mlp_b1   = (const float*)d_in[14];
    const float* mlp_w2   = (const float*)d_in[15];
    const float* mlp_b2   = (const float*)d_in[16];
    float* out = (float*)d_out;

    const int ATTN_SMEM = (5 * 8704 + 64 * 128) * 4;                 // 206848 B
    const int MLP_SMEM  = (2 * 17408 + 2 * 8704 + 128) * 4;          // 209408 B
    cudaFuncSetAttribute(attn_kernel, cudaFuncAttributeMaxDynamicSharedMemorySize, ATTN_SMEM);
    cudaFuncSetAttribute(mlp_kernel,  cudaFuncAttributeMaxDynamicSharedMemorySize, MLP_SMEM);

    ln1_kernel<<<2048, 256>>>(x, norm1_g, norm1_b);
    bias_kernel<<<1, 256>>>(table_r, table_a);
    attn_kernel<<<dim3(1024, 2), 256, ATTN_SMEM>>>(qkv_r, proj_r_w, proj_r_b,
                                                   qkv_a, proj_a_w, proj_a_b);
    mlp_kernel<<<1024, 256, MLP_SMEM>>>(x, norm2_g, norm2_b,
                                        mlp_w1, mlp_b1, mlp_w2, mlp_b2, out);
}

// round 2
// speedup vs baseline: 1.0083x; 1.0083x over previous
#include <cuda_runtime.h>

#define HW 65536          // 256*256 tokens
#define C_FULL 256
#define C_HALF 128

// Scratch (device globals; allocation-free rule)
__device__ float g_xn[HW * C_FULL];          // LN1 output, NHWC
__device__ float g_x1[HW * C_FULL];          // branch outputs (xn_half + proj(attn)), NHWC
__device__ float g_bias[2 * 2 * 64 * 64];    // [branch][head][n][m] rel-pos bias

// ---------------------------------------------------------------------------
// LN1: read x NCHW, write normalized NHWC to g_xn
// ---------------------------------------------------------------------------
__global__ void __launch_bounds__(256) ln1_kernel(const float* __restrict__ x,
                                                  const float* __restrict__ g,
                                                  const float* __restrict__ b) {
    __shared__ float s[256][33];
    __shared__ float mu[32], rs[32];
    int t0 = blockIdx.x * 32;
    int tid = threadIdx.x, lane = tid & 31, wid = tid >> 5;

    #pragma unroll
    for (int c = wid; c < 256; c += 8)
        s[c][lane] = x[c * HW + t0 + lane];
    __syncthreads();

    for (int it = 0; it < 4; it++) {
        int tok = wid * 4 + it;
        float sum = 0.f, sq = 0.f;
        #pragma unroll
        for (int j = 0; j < 8; j++) { float v = s[lane + 32 * j][tok]; sum += v; sq += v * v; }
        #pragma unroll
        for (int o = 16; o; o >>= 1) {
            sum += __shfl_down_sync(~0u, sum, o);
            sq  += __shfl_down_sync(~0u, sq, o);
        }
        if (lane == 0) {
            float m = sum * (1.f / 256.f);
            float var = sq * (1.f / 256.f) - m * m;
            mu[tok] = m; rs[tok] = rsqrtf(var + 1e-5f);
        }
    }
    __syncthreads();

    int c = tid;
    float gc = g[c], bc = b[c];
    for (int k = 0; k < 32; k++)
        g_xn[(t0 + k) * 256 + c] = (s[c][k] - mu[k]) * rs[k] * gc + bc;
}

// ---------------------------------------------------------------------------
// Precompute relative-position bias tables: g_bias[br][h][n][m]
// ---------------------------------------------------------------------------
__global__ void bias_kernel(const float* __restrict__ tr, const float* __restrict__ ta) {
    for (int idx = threadIdx.x; idx < 16384; idx += blockDim.x) {
        int br = idx >> 13, rem = idx & 8191;
        int h = rem >> 12, n = (rem >> 6) & 63, m = rem & 63;
        int Wh = br ? 4 : 16, Ww = br ? 16 : 4, lg = br ? 4 : 2;
        int r1 = n >> lg, c1 = n & (Ww - 1);
        int r2 = m >> lg, c2 = m & (Ww - 1);
        int ridx = (r1 - r2 + Wh - 1) * (2 * Ww - 1) + (c1 - c2 + Ww - 1);
        const float* t = br ? ta : tr;
        g_bias[idx] = t[ridx * 2 + h];
    }
}

// ---------------------------------------------------------------------------
// Window attention, both branches (blockIdx.y selects branch), 1 block/window
// ---------------------------------------------------------------------------
__global__ void __launch_bounds__(256) attn_kernel(
    const float* __restrict__ Wq_r, const float* __restrict__ Wp_r, const float* __restrict__ bp_r,
    const float* __restrict__ Wq_a, const float* __restrict__ Wp_a, const float* __restrict__ bp_a)
{
    extern __shared__ float sm[];
    float* xsT = sm;                 // [128][68] xn half, transposed (k-major)
    float* qT  = sm + 8704;          // [128][68] q[hd][n]
    float* kT  = sm + 2 * 8704;      // [128][68] k[hd][m]
    float* OT  = sm + 3 * 8704;      // [128][68] attn out transposed
    float* PT  = sm + 4 * 8704;      // [2*64][68] P[h*64+m][n]
    float* vR  = sm + 5 * 8704;      // [64][128] v[m][col]

    int br = blockIdx.y;
    int co  = br ? 128 : 0;
    int lg  = br ? 4 : 2;            // log2 Ww
    int Ww  = 1 << lg;
    int nWb = br ? 16 : 64;          // windows along W
    int Wh  = br ? 4 : 16;
    const float* Wq = br ? Wq_a : Wq_r;
    const float* Wp = br ? Wp_a : Wp_r;
    const float* bp = br ? bp_a : bp_r;

    int wi = blockIdx.x;
    int hb = wi / nWb, wb = wi - hb * nWb;
    int h0 = hb * Wh, w0 = wb * Ww;
    int tid = threadIdx.x;

    // ---- load window tile transposed ----
    for (int idx = tid; idx < 64 * 128; idx += 256) {
        int n = idx >> 7, k = idx & 127;
        int t = ((h0 + (n >> lg)) << 8) + w0 + (n & (Ww - 1));
        xsT[k * 68 + n] = g_xn[t * 256 + co + k];
    }
    __syncthreads();

    // ---- QKV: qkv[n][col] = sum_k xs[n][k]*Wq[k][col], 384 cols in 2 passes ----
    for (int p = 0; p < 2; p++) {
        int col = p ? 256 + tid : tid;
        if (col < 384) {
            float acc[64];
            #pragma unroll
            for (int r = 0; r < 64; r++) acc[r] = 0.f;
            const float* wptr = Wq + col;
            for (int k = 0; k < 128; k++) {
                float w = wptr[k * 384];
                const float4* xr = (const float4*)(xsT + k * 68);
                #pragma unroll
                for (int r4 = 0; r4 < 16; r4++) {
                    float4 xv = xr[r4];
                    acc[4 * r4 + 0] += xv.x * w; acc[4 * r4 + 1] += xv.y * w;
                    acc[4 * r4 + 2] += xv.z * w; acc[4 * r4 + 3] += xv.w * w;
                }
            }
            if (col < 128) {
                #pragma unroll
                for (int n = 0; n < 64; n++) qT[col * 68 + n] = acc[n];
            } else if (col < 256) {
                #pragma unroll
                for (int n = 0; n < 64; n++) kT[(col - 128) * 68 + n] = acc[n];
            } else {
                #pragma unroll
                for (int n = 0; n < 64; n++) vR[n * 128 + (col - 256)] = acc[n];
            }
        }
    }
    __syncthreads();

    // ---- S = q k^T * scale + bias; softmax; write P transposed ----
    if (tid < 128) {
        int h = tid >> 6, n = tid & 63;
        float acc[64];
        #pragma unroll
        for (int m = 0; m < 64; m++) acc[m] = 0.f;
        for (int d = 0; d < 64; d++) {
            float qv = qT[(h * 64 + d) * 68 + n];
            const float4* kr = (const float4*)(kT + (h * 64 + d) * 68);
            #pragma unroll
            for (int m4 = 0; m4 < 16; m4++) {
                float4 kv = kr[m4];
                acc[4 * m4 + 0] += qv * kv.x; acc[4 * m4 + 1] += qv * kv.y;
                acc[4 * m4 + 2] += qv * kv.z; acc[4 * m4 + 3] += qv * kv.w;
            }
        }
        const float4* bptr = (const float4*)(g_bias + ((br * 2 + h) * 64 + n) * 64);
        #pragma unroll
        for (int m4 = 0; m4 < 16; m4++) {
            float4 bv = bptr[m4];
            acc[4 * m4 + 0] = acc[4 * m4 + 0] * 0.125f + bv.x;
            acc[4 * m4 + 1] = acc[4 * m4 + 1] * 0.125f + bv.y;
            acc[4 * m4 + 2] = acc[4 * m4 + 2] * 0.125f + bv.z;
            acc[4 * m4 + 3] = acc[4 * m4 + 3] * 0.125f + bv.w;
        }
        float mx = -1e30f;
        #pragma unroll
        for (int m = 0; m < 64; m++) mx = fmaxf(mx, acc[m]);
        float ssum = 0.f;
        #pragma unroll
        for (int m = 0; m < 64; m++) { float e = expf(acc[m] - mx); acc[m] = e; ssum += e; }
        float inv = 1.f / ssum;
        #pragma unroll
        for (int m = 0; m < 64; m++) PT[(h * 64 + m) * 68 + n] = acc[m] * inv;
    }
    __syncthreads();

    // ---- O = P @ V (per head), write transposed ----
    if (tid < 128) {
        int j = tid, h = j >> 6;
        float acc[64];
        #pragma unroll
        for (int n = 0; n < 64; n++) acc[n] = 0.f;
        for (int m = 0; m < 64; m++) {
            float vv = vR[m * 128 + j];
            const float4* pr = (const float4*)(PT + (h * 64 + m) * 68);
            #pragma unroll
            for (int n4 = 0; n4 < 16; n4++) {
                float4 pv = pr[n4];
                acc[4 * n4 + 0] += pv.x * vv; acc[4 * n4 + 1] += pv.y * vv;
                acc[4 * n4 + 2] += pv.z * vv; acc[4 * n4 + 3] += pv.w * vv;
            }
        }
        #pragma unroll
        for (int n = 0; n < 64; n++) OT[j * 68 + n] = acc[n];
    }
    __syncthreads();

    // ---- proj + in-branch residual, write to g_x1 ----
    if (tid < 128) {
        int cc = tid;
        float acc[64];
        #pragma unroll
        for (int n = 0; n < 64; n++) acc[n] = 0.f;
        for (int k = 0; k < 128; k++) {
            float w = Wp[k * 128 + cc];
            const float4* orow = (const float4*)(OT + k * 68);
            #pragma unroll
            for (int n4 = 0; n4 < 16; n4++) {
                float4 ov = orow[n4];
                acc[4 * n4 + 0] += ov.x * w; acc[4 * n4 + 1] += ov.y * w;
                acc[4 * n4 + 2] += ov.z * w; acc[4 * n4 + 3] += ov.w * w;
            }
        }
        float bb = bp[cc];
        for (int n = 0; n < 64; n++) {
            int t = ((h0 + (n >> lg)) << 8) + w0 + (n & (Ww - 1));
            g_x1[t * 256 + co + cc] = acc[n] + bb + xsT[cc * 68 + n];
        }
    }
}

// ---------------------------------------------------------------------------
// Fused: x_full = idt + branch_out; LN2; MLP(1024, exact GELU); residual;
// write final output NCHW.  64 tokens per block.
// ---------------------------------------------------------------------------
__global__ void __launch_bounds__(256) mlp_kernel(
    const float* __restrict__ x, const float* __restrict__ g2, const float* __restrict__ b2,
    const float* __restrict__ W1, const float* __restrict__ b1,
    const float* __restrict__ W2, const float* __restrict__ b2o, float* __restrict__ out)
{
    extern __shared__ float sm[];
    float* xfT = sm;                     // [256][68] x_full transposed
    float* xnT = sm + 17408;             // [256][68] LN2 output transposed
    float* HsT = sm + 2 * 17408;         // [128][68] hidden chunk (gelu'd)
    float* HsP = sm + 2 * 17408 + 8704;  // [128][68] seg-1 partials
    float* mu  = sm + 2 * 17408 + 2 * 8704;
    float* rs  = mu + 64;

    int t0 = blockIdx.x * 64;
    int tid = threadIdx.x;

    // x_full = x (NCHW) + g_x1 (NHWC)
    for (int idx = tid; idx < 16384; idx += 256) {
        int c = idx >> 6, n = idx & 63;
        xfT[c * 68 + n] = x[c * HW + t0 + n];
    }
    __syncthreads();
    for (int k = 0; k < 64; k++)
        xfT[tid * 68 + k] += g_x1[(t0 + k) * 256 + tid];
    __syncthreads();

    // LN2 stats (4 threads per token)
    {
        int tok = tid >> 2, part = tid & 3;
        float sum = 0.f, sq = 0.f;
        for (int i = 0; i < 64; i++) {
            float v = xfT[(part * 64 + i) * 68 + tok];
            sum += v; sq += v * v;
        }
        sum += __shfl_down_sync(~0u, sum, 2); sq += __shfl_down_sync(~0u, sq, 2);
        sum += __shfl_down_sync(~0u, sum, 1); sq += __shfl_down_sync(~0u, sq, 1);
        if (part == 0) {
            float m = sum * (1.f / 256.f);
            mu[tok] = m;
            rs[tok] = rsqrtf(sq * (1.f / 256.f) - m * m + 1e-5f);
        }
    }
    __syncthreads();

    for (int idx = tid; idx < 16384; idx += 256) {
        int c = idx >> 6, n = idx & 63;
        xnT[c * 68 + n] = (xfT[c * 68 + n] - mu[n]) * rs[n] * g2[c] + b2[c];
    }
    __syncthreads();

    float accO[64];
    #pragma unroll
    for (int n = 0; n < 64; n++) accO[n] = 0.f;
    int jloc = tid & 127, seg = tid >> 7;

    for (int hb = 0; hb < 8; hb++) {
        // GEMM1 half-K per seg
        float accH[64];
        #pragma unroll
        for (int n = 0; n < 64; n++) accH[n] = 0.f;
        int jg = hb * 128 + jloc;
        const float* w1p = W1 + jg + (seg * 128) * 1024;
        for (int kk = 0; kk < 128; kk++) {
            float w = w1p[kk * 1024];
            const float4* xr = (const float4*)(xnT + (seg * 128 + kk) * 68);
            #pragma unroll
            for (int n4 = 0; n4 < 16; n4++) {
                float4 xv = xr[n4];
                accH[4 * n4 + 0] += xv.x * w; accH[4 * n4 + 1] += xv.y * w;
                accH[4 * n4 + 2] += xv.z * w; accH[4 * n4 + 3] += xv.w * w;
            }
        }
        float* dst = seg ? HsP : HsT;
        #pragma unroll
        for (int n = 0; n < 64; n++) dst[jloc * 68 + n] = accH[n];
        __syncthreads();

        // combine + bias + exact GELU
        for (int idx = tid; idx < 8192; idx += 256) {
            int j = idx >> 6, n = idx & 63;
            float hv = HsT[j * 68 + n] + HsP[j * 68 + n] + b1[hb * 128 + j];
            hv = 0.5f * hv * (1.f + erff(hv * 0.70710678118f));
            HsT[j * 68 + n] = hv;
        }
        __syncthreads();

        // GEMM2 accumulate (one output column per thread)
        const float* w2p = W2 + hb * 128 * 256 + tid;
        for (int j = 0; j < 128; j++) {
            float w = w2p[j * 256];
            const float4* hr = (const float4*)(HsT + j * 68);
            #pragma unroll
            for (int n4 = 0; n4 < 16; n4++) {
                float4 hv = hr[n4];
                accO[4 * n4 + 0] += hv.x * w; accO[4 * n4 + 1] += hv.y * w;
                accO[4 * n4 + 2] += hv.z * w; accO[4 * n4 + 3] += hv.w * w;
            }
        }
        __syncthreads();
    }

    // epilogue: residual, stage through smem for coalesced NCHW writes
    {
        float bb = b2o[tid];
        #pragma unroll
        for (int n = 0; n < 64; n++)
            xnT[tid * 68 + n] = accO[n] + bb + xfT[tid * 68 + n];
    }
    __syncthreads();
    for (int idx = tid; idx < 16384; idx += 256) {
        int c = idx >> 6, n = idx & 63;
        out[c * HW + t0 + n] = xnT[c * 68 + n];
    }
}

// ---------------------------------------------------------------------------
extern "C" void kernel_launch(void* const* d_in, const int* in_sizes, int n_in,
                              void* d_out, int out_size) {
    const float* x        = (const float*)d_in[0];
    const float* norm1_g  = (const float*)d_in[1];
    const float* norm1_b  = (const float*)d_in[2];
    const float* qkv_r    = (const float*)d_in[3];
    const float* proj_r_w = (const float*)d_in[4];
    const float* proj_r_b = (const float*)d_in[5];
    const float* table_r  = (const float*)d_in[6];
    const float* qkv_a    = (const float*)d_in[7];
    const float* proj_a_w = (const float*)d_in[8];
    const float* proj_a_b = (const float*)d_in[9];
    const float* table_a  = (const float*)d_in[10];
    const float* norm2_g  = (const float*)d_in[11];
    const float* norm2_b  = (const float*)d_in[12];
    const float* mlp_w1   = (const float*)d_in[13];
    const float* mlp_b1   = (const float*)d_in[14];
    const float* mlp_w2   = (const float*)d_in[15];
    const float* mlp_b2   = (const float*)d_in[16];
    float* out = (float*)d_out;

    const int ATTN_SMEM = (5 * 8704 + 64 * 128) * 4;                 // 206848 B
    const int MLP_SMEM  = (2 * 17408 + 2 * 8704 + 128) * 4;          // 209408 B
    cudaFuncSetAttribute(attn_kernel, cudaFuncAttributeMaxDynamicSharedMemorySize, ATTN_SMEM);
    cudaFuncSetAttribute(mlp_kernel,  cudaFuncAttributeMaxDynamicSharedMemorySize, MLP_SMEM);

    ln1_kernel<<<2048, 256>>>(x, norm1_g, norm1_b);
    bias_kernel<<<1, 256>>>(table_r, table_a);
    attn_kernel<<<dim3(1024, 2), 256, ATTN_SMEM>>>(qkv_r, proj_r_w, proj_r_b,
                                                   qkv_a, proj_a_w, proj_a_b);
    mlp_kernel<<<1024, 256, MLP_SMEM>>>(x, norm2_g, norm2_b,
                                        mlp_w1, mlp_b1, mlp_w2, mlp_b2, out);
}

// round 4
// speedup vs baseline: 1.8326x; 1.8175x over previous
#include <cuda_runtime.h>
#include <cstdint>

#define HW 65536

__device__ float g_xn[HW * 256];
__device__ float g_x1[HW * 256];
__device__ float g_bias[2 * 2 * 64 * 64];
__device__ float g_h[1024 * HW];       // H scratch, layout [k][token]

__device__ __forceinline__ uint32_t f2tf32(float v) {
    uint32_t u; asm("cvt.rna.tf32.f32 %0, %1;" : "=r"(u) : "f"(v)); return u;
}
__device__ __forceinline__ void mma8(float* d, const uint32_t* a, const uint32_t* b) {
    asm volatile("mma.sync.aligned.m16n8k8.row.col.f32.tf32.tf32.f32 "
        "{%0,%1,%2,%3}, {%4,%5,%6,%7}, {%8,%9}, {%0,%1,%2,%3};"
        : "+f"(d[0]), "+f"(d[1]), "+f"(d[2]), "+f"(d[3])
        : "r"(a[0]), "r"(a[1]), "r"(a[2]), "r"(a[3]), "r"(b[0]), "r"(b[1]));
}
__device__ __forceinline__ float gelu(float v) {
    return 0.5f * v * (1.f + erff(v * 0.70710678118f));
}
// A fragment slot (float index): layout [kb][mt][tig*8+g] x uint4 components (hm, hk)
__device__ __forceinline__ int a_slot(int tok, int c) {
    int kb = c >> 3, tig = c & 3, hk = (c >> 2) & 1;
    int mt = tok >> 4, g = tok & 7, hm = (tok >> 3) & 1;
    return (((kb * 8 + mt) * 32 + tig * 8 + g) << 2) + hm + (hk << 1);
}
// B fragment slot (float index): layout [kb][nt][tig][g] x float2 (hf)
__device__ __forceinline__ int b_slot(int kk, int n) {
    int kb = kk >> 3, kl = kk & 7, tig = kl & 3, hf = kl >> 2;
    int nt = n >> 3, g = n & 7;
    return (((((kb * 32 + nt) * 4 + tig) * 8) + g) << 1) + hf;
}

// ---------------- LN1 ----------------
__global__ void __launch_bounds__(256) ln1_kernel(const float* __restrict__ x,
                                                  const float* __restrict__ g,
                                                  const float* __restrict__ b) {
    __shared__ float s[256][33];
    __shared__ float mu[32], rs[32];
    int t0 = blockIdx.x * 32;
    int tid = threadIdx.x, lane = tid & 31, wid = tid >> 5;
    #pragma unroll
    for (int c = wid; c < 256; c += 8) s[c][lane] = x[c * HW + t0 + lane];
    __syncthreads();
    for (int it = 0; it < 4; it++) {
        int tok = wid * 4 + it;
        float sum = 0.f, sq = 0.f;
        #pragma unroll
        for (int j = 0; j < 8; j++) { float v = s[lane + 32 * j][tok]; sum += v; sq += v * v; }
        #pragma unroll
        for (int o = 16; o; o >>= 1) { sum += __shfl_down_sync(~0u, sum, o); sq += __shfl_down_sync(~0u, sq, o); }
        if (lane == 0) {
            float m = sum * (1.f / 256.f);
            mu[tok] = m; rs[tok] = rsqrtf(sq * (1.f / 256.f) - m * m + 1e-5f);
        }
    }
    __syncthreads();
    float gc = g[tid], bc = b[tid];
    for (int k = 0; k < 32; k++)
        g_xn[(t0 + k) * 256 + tid] = (s[tid][k] - mu[k]) * rs[k] * gc + bc;
}

// ---------------- bias tables ----------------
__global__ void bias_kernel(const float* __restrict__ tr, const float* __restrict__ ta) {
    for (int idx = threadIdx.x; idx < 16384; idx += blockDim.x) {
        int br = idx >> 13, rem = idx & 8191;
        int h = rem >> 12, n = (rem >> 6) & 63, m = rem & 63;
        int Wh = br ? 4 : 16, Ww = br ? 16 : 4, lg = br ? 4 : 2;
        int ridx = ((n >> lg) - (m >> lg) + Wh - 1) * (2 * Ww - 1) + ((n & (Ww - 1)) - (m & (Ww - 1)) + Ww - 1);
        g_bias[idx] = (br ? ta : tr)[ridx * 2 + h];
    }
}

// ---------------- window attention (fp32) ----------------
__global__ void __launch_bounds__(256) attn_kernel(
    const float* __restrict__ Wq_r, const float* __restrict__ Wp_r, const float* __restrict__ bp_r,
    const float* __restrict__ Wq_a, const float* __restrict__ Wp_a, const float* __restrict__ bp_a)
{
    extern __shared__ float sm[];
    float* xsT = sm;
    float* qT  = sm + 8704;
    float* kT  = sm + 2 * 8704;
    float* OT  = sm + 3 * 8704;
    float* PT  = sm + 4 * 8704;
    float* vR  = sm + 5 * 8704;

    int br = blockIdx.y;
    int co = br ? 128 : 0;
    int lg = br ? 4 : 2;
    int Ww = 1 << lg;
    int nWb = br ? 16 : 64;
    int Wh = br ? 4 : 16;
    const float* Wq = br ? Wq_a : Wq_r;
    const float* Wp = br ? Wp_a : Wp_r;
    const float* bp = br ? bp_a : bp_r;

    int wi = blockIdx.x;
    int hb = wi / nWb, wb = wi - hb * nWb;
    int h0 = hb * Wh, w0 = wb * Ww;
    int tid = threadIdx.x;

    for (int idx = tid; idx < 64 * 128; idx += 256) {
        int n = idx >> 7, k = idx & 127;
        int t = ((h0 + (n >> lg)) << 8) + w0 + (n & (Ww - 1));
        xsT[k * 68 + n] = g_xn[t * 256 + co + k];
    }
    __syncthreads();

    for (int p = 0; p < 2; p++) {
        int col = p ? 256 + tid : tid;
        if (col < 384) {
            float acc[64];
            #pragma unroll
            for (int r = 0; r < 64; r++) acc[r] = 0.f;
            const float* wptr = Wq + col;
            for (int k = 0; k < 128; k++) {
                float w = wptr[k * 384];
                const float4* xr = (const float4*)(xsT + k * 68);
                #pragma unroll
                for (int r4 = 0; r4 < 16; r4++) {
                    float4 xv = xr[r4];
                    acc[4*r4+0] += xv.x*w; acc[4*r4+1] += xv.y*w; acc[4*r4+2] += xv.z*w; acc[4*r4+3] += xv.w*w;
                }
            }
            if (col < 128)      { for (int n = 0; n < 64; n++) qT[col*68+n] = acc[n]; }
            else if (col < 256) { for (int n = 0; n < 64; n++) kT[(col-128)*68+n] = acc[n]; }
            else                { for (int n = 0; n < 64; n++) vR[n*128+(col-256)] = acc[n]; }
        }
    }
    __syncthreads();

    if (tid < 128) {
        int h = tid >> 6, n = tid & 63;
        float acc[64];
        #pragma unroll
        for (int m = 0; m < 64; m++) acc[m] = 0.f;
        for (int d = 0; d < 64; d++) {
            float qv = qT[(h*64+d)*68+n];
            const float4* kr = (const float4*)(kT + (h*64+d)*68);
            #pragma unroll
            for (int m4 = 0; m4 < 16; m4++) {
                float4 kv = kr[m4];
                acc[4*m4+0] += qv*kv.x; acc[4*m4+1] += qv*kv.y; acc[4*m4+2] += qv*kv.z; acc[4*m4+3] += qv*kv.w;
            }
        }
        const float4* bptr = (const float4*)(g_bias + ((br*2+h)*64+n)*64);
        #pragma unroll
        for (int m4 = 0; m4 < 16; m4++) {
            float4 bv = bptr[m4];
            acc[4*m4+0] = acc[4*m4+0]*0.125f + bv.x; acc[4*m4+1] = acc[4*m4+1]*0.125f + bv.y;
            acc[4*m4+2] = acc[4*m4+2]*0.125f + bv.z; acc[4*m4+3] = acc[4*m4+3]*0.125f + bv.w;
        }
        float mx = -1e30f;
        #pragma unroll
        for (int m = 0; m < 64; m++) mx = fmaxf(mx, acc[m]);
        float ssum = 0.f;
        #pragma unroll
        for (int m = 0; m < 64; m++) { float e = expf(acc[m]-mx); acc[m] = e; ssum += e; }
        float inv = 1.f / ssum;
        #pragma unroll
        for (int m = 0; m < 64; m++) PT[(h*64+m)*68+n] = acc[m]*inv;
    }
    __syncthreads();

    if (tid < 128) {
        int j = tid, h = j >> 6;
        float acc[64];
        #pragma unroll
        for (int n = 0; n < 64; n++) acc[n] = 0.f;
        for (int m = 0; m < 64; m++) {
            float vv = vR[m*128+j];
            const float4* pr = (const float4*)(PT + (h*64+m)*68);
            #pragma unroll
            for (int n4 = 0; n4 < 16; n4++) {
                float4 pv = pr[n4];
                acc[4*n4+0] += pv.x*vv; acc[4*n4+1] += pv.y*vv; acc[4*n4+2] += pv.z*vv; acc[4*n4+3] += pv.w*vv;
            }
        }
        #pragma unroll
        for (int n = 0; n < 64; n++) OT[j*68+n] = acc[n];
    }
    __syncthreads();

    if (tid < 128) {
        float acc[64];
        #pragma unroll
        for (int n = 0; n < 64; n++) acc[n] = 0.f;
        for (int k = 0; k < 128; k++) {
            float w = Wp[k*128 + tid];
            const float4* orow = (const float4*)(OT + k*68);
            #pragma unroll
            for (int n4 = 0; n4 < 16; n4++) {
                float4 ov = orow[n4];
                acc[4*n4+0] += ov.x*w; acc[4*n4+1] += ov.y*w; acc[4*n4+2] += ov.z*w; acc[4*n4+3] += ov.w*w;
            }
        }
        float bb = bp[tid];
        for (int n = 0; n < 64; n++) {
            int t = ((h0 + (n >> lg)) << 8) + w0 + (n & (Ww - 1));
            g_x1[t*256 + co + tid] = acc[n] + bb + xsT[tid*68+n];
        }
    }
}

// ===========================================================================
// MLP1: LN2 + GEMM1 (256->1024) + GELU -> g_h [k][tok]. tf32 mma.sync.
// CTA: 128 tokens, 256 thr (8 warps, 2m x 4n), warp tile 64 tok x 64 cols.
// Smem floats: A frag 32768 @0 | B 2x8192 @32768 | LN S[128][129] @32768 | stats @49280
// ===========================================================================
#define M1_SMEM 201216
__global__ void __launch_bounds__(256, 1) mlp1_kernel(
    const float* __restrict__ x, const float* __restrict__ g2, const float* __restrict__ b2,
    const float* __restrict__ W1, const float* __restrict__ b1)
{
    extern __shared__ float sm[];
    float* A    = sm;
    float* Bbuf = sm + 32768;
    float* S    = sm + 32768;
    float* tmpS = sm + 49280;
    float* tmpQ = sm + 49536;
    float* tsum = sm + 49792;
    float* tsq  = sm + 49920;
    float* mu   = sm + 50048;
    float* rs   = sm + 50176;

    int tid = threadIdx.x, wid = tid >> 5, lane = tid & 31;
    int t0 = blockIdx.x * 128;

    // ---- LN2 into A fragments ----
    if (tid < 128) { tsum[tid] = 0.f; tsq[tid] = 0.f; }
    for (int h = 0; h < 2; h++) {
        __syncthreads();
        #pragma unroll 4
        for (int it = 0; it < 64; it++) {
            int idx = it * 256 + tid;
            int n = idx & 127, cl = idx >> 7;
            S[cl * 129 + n] = x[(size_t)(h * 128 + cl) * HW + t0 + n];
        }
        __syncthreads();
        #pragma unroll 4
        for (int it = 0; it < 64; it++) {
            int idx = it * 256 + tid;
            int cl = idx & 127, n = idx >> 7;
            S[cl * 129 + n] += g_x1[(size_t)(t0 + n) * 256 + h * 128 + cl];
        }
        __syncthreads();
        {
            int n = tid & 127, part = tid >> 7;
            float s1 = 0.f, s2 = 0.f;
            for (int cl = part * 64; cl < part * 64 + 64; cl++) {
                float v = S[cl * 129 + n];
                s1 += v; s2 += v * v;
                A[a_slot(n, h * 128 + cl)] = v;
            }
            tmpS[part * 128 + n] = s1; tmpQ[part * 128 + n] = s2;
        }
        __syncthreads();
        if (tid < 128) {
            tsum[tid] += tmpS[tid] + tmpS[128 + tid];
            tsq[tid]  += tmpQ[tid] + tmpQ[128 + tid];
        }
    }
    __syncthreads();
    if (tid < 128) {
        float m = tsum[tid] * (1.f / 256.f);
        mu[tid] = m;
        rs[tid] = rsqrtf(tsq[tid] * (1.f / 256.f) - m * m + 1e-5f);
    }
    __syncthreads();
    {
        int tok = tid & 127, half = tid >> 7;
        float m = mu[tok], r = rs[tok];
        for (int c = half * 128; c < half * 128 + 128; c++) {
            int idx = a_slot(tok, c);
            float v = A[idx];
            A[idx] = __uint_as_float(f2tf32((v - m) * r * g2[c] + b2[c]));
        }
    }
    __syncthreads();

    // ---- GEMM1 ----
    int mwarp = wid >> 2, nwarp = wid & 3;
    int g = lane >> 2, tg = lane & 3;

    for (int jb = 0; jb < 4; jb++) {
        float d[4][8][4];
        #pragma unroll
        for (int mt = 0; mt < 4; mt++)
            #pragma unroll
            for (int nt = 0; nt < 8; nt++)
                #pragma unroll
                for (int q = 0; q < 4; q++) d[mt][nt][q] = 0.f;

        for (int kc = 0; kc < 8; kc++) {
            float* Bc = Bbuf + (kc & 1) * 8192;
            #pragma unroll 8
            for (int kk = 0; kk < 32; kk++) {
                float v = W1[(size_t)(kc * 32 + kk) * 1024 + jb * 256 + tid];
                Bc[b_slot(kk, tid)] = __uint_as_float(f2tf32(v));
            }
            __syncthreads();
            #pragma unroll
            for (int kbl = 0; kbl < 4; kbl++) {
                uint32_t a[4][4], b[8][2];
                const uint4* Au = (const uint4*)A;
                #pragma unroll
                for (int mt = 0; mt < 4; mt++)
                    *(uint4*)a[mt] = Au[((kc * 4 + kbl) * 8 + mwarp * 4 + mt) * 32 + tg * 8 + g];
                const uint2* Bu = (const uint2*)Bc;
                #pragma unroll
                for (int nt = 0; nt < 8; nt++)
                    *(uint2*)b[nt] = Bu[(kbl * 32 + nwarp * 8 + nt) * 32 + tg * 8 + g];
                #pragma unroll
                for (int mt = 0; mt < 4; mt++)
                    #pragma unroll
                    for (int nt = 0; nt < 8; nt++)
                        mma8(d[mt][nt], a[mt], b[nt]);
            }
        }
        // epilogue: bias + GELU + tf32 -> g_h[k][tok]
        #pragma unroll
        for (int mt = 0; mt < 4; mt++) {
            #pragma unroll
            for (int nt = 0; nt < 8; nt++) {
                int row0 = mwarp * 64 + mt * 16 + g;
                int col0 = jb * 256 + nwarp * 64 + nt * 8 + 2 * tg;
                float b0v = b1[col0], b1v = b1[col0 + 1];
                float v0 = gelu(d[mt][nt][0] + b0v);
                float v1 = gelu(d[mt][nt][1] + b1v);
                float v2 = gelu(d[mt][nt][2] + b0v);
                float v3 = gelu(d[mt][nt][3] + b1v);
                g_h[(size_t)col0 * HW + t0 + row0]           = __uint_as_float(f2tf32(v0));
                g_h[(size_t)(col0 + 1) * HW + t0 + row0]     = __uint_as_float(f2tf32(v1));
                g_h[(size_t)col0 * HW + t0 + row0 + 8]       = __uint_as_float(f2tf32(v2));
                g_h[(size_t)(col0 + 1) * HW + t0 + row0 + 8] = __uint_as_float(f2tf32(v3));
            }
        }
    }
}

// ===========================================================================
// MLP2: GEMM2 (1024->256) + residual -> out (NCHW). tf32 mma.sync.
// Smem floats: A 2x4096 @0 | B 2x8192 @8192 | epilogue overlay S[256][133] @0
// ===========================================================================
#define M2_SMEM 136192
__global__ void __launch_bounds__(256, 1) mlp2_kernel(
    const float* __restrict__ x, const float* __restrict__ W2,
    const float* __restrict__ b2o, float* __restrict__ out)
{
    extern __shared__ float sm[];
    float* Abuf = sm;
    float* Bbuf = sm + 8192;
    float* S    = sm;

    int tid = threadIdx.x, wid = tid >> 5, lane = tid & 31;
    int t0 = blockIdx.x * 128;
    int mwarp = wid >> 2, nwarp = wid & 3;
    int g = lane >> 2, tg = lane & 3;

    float d[4][8][4];
    #pragma unroll
    for (int mt = 0; mt < 4; mt++)
        #pragma unroll
        for (int nt = 0; nt < 8; nt++)
            #pragma unroll
            for (int q = 0; q < 4; q++) d[mt][nt][q] = 0.f;

    int tokA = tid & 127, hiA = tid >> 7;
    for (int kc = 0; kc < 32; kc++) {
        float* Ac = Abuf + (kc & 1) * 4096;
        float* Bc = Bbuf + (kc & 1) * 8192;
        #pragma unroll 4
        for (int i = 0; i < 16; i++) {
            int kk = i * 2 + hiA;
            Ac[a_slot(tokA, kk)] = g_h[(size_t)(kc * 32 + kk) * HW + t0 + tokA];
        }
        #pragma unroll 8
        for (int kk = 0; kk < 32; kk++) {
            float v = W2[(size_t)(kc * 32 + kk) * 256 + tid];
            Bc[b_slot(kk, tid)] = __uint_as_float(f2tf32(v));
        }
        __syncthreads();
        #pragma unroll
        for (int kbl = 0; kbl < 4; kbl++) {
            uint32_t a[4][4], b[8][2];
            const uint4* Au = (const uint4*)Ac;
            #pragma unroll
            for (int mt = 0; mt < 4; mt++)
                *(uint4*)a[mt] = Au[(kbl * 8 + mwarp * 4 + mt) * 32 + tg * 8 + g];
            const uint2* Bu = (const uint2*)Bc;
            #pragma unroll
            for (int nt = 0; nt < 8; nt++)
                *(uint2*)b[nt] = Bu[(kbl * 32 + nwarp * 8 + nt) * 32 + tg * 8 + g];
            #pragma unroll
            for (int mt = 0; mt < 4; mt++)
                #pragma unroll
                for (int nt = 0; nt < 8; nt++)
                    mma8(d[mt][nt], a[mt], b[nt]);
        }
    }

    // epilogue: stage g_x1 tile, then residual + NCHW store
    __syncthreads();
    #pragma unroll 4
    for (int i = 0; i < 128; i++)
        S[tid * 133 + i] = g_x1[(size_t)(t0 + i) * 256 + tid];
    __syncthreads();

    #pragma unroll
    for (int mt = 0; mt < 4; mt++) {
        #pragma unroll
        for (int nt = 0; nt < 8; nt++) {
            int row0 = mwarp * 64 + mt * 16 + g;
            int col0 = nwarp * 64 + nt * 8 + 2 * tg;
            #pragma unroll
            for (int q = 0; q < 4; q++) {
                int col = col0 + (q & 1);
                int row = row0 + (q >> 1) * 8;
                float v = d[mt][nt][q] + b2o[col]
                        + x[(size_t)col * HW + t0 + row] + S[col * 133 + row];
                out[(size_t)col * HW + t0 + row] = v;
            }
        }
    }
}

// ---------------------------------------------------------------------------
extern "C" void kernel_launch(void* const* d_in, const int* in_sizes, int n_in,
                              void* d_out, int out_size) {
    const float* x        = (const float*)d_in[0];
    const float* norm1_g  = (const float*)d_in[1];
    const float* norm1_b  = (const float*)d_in[2];
    const float* qkv_r    = (const float*)d_in[3];
    const float* proj_r_w = (const float*)d_in[4];
    const float* proj_r_b = (const float*)d_in[5];
    const float* table_r  = (const float*)d_in[6];
    const float* qkv_a    = (const float*)d_in[7];
    const float* proj_a_w = (const float*)d_in[8];
    const float* proj_a_b = (const float*)d_in[9];
    const float* table_a  = (const float*)d_in[10];
    const float* norm2_g  = (const float*)d_in[11];
    const float* norm2_b  = (const float*)d_in[12];
    const float* mlp_w1   = (const float*)d_in[13];
    const float* mlp_b1   = (const float*)d_in[14];
    const float* mlp_w2   = (const float*)d_in[15];
    const float* mlp_b2   = (const float*)d_in[16];
    float* out = (float*)d_out;

    const int ATTN_SMEM = (5 * 8704 + 64 * 128) * 4;   // 206848 B
    cudaFuncSetAttribute(attn_kernel, cudaFuncAttributeMaxDynamicSharedMemorySize, ATTN_SMEM);
    cudaFuncSetAttribute(mlp1_kernel, cudaFuncAttributeMaxDynamicSharedMemorySize, M1_SMEM);
    cudaFuncSetAttribute(mlp2_kernel, cudaFuncAttributeMaxDynamicSharedMemorySize, M2_SMEM);

    ln1_kernel<<<2048, 256>>>(x, norm1_g, norm1_b);
    bias_kernel<<<1, 256>>>(table_r, table_a);
    attn_kernel<<<dim3(1024, 2), 256, ATTN_SMEM>>>(qkv_r, proj_r_w, proj_r_b,
                                                   qkv_a, proj_a_w, proj_a_b);
    mlp1_kernel<<<512, 256, M1_SMEM>>>(x, norm2_g, norm2_b, mlp_w1, mlp_b1);
    mlp2_kernel<<<512, 256, M2_SMEM>>>(x, mlp_w2, mlp_b2, out);
}

// round 5
// speedup vs baseline: 2.8780x; 1.5704x over previous
#include <cuda_runtime.h>
#include <cstdint>

#define HW 65536

__device__ float g_xn[HW * 256];
__device__ float g_x1[HW * 256];
__device__ float g_bias[2 * 2 * 64 * 64];
__device__ float g_h[1024 * HW];          // H scratch, layout [k][token]
__device__ float g_w1f[4 * 8 * 8192];     // W1 tf32, frag order [jb][kc][8192]
__device__ float g_w2f[32 * 8192];        // W2 tf32, frag order [kc][8192]

__device__ __forceinline__ uint32_t f2tf32(float v) {
    uint32_t u; asm("cvt.rna.tf32.f32 %0, %1;" : "=r"(u) : "f"(v)); return u;
}
__device__ __forceinline__ uint32_t smem_u32(const void* p) {
    uint32_t a;
    asm("{ .reg .u64 t; cvta.to.shared.u64 t, %1; cvt.u32.u64 %0, t; }" : "=r"(a) : "l"(p));
    return a;
}
__device__ __forceinline__ void cp16(uint32_t dst, const void* src) {
    asm volatile("cp.async.cg.shared.global [%0], [%1], 16;" :: "r"(dst), "l"(src));
}
__device__ __forceinline__ void cp4(uint32_t dst, const void* src) {
    asm volatile("cp.async.ca.shared.global [%0], [%1], 4;" :: "r"(dst), "l"(src));
}
#define CP_COMMIT() asm volatile("cp.async.commit_group;" ::: "memory")
#define CP_WAIT1()  asm volatile("cp.async.wait_group 1;" ::: "memory")
#define CP_WAIT0()  asm volatile("cp.async.wait_group 0;" ::: "memory")

__device__ __forceinline__ void mma8(float* d, const uint32_t* a, const uint32_t* b) {
    asm volatile("mma.sync.aligned.m16n8k8.row.col.f32.tf32.tf32.f32 "
        "{%0,%1,%2,%3}, {%4,%5,%6,%7}, {%8,%9}, {%0,%1,%2,%3};"
        : "+f"(d[0]), "+f"(d[1]), "+f"(d[2]), "+f"(d[3])
        : "r"(a[0]), "r"(a[1]), "r"(a[2]), "r"(a[3]), "r"(b[0]), "r"(b[1]));
}
__device__ __forceinline__ float gelu(float v) {
    return 0.5f * v * (1.f + erff(v * 0.70710678118f));
}
// A fragment slot (float index)
__device__ __forceinline__ int a_slot(int tok, int c) {
    int kb = c >> 3, tig = c & 3, hk = (c >> 2) & 1;
    int mt = tok >> 4, g = tok & 7, hm = (tok >> 3) & 1;
    return (((kb * 8 + mt) * 32 + tig * 8 + g) << 2) + hm + (hk << 1);
}

// ---------------- LN1 ----------------
__global__ void __launch_bounds__(256) ln1_kernel(const float* __restrict__ x,
                                                  const float* __restrict__ g,
                                                  const float* __restrict__ b) {
    __shared__ float s[256][33];
    __shared__ float mu[32], rs[32];
    int t0 = blockIdx.x * 32;
    int tid = threadIdx.x, lane = tid & 31, wid = tid >> 5;
    #pragma unroll
    for (int c = wid; c < 256; c += 8) s[c][lane] = x[c * HW + t0 + lane];
    __syncthreads();
    for (int it = 0; it < 4; it++) {
        int tok = wid * 4 + it;
        float sum = 0.f, sq = 0.f;
        #pragma unroll
        for (int j = 0; j < 8; j++) { float v = s[lane + 32 * j][tok]; sum += v; sq += v * v; }
        #pragma unroll
        for (int o = 16; o; o >>= 1) { sum += __shfl_down_sync(~0u, sum, o); sq += __shfl_down_sync(~0u, sq, o); }
        if (lane == 0) {
            float m = sum * (1.f / 256.f);
            mu[tok] = m; rs[tok] = rsqrtf(sq * (1.f / 256.f) - m * m + 1e-5f);
        }
    }
    __syncthreads();
    float gc = g[tid], bc = b[tid];
    for (int k = 0; k < 32; k++)
        g_xn[(t0 + k) * 256 + tid] = (s[tid][k] - mu[k]) * rs[k] * gc + bc;
}

// ---------------- bias tables ----------------
__global__ void bias_kernel(const float* __restrict__ tr, const float* __restrict__ ta) {
    for (int idx = threadIdx.x; idx < 16384; idx += blockDim.x) {
        int br = idx >> 13, rem = idx & 8191;
        int h = rem >> 12, n = (rem >> 6) & 63, m = rem & 63;
        int Wh = br ? 4 : 16, Ww = br ? 16 : 4, lg = br ? 4 : 2;
        int ridx = ((n >> lg) - (m >> lg) + Wh - 1) * (2 * Ww - 1) + ((n & (Ww - 1)) - (m & (Ww - 1)) + Ww - 1);
        g_bias[idx] = (br ? ta : tr)[ridx * 2 + h];
    }
}

// ---------------- weight pre-format (tf32, fragment order) ----------------
__global__ void __launch_bounds__(256) wfmt_kernel(const float* __restrict__ W1,
                                                   const float* __restrict__ W2) {
    int idx = blockIdx.x * 256 + threadIdx.x;       // 0 .. 524287
    int r = idx & 8191;
    int hf = r & 1, g = (r >> 1) & 7, tig = (r >> 4) & 3, nt = (r >> 6) & 31, kb = r >> 11;
    int kk = kb * 8 + hf * 4 + tig, n = nt * 8 + g;
    if (idx < 262144) {
        int jb = idx >> 16, kc = (idx >> 13) & 7;
        g_w1f[idx] = __uint_as_float(f2tf32(W1[(size_t)(kc * 32 + kk) * 1024 + jb * 256 + n]));
    } else {
        int j = idx - 262144;
        int kc = j >> 13;
        g_w2f[j] = __uint_as_float(f2tf32(W2[(size_t)(kc * 32 + kk) * 256 + n]));
    }
}

// ---------------- window attention (fp32, smem-dieted, 2 CTA/SM) ----------------
// dynamic smem: xv (X then V) @0, qpo (Q then P then O) @8704, kb (K) @17408  (floats)
#define ATTN_SMEM (3 * 8704 * 4)
__global__ void __launch_bounds__(256, 2) attn_kernel(
    const float* __restrict__ Wq_r, const float* __restrict__ Wp_r, const float* __restrict__ bp_r,
    const float* __restrict__ Wq_a, const float* __restrict__ Wp_a, const float* __restrict__ bp_a)
{
    extern __shared__ float sm[];
    float* xv  = sm;                // X [k][n] (68 pitch) -> V [m][col] (64x128)
    float* qpo = sm + 8704;         // Q [d][n] -> P [m][n] -> O [j][n]
    float* kbf = sm + 2 * 8704;     // K [d][n]

    int br = blockIdx.y;
    int co = br ? 128 : 0;
    int lg = br ? 4 : 2;
    int Ww = 1 << lg;
    int nWb = br ? 16 : 64;
    int Wh = br ? 4 : 16;
    const float* Wq = br ? Wq_a : Wq_r;
    const float* Wp = br ? Wp_a : Wp_r;
    const float* bp = br ? bp_a : bp_r;

    int wi = blockIdx.x;
    int hb = wi / nWb, wb = wi - hb * nWb;
    int h0 = hb * Wh, w0 = wb * Ww;
    int tid = threadIdx.x;

    // ---- X tile [k][n] ----
    for (int idx = tid; idx < 64 * 128; idx += 256) {
        int n = idx >> 7, k = idx & 127;
        int t = ((h0 + (n >> lg)) << 8) + w0 + (n & (Ww - 1));
        xv[k * 68 + n] = g_xn[t * 256 + co + k];
    }
    __syncthreads();

    // ---- QKV pass0: cols 0..255 -> Q, K ----
    {
        int col = tid;
        float acc[64];
        #pragma unroll
        for (int r = 0; r < 64; r++) acc[r] = 0.f;
        const float* wptr = Wq + col;
        for (int k = 0; k < 128; k++) {
            float w = wptr[k * 384];
            const float4* xr = (const float4*)(xv + k * 68);
            #pragma unroll
            for (int r4 = 0; r4 < 16; r4++) {
                float4 q = xr[r4];
                acc[4*r4+0] += q.x*w; acc[4*r4+1] += q.y*w; acc[4*r4+2] += q.z*w; acc[4*r4+3] += q.w*w;
            }
        }
        if (col < 128) { for (int n = 0; n < 64; n++) qpo[col*68+n] = acc[n]; }
        else           { for (int n = 0; n < 64; n++) kbf[(col-128)*68+n] = acc[n]; }
    }
    // ---- QKV pass1: cols 256..383 -> V (held in regs) ----
    float vacc[64];
    if (tid < 128) {
        #pragma unroll
        for (int r = 0; r < 64; r++) vacc[r] = 0.f;
        const float* wptr = Wq + 256 + tid;
        for (int k = 0; k < 128; k++) {
            float w = wptr[k * 384];
            const float4* xr = (const float4*)(xv + k * 68);
            #pragma unroll
            for (int r4 = 0; r4 < 16; r4++) {
                float4 q = xr[r4];
                vacc[4*r4+0] += q.x*w; vacc[4*r4+1] += q.y*w; vacc[4*r4+2] += q.z*w; vacc[4*r4+3] += q.w*w;
            }
        }
    }
    __syncthreads();                 // all X reads done
    if (tid < 128) {
        #pragma unroll
        for (int n = 0; n < 64; n++) xv[n * 128 + tid] = vacc[n];   // V[m][col]
    }
    __syncthreads();

    // ---- S + softmax (into regs) ----
    float pacc[64];
    int hh = tid >> 6, nn = tid & 63;
    if (tid < 128) {
        #pragma unroll
        for (int m = 0; m < 64; m++) pacc[m] = 0.f;
        for (int d = 0; d < 64; d++) {
            float qv = qpo[(hh*64+d)*68 + nn];
            const float4* kr = (const float4*)(kbf + (hh*64+d)*68);
            #pragma unroll
            for (int m4 = 0; m4 < 16; m4++) {
                float4 kv = kr[m4];
                pacc[4*m4+0] += qv*kv.x; pacc[4*m4+1] += qv*kv.y; pacc[4*m4+2] += qv*kv.z; pacc[4*m4+3] += qv*kv.w;
            }
        }
        const float4* bptr = (const float4*)(g_bias + ((br*2+hh)*64+nn)*64);
        #pragma unroll
        for (int m4 = 0; m4 < 16; m4++) {
            float4 bv = bptr[m4];
            pacc[4*m4+0] = pacc[4*m4+0]*0.125f + bv.x; pacc[4*m4+1] = pacc[4*m4+1]*0.125f + bv.y;
            pacc[4*m4+2] = pacc[4*m4+2]*0.125f + bv.z; pacc[4*m4+3] = pacc[4*m4+3]*0.125f + bv.w;
        }
        float mx = -1e30f;
        #pragma unroll
        for (int m = 0; m < 64; m++) mx = fmaxf(mx, pacc[m]);
        float ssum = 0.f;
        #pragma unroll
        for (int m = 0; m < 64; m++) { float e = expf(pacc[m]-mx); pacc[m] = e; ssum += e; }
        float inv = 1.f / ssum;
        #pragma unroll
        for (int m = 0; m < 64; m++) pacc[m] *= inv;
    }
    __syncthreads();                 // Q,K reads done
    if (tid < 128) {
        #pragma unroll
        for (int m = 0; m < 64; m++) qpo[(hh*64+m)*68 + nn] = pacc[m];   // P over Q
    }
    __syncthreads();

    // ---- O = P @ V ----
    float oacc[64];
    if (tid < 128) {
        int j = tid, h = j >> 6;
        #pragma unroll
        for (int n = 0; n < 64; n++) oacc[n] = 0.f;
        for (int m = 0; m < 64; m++) {
            float vv = xv[m*128 + j];
            const float4* pr = (const float4*)(qpo + (h*64+m)*68);
            #pragma unroll
            for (int n4 = 0; n4 < 16; n4++) {
                float4 pv = pr[n4];
                oacc[4*n4+0] += pv.x*vv; oacc[4*n4+1] += pv.y*vv; oacc[4*n4+2] += pv.z*vv; oacc[4*n4+3] += pv.w*vv;
            }
        }
    }
    __syncthreads();                 // P reads done
    if (tid < 128) {
        #pragma unroll
        for (int n = 0; n < 64; n++) qpo[tid*68 + n] = oacc[n];          // O over P
    }
    __syncthreads();

    // ---- proj + residual (re-read g_xn) ----
    if (tid < 128) {
        float acc[64];
        #pragma unroll
        for (int n = 0; n < 64; n++) acc[n] = 0.f;
        for (int k = 0; k < 128; k++) {
            float w = Wp[k*128 + tid];
            const float4* orow = (const float4*)(qpo + k*68);
            #pragma unroll
            for (int n4 = 0; n4 < 16; n4++) {
                float4 ov = orow[n4];
                acc[4*n4+0] += ov.x*w; acc[4*n4+1] += ov.y*w; acc[4*n4+2] += ov.z*w; acc[4*n4+3] += ov.w*w;
            }
        }
        float bb = bp[tid];
        for (int n = 0; n < 64; n++) {
            int t = ((h0 + (n >> lg)) << 8) + w0 + (n & (Ww - 1));
            g_x1[t*256 + co + tid] = acc[n] + bb + g_xn[t*256 + co + tid];
        }
    }
}

// ===========================================================================
// MLP1: LN2 + GEMM1 + GELU -> g_h [k][tok]. cp.async weights from g_w1f.
// Smem floats: A 32768 @0 | B 2x8192 @32768 | LN overlay S @32768, stats @49280
// ===========================================================================
#define M1_SMEM 201216
__global__ void __launch_bounds__(256, 1) mlp1_kernel(
    const float* __restrict__ x, const float* __restrict__ g2, const float* __restrict__ b2,
    const float* __restrict__ b1)
{
    extern __shared__ float sm[];
    float* A    = sm;
    float* S    = sm + 32768;
    float* tmpS = sm + 49280;
    float* tmpQ = sm + 49536;
    float* tsum = sm + 49792;
    float* tsq  = sm + 49920;
    float* mu   = sm + 50048;
    float* rs   = sm + 50176;

    int tid = threadIdx.x, wid = tid >> 5, lane = tid & 31;
    int t0 = blockIdx.x * 128;
    uint32_t bbase = smem_u32(sm) + 131072;   // B region byte addr

    // ---- LN2 into A fragments ----
    if (tid < 128) { tsum[tid] = 0.f; tsq[tid] = 0.f; }
    for (int h = 0; h < 2; h++) {
        __syncthreads();
        #pragma unroll 4
        for (int it = 0; it < 64; it++) {
            int idx = it * 256 + tid;
            int n = idx & 127, cl = idx >> 7;
            S[cl * 129 + n] = x[(size_t)(h * 128 + cl) * HW + t0 + n];
        }
        __syncthreads();
        #pragma unroll 4
        for (int it = 0; it < 64; it++) {
            int idx = it * 256 + tid;
            int cl = idx & 127, n = idx >> 7;
            S[cl * 129 + n] += g_x1[(size_t)(t0 + n) * 256 + h * 128 + cl];
        }
        __syncthreads();
        {
            int n = tid & 127, part = tid >> 7;
            float s1 = 0.f, s2 = 0.f;
            for (int cl = part * 64; cl < part * 64 + 64; cl++) {
                float v = S[cl * 129 + n];
                s1 += v; s2 += v * v;
                A[a_slot(n, h * 128 + cl)] = v;
            }
            tmpS[part * 128 + n] = s1; tmpQ[part * 128 + n] = s2;
        }
        __syncthreads();
        if (tid < 128) {
            tsum[tid] += tmpS[tid] + tmpS[128 + tid];
            tsq[tid]  += tmpQ[tid] + tmpQ[128 + tid];
        }
    }
    __syncthreads();
    if (tid < 128) {
        float m = tsum[tid] * (1.f / 256.f);
        mu[tid] = m;
        rs[tid] = rsqrtf(tsq[tid] * (1.f / 256.f) - m * m + 1e-5f);
    }
    __syncthreads();
    {
        int tok = tid & 127, half = tid >> 7;
        float m = mu[tok], r = rs[tok];
        for (int c = half * 128; c < half * 128 + 128; c++) {
            int idx = a_slot(tok, c);
            A[idx] = __uint_as_float(f2tf32((A[idx] - m) * r * g2[c] + b2[c]));
        }
    }
    __syncthreads();

    // ---- GEMM1, cp.async double-buffered B ----
    int mwarp = wid >> 2, nwarp = wid & 3;
    int g = lane >> 2, tg = lane & 3;

    for (int jb = 0; jb < 4; jb++) {
        float d[4][8][4];
        #pragma unroll
        for (int mt = 0; mt < 4; mt++)
            #pragma unroll
            for (int nt = 0; nt < 8; nt++)
                #pragma unroll
                for (int q = 0; q < 4; q++) d[mt][nt][q] = 0.f;

        {   // prefetch chunk 0
            const float4* src = (const float4*)(g_w1f + (size_t)(jb * 8) * 8192);
            #pragma unroll
            for (int i = 0; i < 8; i++) cp16(bbase + (i * 256 + tid) * 16, src + i * 256 + tid);
            CP_COMMIT();
        }
        for (int kc = 0; kc < 8; kc++) {
            if (kc < 7) {
                const float4* src = (const float4*)(g_w1f + (size_t)(jb * 8 + kc + 1) * 8192);
                uint32_t db = bbase + ((kc + 1) & 1) * 32768;
                #pragma unroll
                for (int i = 0; i < 8; i++) cp16(db + (i * 256 + tid) * 16, src + i * 256 + tid);
                CP_COMMIT();
                CP_WAIT1();
            } else {
                CP_WAIT0();
            }
            __syncthreads();
            const float* Bc = sm + 32768 + (kc & 1) * 8192;
            #pragma unroll
            for (int kbl = 0; kbl < 4; kbl++) {
                uint32_t a[4][4], b[8][2];
                const uint4* Au = (const uint4*)A;
                #pragma unroll
                for (int mt = 0; mt < 4; mt++)
                    *(uint4*)a[mt] = Au[((kc * 4 + kbl) * 8 + mwarp * 4 + mt) * 32 + tg * 8 + g];
                const uint2* Bu = (const uint2*)Bc;
                #pragma unroll
                for (int nt = 0; nt < 8; nt++)
                    *(uint2*)b[nt] = Bu[(kbl * 32 + nwarp * 8 + nt) * 32 + tg * 8 + g];
                #pragma unroll
                for (int mt = 0; mt < 4; mt++)
                    #pragma unroll
                    for (int nt = 0; nt < 8; nt++)
                        mma8(d[mt][nt], a[mt], b[nt]);
            }
            __syncthreads();
        }
        // epilogue: bias + GELU + tf32 -> g_h[k][tok]
        #pragma unroll
        for (int mt = 0; mt < 4; mt++) {
            #pragma unroll
            for (int nt = 0; nt < 8; nt++) {
                int row0 = mwarp * 64 + mt * 16 + g;
                int col0 = jb * 256 + nwarp * 64 + nt * 8 + 2 * tg;
                float b0v = b1[col0], b1v = b1[col0 + 1];
                float v0 = gelu(d[mt][nt][0] + b0v);
                float v1 = gelu(d[mt][nt][1] + b1v);
                float v2 = gelu(d[mt][nt][2] + b0v);
                float v3 = gelu(d[mt][nt][3] + b1v);
                g_h[(size_t)col0 * HW + t0 + row0]           = __uint_as_float(f2tf32(v0));
                g_h[(size_t)(col0 + 1) * HW + t0 + row0]     = __uint_as_float(f2tf32(v1));
                g_h[(size_t)col0 * HW + t0 + row0 + 8]       = __uint_as_float(f2tf32(v2));
                g_h[(size_t)(col0 + 1) * HW + t0 + row0 + 8] = __uint_as_float(f2tf32(v3));
            }
        }
    }
}

// ===========================================================================
// MLP2: GEMM2 + residual -> out. cp.async A (g_h) + B (g_w2f), double-buffered.
// Smem floats: A 2x4096 @0 | B 2x8192 @8192 | epilogue overlay S[256][133] @0
// ===========================================================================
#define M2_SMEM 136192
__global__ void __launch_bounds__(256, 1) mlp2_kernel(
    const float* __restrict__ x, const float* __restrict__ b2o, float* __restrict__ out)
{
    extern __shared__ float sm[];
    float* S = sm;

    int tid = threadIdx.x, wid = tid >> 5, lane = tid & 31;
    int t0 = blockIdx.x * 128;
    int mwarp = wid >> 2, nwarp = wid & 3;
    int g = lane >> 2, tg = lane & 3;
    uint32_t abase = smem_u32(sm);
    uint32_t bbase = abase + 32768;
    int tokA = tid & 127, hiA = tid >> 7;

    float d[4][8][4];
    #pragma unroll
    for (int mt = 0; mt < 4; mt++)
        #pragma unroll
        for (int nt = 0; nt < 8; nt++)
            #pragma unroll
            for (int q = 0; q < 4; q++) d[mt][nt][q] = 0.f;

    // prefetch chunk 0
    {
        #pragma unroll
        for (int i = 0; i < 16; i++) {
            int kk = i * 2 + hiA;
            cp4(abase + (uint32_t)a_slot(tokA, kk) * 4, g_h + (size_t)kk * HW + t0 + tokA);
        }
        const float4* src = (const float4*)(g_w2f);
        #pragma unroll
        for (int i = 0; i < 8; i++) cp16(bbase + (i * 256 + tid) * 16, src + i * 256 + tid);
        CP_COMMIT();
    }
    for (int kc = 0; kc < 32; kc++) {
        if (kc < 31) {
            uint32_t da = abase + ((kc + 1) & 1) * 16384;
            #pragma unroll
            for (int i = 0; i < 16; i++) {
                int kk = i * 2 + hiA;
                cp4(da + (uint32_t)a_slot(tokA, kk) * 4,
                    g_h + (size_t)((kc + 1) * 32 + kk) * HW + t0 + tokA);
            }
            const float4* src = (const float4*)(g_w2f + (size_t)(kc + 1) * 8192);
            uint32_t db = bbase + ((kc + 1) & 1) * 32768;
            #pragma unroll
            for (int i = 0; i < 8; i++) cp16(db + (i * 256 + tid) * 16, src + i * 256 + tid);
            CP_COMMIT();
            CP_WAIT1();
        } else {
            CP_WAIT0();
        }
        __syncthreads();
        const float* Ac = sm + (kc & 1) * 4096;
        const float* Bc = sm + 8192 + (kc & 1) * 8192;
        #pragma unroll
        for (int kbl = 0; kbl < 4; kbl++) {
            uint32_t a[4][4], b[8][2];
            const uint4* Au = (const uint4*)Ac;
            #pragma unroll
            for (int mt = 0; mt < 4; mt++)
                *(uint4*)a[mt] = Au[(kbl * 8 + mwarp * 4 + mt) * 32 + tg * 8 + g];
            const uint2* Bu = (const uint2*)Bc;
            #pragma unroll
            for (int nt = 0; nt < 8; nt++)
                *(uint2*)b[nt] = Bu[(kbl * 32 + nwarp * 8 + nt) * 32 + tg * 8 + g];
            #pragma unroll
            for (int mt = 0; mt < 4; mt++)
                #pragma unroll
                for (int nt = 0; nt < 8; nt++)
                    mma8(d[mt][nt], a[mt], b[nt]);
        }
        __syncthreads();
    }

    // epilogue: stage g_x1, residual, NCHW store
    #pragma unroll 4
    for (int i = 0; i < 128; i++)
        S[tid * 133 + i] = g_x1[(size_t)(t0 + i) * 256 + tid];
    __syncthreads();

    #pragma unroll
    for (int mt = 0; mt < 4; mt++) {
        #pragma unroll
        for (int nt = 0; nt < 8; nt++) {
            int row0 = mwarp * 64 + mt * 16 + g;
            int col0 = nwarp * 64 + nt * 8 + 2 * tg;
            #pragma unroll
            for (int q = 0; q < 4; q++) {
                int col = col0 + (q & 1);
                int row = row0 + (q >> 1) * 8;
                float v = d[mt][nt][q] + b2o[col]
                        + x[(size_t)col * HW + t0 + row] + S[col * 133 + row];
                out[(size_t)col * HW + t0 + row] = v;
            }
        }
    }
}

// ---------------------------------------------------------------------------
extern "C" void kernel_launch(void* const* d_in, const int* in_sizes, int n_in,
                              void* d_out, int out_size) {
    const float* x        = (const float*)d_in[0];
    const float* norm1_g  = (const float*)d_in[1];
    const float* norm1_b  = (const float*)d_in[2];
    const float* qkv_r    = (const float*)d_in[3];
    const float* proj_r_w = (const float*)d_in[4];
    const float* proj_r_b = (const float*)d_in[5];
    const float* table_r  = (const float*)d_in[6];
    const float* qkv_a    = (const float*)d_in[7];
    const float* proj_a_w = (const float*)d_in[8];
    const float* proj_a_b = (const float*)d_in[9];
    const float* table_a  = (const float*)d_in[10];
    const float* norm2_g  = (const float*)d_in[11];
    const float* norm2_b  = (const float*)d_in[12];
    const float* mlp_w1   = (const float*)d_in[13];
    const float* mlp_b1   = (const float*)d_in[14];
    const float* mlp_w2   = (const float*)d_in[15];
    const float* mlp_b2   = (const float*)d_in[16];
    float* out = (float*)d_out;

    cudaFuncSetAttribute(attn_kernel, cudaFuncAttributeMaxDynamicSharedMemorySize, ATTN_SMEM);
    cudaFuncSetAttribute(mlp1_kernel, cudaFuncAttributeMaxDynamicSharedMemorySize, M1_SMEM);
    cudaFuncSetAttribute(mlp2_kernel, cudaFuncAttributeMaxDynamicSharedMemorySize, M2_SMEM);

    ln1_kernel<<<2048, 256>>>(x, norm1_g, norm1_b);
    bias_kernel<<<1, 256>>>(table_r, table_a);
    wfmt_kernel<<<2048, 256>>>(mlp_w1, mlp_w2);
    attn_kernel<<<dim3(1024, 2), 256, ATTN_SMEM>>>(qkv_r, proj_r_w, proj_r_b,
                                                   qkv_a, proj_a_w, proj_a_b);
    mlp1_kernel<<<512, 256, M1_SMEM>>>(x, norm2_g, norm2_b, mlp_b1);
    mlp2_kernel<<<512, 256, M2_SMEM>>>(x, mlp_b2, out);
}

// round 9
// speedup vs baseline: 3.9866x; 1.3852x over previous
#include <cuda_runtime.h>
#include <cstdint>

#define HW 65536

__device__ float g_xn[HW * 256];
__device__ float g_x1[HW * 256];
__device__ float g_bias[2 * 2 * 64 * 64];
__device__ float g_h[1024 * HW];          // H scratch, layout [k][token]
__device__ float g_w1f[4 * 8 * 8192];     // W1 tf32, frag order [jb][kc][8192]
__device__ float g_w2f[32 * 8192];        // W2 tf32, frag order [kc][8192]
__device__ float g_wqkvf[2 * 3 * 4 * 4096]; // Wqkv tf32 frag order [br][nb][kc][4096]
__device__ float g_wpf[2 * 4 * 4096];       // Wproj tf32 frag order [br][kc][4096]

__device__ __forceinline__ uint32_t f2tf32(float v) {
    uint32_t u; asm("cvt.rna.tf32.f32 %0, %1;" : "=r"(u) : "f"(v)); return u;
}
__device__ __forceinline__ uint32_t smem_u32(const void* p) {
    uint32_t a;
    asm("{ .reg .u64 t; cvta.to.shared.u64 t, %1; cvt.u32.u64 %0, t; }" : "=r"(a) : "l"(p));
    return a;
}
__device__ __forceinline__ void cp16(uint32_t dst, const void* src) {
    asm volatile("cp.async.cg.shared.global [%0], [%1], 16;" :: "r"(dst), "l"(src));
}
__device__ __forceinline__ void cp4(uint32_t dst, const void* src) {
    asm volatile("cp.async.ca.shared.global [%0], [%1], 4;" :: "r"(dst), "l"(src));
}
#define CP_COMMIT() asm volatile("cp.async.commit_group;" ::: "memory")
#define CP_WAIT1()  asm volatile("cp.async.wait_group 1;" ::: "memory")
#define CP_WAIT0()  asm volatile("cp.async.wait_group 0;" ::: "memory")

__device__ __forceinline__ void mma8(float* d, const uint32_t* a, const uint32_t* b) {
    asm volatile("mma.sync.aligned.m16n8k8.row.col.f32.tf32.tf32.f32 "
        "{%0,%1,%2,%3}, {%4,%5,%6,%7}, {%8,%9}, {%0,%1,%2,%3};"
        : "+f"(d[0]), "+f"(d[1]), "+f"(d[2]), "+f"(d[3])
        : "r"(a[0]), "r"(a[1]), "r"(a[2]), "r"(a[3]), "r"(b[0]), "r"(b[1]));
}
__device__ __forceinline__ float gelu(float v) {
    return 0.5f * v * (1.f + erff(v * 0.70710678118f));
}
// A fragment float offset: rows (tok), k (c)
__device__ __forceinline__ int a_off(int tok, int c) {
    return ((c >> 3) * 8 + (tok >> 4)) * 128 + ((c & 3) * 8 + (tok & 7)) * 4
         + ((tok >> 3) & 1) + 2 * ((c >> 2) & 1);
}
__device__ __forceinline__ int a_slot(int tok, int c) { return a_off(tok, c); }
// B fragment float offset for N=128 tiles: k (kk), col (n)
__device__ __forceinline__ int b16_off(int kk, int n) {
    return (((kk >> 3) * 16 + (n >> 3)) * 4 + (kk & 3)) * 16 + (n & 7) * 2 + ((kk >> 2) & 1);
}

// ---------------- LN1 ----------------
__global__ void __launch_bounds__(256) ln1_kernel(const float* __restrict__ x,
                                                  const float* __restrict__ g,
                                                  const float* __restrict__ b) {
    __shared__ float s[256][33];
    __shared__ float mu[32], rs[32];
    int t0 = blockIdx.x * 32;
    int tid = threadIdx.x, lane = tid & 31, wid = tid >> 5;
    #pragma unroll
    for (int c = wid; c < 256; c += 8) s[c][lane] = x[c * HW + t0 + lane];
    __syncthreads();
    for (int it = 0; it < 4; it++) {
        int tok = wid * 4 + it;
        float sum = 0.f, sq = 0.f;
        #pragma unroll
        for (int j = 0; j < 8; j++) { float v = s[lane + 32 * j][tok]; sum += v; sq += v * v; }
        #pragma unroll
        for (int o = 16; o; o >>= 1) { sum += __shfl_down_sync(~0u, sum, o); sq += __shfl_down_sync(~0u, sq, o); }
        if (lane == 0) {
            float m = sum * (1.f / 256.f);
            mu[tok] = m; rs[tok] = rsqrtf(sq * (1.f / 256.f) - m * m + 1e-5f);
        }
    }
    __syncthreads();
    float gc = g[tid], bc = b[tid];
    for (int k = 0; k < 32; k++)
        g_xn[(t0 + k) * 256 + tid] = (s[tid][k] - mu[k]) * rs[k] * gc + bc;
}

// ---------------- bias tables ----------------
__global__ void bias_kernel(const float* __restrict__ tr, const float* __restrict__ ta) {
    for (int idx = threadIdx.x; idx < 16384; idx += blockDim.x) {
        int br = idx >> 13, rem = idx & 8191;
        int h = rem >> 12, n = (rem >> 6) & 63, m = rem & 63;
        int Wh = br ? 4 : 16, Ww = br ? 16 : 4, lg = br ? 4 : 2;
        int ridx = ((n >> lg) - (m >> lg) + Wh - 1) * (2 * Ww - 1) + ((n & (Ww - 1)) - (m & (Ww - 1)) + Ww - 1);
        g_bias[idx] = (br ? ta : tr)[ridx * 2 + h];
    }
}

// ---------------- MLP weight pre-format ----------------
__global__ void __launch_bounds__(256) wfmt_kernel(const float* __restrict__ W1,
                                                   const float* __restrict__ W2) {
    int idx = blockIdx.x * 256 + threadIdx.x;
    int r = idx & 8191;
    int hf = r & 1, g = (r >> 1) & 7, tig = (r >> 4) & 3, nt = (r >> 6) & 31, kb = r >> 11;
    int kk = kb * 8 + hf * 4 + tig, n = nt * 8 + g;
    if (idx < 262144) {
        int jb = idx >> 16, kc = (idx >> 13) & 7;
        g_w1f[idx] = __uint_as_float(f2tf32(W1[(size_t)(kc * 32 + kk) * 1024 + jb * 256 + n]));
    } else {
        int j = idx - 262144;
        int kc = j >> 13;
        g_w2f[j] = __uint_as_float(f2tf32(W2[(size_t)(kc * 32 + kk) * 256 + n]));
    }
}

// ---------------- attention weight pre-format (b16 tiles, N=128) ----------------
__global__ void __launch_bounds__(256) wfmt2_kernel(
    const float* __restrict__ Wq_r, const float* __restrict__ Wp_r,
    const float* __restrict__ Wq_a, const float* __restrict__ Wp_a)
{
    int idx = blockIdx.x * 256 + threadIdx.x;      // 0..131071
    int r = idx & 4095;
    int hf = r & 1, gg = (r >> 1) & 7, tig = (r >> 4) & 3, nt = (r >> 6) & 15, kb = r >> 10;
    int kk = kb * 8 + hf * 4 + tig, n = nt * 8 + gg;
    if (idx < 98304) {
        int br = idx / 49152;
        int r0 = idx % 49152;
        int nb = r0 >> 14, kc = (r0 >> 12) & 3;
        const float* W = br ? Wq_a : Wq_r;
        g_wqkvf[idx] = __uint_as_float(f2tf32(W[(size_t)(kc * 32 + kk) * 384 + nb * 128 + n]));
    } else {
        int j = idx - 98304;
        int br = j >> 14, kc = (j >> 12) & 3;
        const float* W = br ? Wp_a : Wp_r;
        g_wpf[j] = __uint_as_float(f2tf32(W[(size_t)(kc * 32 + kk) * 128 + n]));
    }
}

// ===========================================================================
// Tensor-core window attention. CTA = 2 windows (128 tokens) of one branch.
// smem float regions: AX[0,16384) X-frags->V-frags | QA[16384,32768) Xplain/Q/P/epi
// KB[32768,49152) K-frags/red/O-frags | BB[49152,57344) cp.async staging
// ===========================================================================
#define ATTN_SMEM 229376
__device__ __forceinline__ int tok_t(int pair, int n, int lg, int nWb, int Wh, int Ww) {
    int w = n >> 6, nl = n & 63;
    int wi = pair * 2 + w;
    int hb = wi / nWb, wb = wi - hb * nWb;
    return ((hb * Wh + (nl >> lg)) << 8) + wb * Ww + (nl & (Ww - 1));
}

__global__ void __launch_bounds__(256, 1) attn_kernel(
    const float* __restrict__ bp_r, const float* __restrict__ bp_a)
{
    extern __shared__ float sm[];
    float* AX = sm;
    float* QA = sm + 16384;
    float* KB = sm + 32768;
    float* BB = sm + 49152;
    float* red_max = KB;          // overlay, alive only during softmax
    float* red_sum = KB + 512;

    int br = blockIdx.y;
    int co = br ? 128 : 0, lg = br ? 4 : 2;
    int Ww = 1 << lg, nWb = br ? 16 : 64, Wh = br ? 4 : 16;
    const float* bp = br ? bp_a : bp_r;
    int pair = blockIdx.x;
    int tid = threadIdx.x, wid = tid >> 5, lane = tid & 31;
    int g = lane >> 2, tg = lane & 3;
    uint32_t bb_addr = smem_u32(sm) + 49152 * 4;

    // ---- phase 0: X plain tile (pitch 130) then a-frag scatter ----
    {
        int k = tid & 127;
        #pragma unroll 2
        for (int it = 0; it < 64; it++) {
            int idx = it * 256 + tid;
            int n = idx >> 7;
            int t = tok_t(pair, n, lg, nWb, Wh, Ww);
            QA[k * 130 + n] = g_xn[t * 256 + co + k];
        }
    }
    __syncthreads();
    {
        #pragma unroll
        for (int i = 0; i < 16; i++) {
            int p = wid * 16 + i;
            int kb = p >> 3, mt = p & 7;
            int k0 = kb * 8 + tg, row = mt * 16 + g;
            uint4 u;
            u.x = f2tf32(QA[k0 * 130 + row]);
            u.y = f2tf32(QA[k0 * 130 + row + 8]);
            u.z = f2tf32(QA[(k0 + 4) * 130 + row]);
            u.w = f2tf32(QA[(k0 + 4) * 130 + row + 8]);
            ((uint4*)AX)[(kb * 8 + mt) * 32 + tg * 8 + g] = u;
        }
    }
    __syncthreads();

    // ---- phase 1: QKV GEMM (12 chunks of 32k x 128n), double-buffered ----
    int mwarp = wid >> 2, nwarp = wid & 3;
    float d[4][4][4];
    #pragma unroll
    for (int mt = 0; mt < 4; mt++)
        #pragma unroll
        for (int nt = 0; nt < 4; nt++)
            #pragma unroll
            for (int q = 0; q < 4; q++) d[mt][nt][q] = 0.f;

    const float* wsrc = g_wqkvf + (size_t)(br * 12) * 4096;
    {
        const float4* s4 = (const float4*)wsrc;
        #pragma unroll
        for (int i = 0; i < 4; i++) cp16(bb_addr + (i * 256 + tid) * 16, s4 + i * 256 + tid);
        CP_COMMIT();
    }
    for (int s = 0; s < 12; s++) {
        if (s < 11) {
            const float4* s4 = (const float4*)(wsrc + (s + 1) * 4096);
            uint32_t db = bb_addr + ((s + 1) & 1) * 16384;
            #pragma unroll
            for (int i = 0; i < 4; i++) cp16(db + (i * 256 + tid) * 16, s4 + i * 256 + tid);
            CP_COMMIT();
            CP_WAIT1();
        } else CP_WAIT0();
        __syncthreads();
        int kc = s & 3;
        const uint2* Bu = (const uint2*)(BB + (s & 1) * 4096);
        const uint4* Au = (const uint4*)AX;
        #pragma unroll
        for (int kbl = 0; kbl < 4; kbl++) {
            uint32_t a[4][4], b[4][2];
            #pragma unroll
            for (int mt = 0; mt < 4; mt++)
                *(uint4*)a[mt] = Au[((kc * 4 + kbl) * 8 + mwarp * 4 + mt) * 32 + tg * 8 + g];
            #pragma unroll
            for (int nt = 0; nt < 4; nt++)
                *(uint2*)b[nt] = Bu[((kbl * 16 + nwarp * 4 + nt) * 4 + tg) * 8 + g];
            #pragma unroll
            for (int mt = 0; mt < 4; mt++)
                #pragma unroll
                for (int nt = 0; nt < 4; nt++)
                    mma8(d[mt][nt], a[mt], b[nt]);
        }
        __syncthreads();
        if (kc == 3) {
            int nb = s >> 2;
            #pragma unroll
            for (int mt = 0; mt < 4; mt++) {
                #pragma unroll
                for (int nt = 0; nt < 4; nt++) {
                    #pragma unroll
                    for (int q = 0; q < 4; q++) {
                        int row = mwarp * 64 + mt * 16 + g + (q >> 1) * 8;
                        int col = nwarp * 32 + nt * 8 + 2 * tg + (q & 1);
                        uint32_t v = f2tf32(d[mt][nt][q]);
                        if (nb == 0)      QA[a_off(row, col)] = __uint_as_float(v);
                        else if (nb == 1) KB[b16_off(col, row)] = __uint_as_float(v);
                        else              AX[b16_off(row, col)] = __uint_as_float(v);
                        d[mt][nt][q] = 0.f;
                    }
                }
            }
            __syncthreads();
        }
    }

    // ---- phase 2: S = Q K^T, softmax ----
    int w = wid >> 2, h = (wid >> 1) & 1, half = wid & 1;
    {
        const uint4* Qa = (const uint4*)QA;
        const uint2* Kb = (const uint2*)KB;
        #pragma unroll
        for (int kbl = 0; kbl < 8; kbl++) {
            uint32_t a[4][4], b[4][2];
            #pragma unroll
            for (int mt = 0; mt < 4; mt++)
                *(uint4*)a[mt] = Qa[((h * 8 + kbl) * 8 + w * 4 + mt) * 32 + tg * 8 + g];
            #pragma unroll
            for (int nt = 0; nt < 4; nt++)
                *(uint2*)b[nt] = Kb[(((h * 8 + kbl) * 16 + w * 8 + half * 4 + nt) * 4 + tg) * 8 + g];
            #pragma unroll
            for (int mt = 0; mt < 4; mt++)
                #pragma unroll
                for (int nt = 0; nt < 4; nt++)
                    mma8(d[mt][nt], a[mt], b[nt]);
        }
    }
    __syncthreads();   // K reads complete; KB reusable for red

    const float* bias = g_bias + (br * 2 + h) * 4096;
    #pragma unroll
    for (int mt = 0; mt < 4; mt++) {
        #pragma unroll
        for (int nt = 0; nt < 4; nt++) {
            int rr = mt * 16 + g, cc = half * 32 + nt * 8 + 2 * tg;
            float2 b0 = *(const float2*)(bias + rr * 64 + cc);
            float2 b1 = *(const float2*)(bias + (rr + 8) * 64 + cc);
            d[mt][nt][0] = d[mt][nt][0] * 0.125f + b0.x;
            d[mt][nt][1] = d[mt][nt][1] * 0.125f + b0.y;
            d[mt][nt][2] = d[mt][nt][2] * 0.125f + b1.x;
            d[mt][nt][3] = d[mt][nt][3] * 0.125f + b1.y;
        }
    }
    int whb = ((w * 2 + h) * 2 + half) * 64;
    #pragma unroll
    for (int mt = 0; mt < 4; mt++) {
        float m0 = -1e30f, m1 = -1e30f;
        #pragma unroll
        for (int nt = 0; nt < 4; nt++) {
            m0 = fmaxf(m0, fmaxf(d[mt][nt][0], d[mt][nt][1]));
            m1 = fmaxf(m1, fmaxf(d[mt][nt][2], d[mt][nt][3]));
        }
        m0 = fmaxf(m0, __shfl_xor_sync(~0u, m0, 1)); m0 = fmaxf(m0, __shfl_xor_sync(~0u, m0, 2));
        m1 = fmaxf(m1, __shfl_xor_sync(~0u, m1, 1)); m1 = fmaxf(m1, __shfl_xor_sync(~0u, m1, 2));
        red_max[whb + mt * 16 + g] = m0;
        red_max[whb + mt * 16 + g + 8] = m1;
    }
    __syncthreads();
    int whb0 = ((w * 2 + h) * 2) * 64;
    #pragma unroll
    for (int mt = 0; mt < 4; mt++) {
        float M0 = fmaxf(red_max[whb0 + mt * 16 + g], red_max[whb0 + 64 + mt * 16 + g]);
        float M1 = fmaxf(red_max[whb0 + mt * 16 + g + 8], red_max[whb0 + 64 + mt * 16 + g + 8]);
        float s0 = 0.f, s1 = 0.f;
        #pragma unroll
        for (int nt = 0; nt < 4; nt++) {
            d[mt][nt][0] = expf(d[mt][nt][0] - M0); s0 += d[mt][nt][0];
            d[mt][nt][1] = expf(d[mt][nt][1] - M0); s0 += d[mt][nt][1];
            d[mt][nt][2] = expf(d[mt][nt][2] - M1); s1 += d[mt][nt][2];
            d[mt][nt][3] = expf(d[mt][nt][3] - M1); s1 += d[mt][nt][3];
        }
        s0 += __shfl_xor_sync(~0u, s0, 1); s0 += __shfl_xor_sync(~0u, s0, 2);
        s1 += __shfl_xor_sync(~0u, s1, 1); s1 += __shfl_xor_sync(~0u, s1, 2);
        red_sum[whb + mt * 16 + g] = s0;
        red_sum[whb + mt * 16 + g + 8] = s1;
    }
    __syncthreads();
    #pragma unroll
    for (int mt = 0; mt < 4; mt++) {
        float i0 = 1.f / (red_sum[whb0 + mt * 16 + g] + red_sum[whb0 + 64 + mt * 16 + g]);
        float i1 = 1.f / (red_sum[whb0 + mt * 16 + g + 8] + red_sum[whb0 + 64 + mt * 16 + g + 8]);
        #pragma unroll
        for (int nt = 0; nt < 4; nt++) {
            #pragma unroll
            for (int q = 0; q < 4; q++) {
                int row = w * 64 + mt * 16 + g + (q >> 1) * 8;
                int m = half * 32 + nt * 8 + 2 * tg + (q & 1);
                float p = d[mt][nt][q] * ((q >> 1) ? i1 : i0);
                QA[a_off(row, h * 64 + m)] = __uint_as_float(f2tf32(p));  // FIX: head-keyed
                d[mt][nt][q] = 0.f;
            }
        }
    }
    __syncthreads();

    // ---- phase 3: O = P V ----
    {
        const uint4* Pa = (const uint4*)QA;
        const uint2* Vb = (const uint2*)AX;
        #pragma unroll
        for (int kbl = 0; kbl < 8; kbl++) {
            uint32_t a[4][4], b[4][2];
            #pragma unroll
            for (int mt = 0; mt < 4; mt++)
                *(uint4*)a[mt] = Pa[((h * 8 + kbl) * 8 + w * 4 + mt) * 32 + tg * 8 + g];  // FIX: head-keyed
            #pragma unroll
            for (int nt = 0; nt < 4; nt++)
                *(uint2*)b[nt] = Vb[(((w * 8 + kbl) * 16 + h * 8 + half * 4 + nt) * 4 + tg) * 8 + g];
            #pragma unroll
            for (int mt = 0; mt < 4; mt++)
                #pragma unroll
                for (int nt = 0; nt < 4; nt++)
                    mma8(d[mt][nt], a[mt], b[nt]);
        }
        #pragma unroll
        for (int mt = 0; mt < 4; mt++) {
            #pragma unroll
            for (int nt = 0; nt < 4; nt++) {
                #pragma unroll
                for (int q = 0; q < 4; q++) {
                    int row = w * 64 + mt * 16 + g + (q >> 1) * 8;
                    int col = h * 64 + half * 32 + nt * 8 + 2 * tg + (q & 1);
                    KB[a_off(row, col)] = __uint_as_float(f2tf32(d[mt][nt][q]));
                    d[mt][nt][q] = 0.f;
                }
            }
        }
    }
    __syncthreads();

    // ---- phase 4: proj = O @ Wp, 4 chunks double-buffered ----
    const float* psrc = g_wpf + (size_t)(br * 4) * 4096;
    {
        const float4* s4 = (const float4*)psrc;
        #pragma unroll
        for (int i = 0; i < 4; i++) cp16(bb_addr + (i * 256 + tid) * 16, s4 + i * 256 + tid);
        CP_COMMIT();
    }
    for (int kc = 0; kc < 4; kc++) {
        if (kc < 3) {
            const float4* s4 = (const float4*)(psrc + (kc + 1) * 4096);
            uint32_t db = bb_addr + ((kc + 1) & 1) * 16384;
            #pragma unroll
            for (int i = 0; i < 4; i++) cp16(db + (i * 256 + tid) * 16, s4 + i * 256 + tid);
            CP_COMMIT();
            CP_WAIT1();
        } else CP_WAIT0();
        __syncthreads();
        const uint2* Bu = (const uint2*)(BB + (kc & 1) * 4096);
        const uint4* Au = (const uint4*)KB;
        #pragma unroll
        for (int kbl = 0; kbl < 4; kbl++) {
            uint32_t a[4][4], b[4][2];
            #pragma unroll
            for (int mt = 0; mt < 4; mt++)
                *(uint4*)a[mt] = Au[((kc * 4 + kbl) * 8 + mwarp * 4 + mt) * 32 + tg * 8 + g];
            #pragma unroll
            for (int nt = 0; nt < 4; nt++)
                *(uint2*)b[nt] = Bu[((kbl * 16 + nwarp * 4 + nt) * 4 + tg) * 8 + g];
            #pragma unroll
            for (int mt = 0; mt < 4; mt++)
                #pragma unroll
                for (int nt = 0; nt < 4; nt++)
                    mma8(d[mt][nt], a[mt], b[nt]);
        }
        __syncthreads();
    }

    // ---- epilogue: stage [tok][c], then residual + NHWC write ----
    float* Sx = QA;        // pitch 132, spills into dead KB
    #pragma unroll
    for (int mt = 0; mt < 4; mt++) {
        #pragma unroll
        for (int nt = 0; nt < 4; nt++) {
            #pragma unroll
            for (int q = 0; q < 4; q++) {
                int row = mwarp * 64 + mt * 16 + g + (q >> 1) * 8;
                int col = nwarp * 32 + nt * 8 + 2 * tg + (q & 1);
                Sx[row * 132 + col] = d[mt][nt][q] + bp[col];
            }
        }
    }
    __syncthreads();
    {
        int c = tid & 127;
        #pragma unroll 2
        for (int it = 0; it < 64; it++) {
            int idx = it * 256 + tid;
            int n = idx >> 7;
            int t = tok_t(pair, n, lg, nWb, Wh, Ww);
            g_x1[t * 256 + co + c] = Sx[n * 132 + c] + g_xn[t * 256 + co + c];
        }
    }
}

// ===========================================================================
// MLP1: LN2 + GEMM1 + GELU -> g_h [k][tok]. cp.async weights from g_w1f.
// ===========================================================================
#define M1_SMEM 201216
__global__ void __launch_bounds__(256, 1) mlp1_kernel(
    const float* __restrict__ x, const float* __restrict__ g2, const float* __restrict__ b2,
    const float* __restrict__ b1)
{
    extern __shared__ float sm[];
    float* A    = sm;
    float* S    = sm + 32768;
    float* tmpS = sm + 49280;
    float* tmpQ = sm + 49536;
    float* tsum = sm + 49792;
    float* tsq  = sm + 49920;
    float* mu   = sm + 50048;
    float* rs   = sm + 50176;

    int tid = threadIdx.x, wid = tid >> 5, lane = tid & 31;
    int t0 = blockIdx.x * 128;
    uint32_t bbase = smem_u32(sm) + 131072;

    if (tid < 128) { tsum[tid] = 0.f; tsq[tid] = 0.f; }
    for (int h = 0; h < 2; h++) {
        __syncthreads();
        #pragma unroll 4
        for (int it = 0; it < 64; it++) {
            int idx = it * 256 + tid;
            int n = idx & 127, cl = idx >> 7;
            S[cl * 129 + n] = x[(size_t)(h * 128 + cl) * HW + t0 + n];
        }
        __syncthreads();
        #pragma unroll 4
        for (int it = 0; it < 64; it++) {
            int idx = it * 256 + tid;
            int cl = idx & 127, n = idx >> 7;
            S[cl * 129 + n] += g_x1[(size_t)(t0 + n) * 256 + h * 128 + cl];
        }
        __syncthreads();
        {
            int n = tid & 127, part = tid >> 7;
            float s1 = 0.f, s2 = 0.f;
            for (int cl = part * 64; cl < part * 64 + 64; cl++) {
                float v = S[cl * 129 + n];
                s1 += v; s2 += v * v;
                A[a_slot(n, h * 128 + cl)] = v;
            }
            tmpS[part * 128 + n] = s1; tmpQ[part * 128 + n] = s2;
        }
        __syncthreads();
        if (tid < 128) {
            tsum[tid] += tmpS[tid] + tmpS[128 + tid];
            tsq[tid]  += tmpQ[tid] + tmpQ[128 + tid];
        }
    }
    __syncthreads();
    if (tid < 128) {
        float m = tsum[tid] * (1.f / 256.f);
        mu[tid] = m;
        rs[tid] = rsqrtf(tsq[tid] * (1.f / 256.f) - m * m + 1e-5f);
    }
    __syncthreads();
    {
        int tok = tid & 127, half = tid >> 7;
        float m = mu[tok], r = rs[tok];
        for (int c = half * 128; c < half * 128 + 128; c++) {
            int idx = a_slot(tok, c);
            A[idx] = __uint_as_float(f2tf32((A[idx] - m) * r * g2[c] + b2[c]));
        }
    }
    __syncthreads();

    int mwarp = wid >> 2, nwarp = wid & 3;
    int g = lane >> 2, tg = lane & 3;

    for (int jb = 0; jb < 4; jb++) {
        float d[4][8][4];
        #pragma unroll
        for (int mt = 0; mt < 4; mt++)
            #pragma unroll
            for (int nt = 0; nt < 8; nt++)
                #pragma unroll
                for (int q = 0; q < 4; q++) d[mt][nt][q] = 0.f;

        {
            const float4* src = (const float4*)(g_w1f + (size_t)(jb * 8) * 8192);
            #pragma unroll
            for (int i = 0; i < 8; i++) cp16(bbase + (i * 256 + tid) * 16, src + i * 256 + tid);
            CP_COMMIT();
        }
        for (int kc = 0; kc < 8; kc++) {
            if (kc < 7) {
                const float4* src = (const float4*)(g_w1f + (size_t)(jb * 8 + kc + 1) * 8192);
                uint32_t db = bbase + ((kc + 1) & 1) * 32768;
                #pragma unroll
                for (int i = 0; i < 8; i++) cp16(db + (i * 256 + tid) * 16, src + i * 256 + tid);
                CP_COMMIT();
                CP_WAIT1();
            } else CP_WAIT0();
            __syncthreads();
            const float* Bc = sm + 32768 + (kc & 1) * 8192;
            #pragma unroll
            for (int kbl = 0; kbl < 4; kbl++) {
                uint32_t a[4][4], b[8][2];
                const uint4* Au = (const uint4*)A;
                #pragma unroll
                for (int mt = 0; mt < 4; mt++)
                    *(uint4*)a[mt] = Au[((kc * 4 + kbl) * 8 + mwarp * 4 + mt) * 32 + tg * 8 + g];
                const uint2* Bu = (const uint2*)Bc;
                #pragma unroll
                for (int nt = 0; nt < 8; nt++)
                    *(uint2*)b[nt] = Bu[(kbl * 32 + nwarp * 8 + nt) * 32 + tg * 8 + g];
                #pragma unroll
                for (int mt = 0; mt < 4; mt++)
                    #pragma unroll
                    for (int nt = 0; nt < 8; nt++)
                        mma8(d[mt][nt], a[mt], b[nt]);
            }
            __syncthreads();
        }
        #pragma unroll
        for (int mt = 0; mt < 4; mt++) {
            #pragma unroll
            for (int nt = 0; nt < 8; nt++) {
                int row0 = mwarp * 64 + mt * 16 + g;
                int col0 = jb * 256 + nwarp * 64 + nt * 8 + 2 * tg;
                float b0v = b1[col0], b1v = b1[col0 + 1];
                float v0 = gelu(d[mt][nt][0] + b0v);
                float v1 = gelu(d[mt][nt][1] + b1v);
                float v2 = gelu(d[mt][nt][2] + b0v);
                float v3 = gelu(d[mt][nt][3] + b1v);
                g_h[(size_t)col0 * HW + t0 + row0]           = __uint_as_float(f2tf32(v0));
                g_h[(size_t)(col0 + 1) * HW + t0 + row0]     = __uint_as_float(f2tf32(v1));
                g_h[(size_t)col0 * HW + t0 + row0 + 8]       = __uint_as_float(f2tf32(v2));
                g_h[(size_t)(col0 + 1) * HW + t0 + row0 + 8] = __uint_as_float(f2tf32(v3));
            }
        }
    }
}

// ===========================================================================
// MLP2: GEMM2 + residual -> out (NCHW)
// ===========================================================================
#define M2_SMEM 136192
__global__ void __launch_bounds__(256, 1) mlp2_kernel(
    const float* __restrict__ x, const float* __restrict__ b2o, float* __restrict__ out)
{
    extern __shared__ float sm[];
    float* S = sm;

    int tid = threadIdx.x, wid = tid >> 5, lane = tid & 31;
    int t0 = blockIdx.x * 128;
    int mwarp = wid >> 2, nwarp = wid & 3;
    int g = lane >> 2, tg = lane & 3;
    uint32_t abase = smem_u32(sm);
    uint32_t bbase = abase + 32768;
    int tokA = tid & 127, hiA = tid >> 7;

    float d[4][8][4];
    #pragma unroll
    for (int mt = 0; mt < 4; mt++)
        #pragma unroll
        for (int nt = 0; nt < 8; nt++)
            #pragma unroll
            for (int q = 0; q < 4; q++) d[mt][nt][q] = 0.f;

    {
        #pragma unroll
        for (int i = 0; i < 16; i++) {
            int kk = i * 2 + hiA;
            cp4(abase + (uint32_t)a_slot(tokA, kk) * 4, g_h + (size_t)kk * HW + t0 + tokA);
        }
        const float4* src = (const float4*)(g_w2f);
        #pragma unroll
        for (int i = 0; i < 8; i++) cp16(bbase + (i * 256 + tid) * 16, src + i * 256 + tid);
        CP_COMMIT();
    }
    for (int kc = 0; kc < 32; kc++) {
        if (kc < 31) {
            uint32_t da = abase + ((kc + 1) & 1) * 16384;
            #pragma unroll
            for (int i = 0; i < 16; i++) {
                int kk = i * 2 + hiA;
                cp4(da + (uint32_t)a_slot(tokA, kk) * 4,
                    g_h + (size_t)((kc + 1) * 32 + kk) * HW + t0 + tokA);
            }
            const float4* src = (const float4*)(g_w2f + (size_t)(kc + 1) * 8192);
            uint32_t db = bbase + ((kc + 1) & 1) * 32768;
            #pragma unroll
            for (int i = 0; i < 8; i++) cp16(db + (i * 256 + tid) * 16, src + i * 256 + tid);
            CP_COMMIT();
            CP_WAIT1();
        } else CP_WAIT0();
        __syncthreads();
        const float* Ac = sm + (kc & 1) * 4096;
        const float* Bc = sm + 8192 + (kc & 1) * 8192;
        #pragma unroll
        for (int kbl = 0; kbl < 4; kbl++) {
            uint32_t a[4][4], b[8][2];
            const uint4* Au = (const uint4*)Ac;
            #pragma unroll
            for (int mt = 0; mt < 4; mt++)
                *(uint4*)a[mt] = Au[(kbl * 8 + mwarp * 4 + mt) * 32 + tg * 8 + g];
            const uint2* Bu = (const uint2*)Bc;
            #pragma unroll
            for (int nt = 0; nt < 8; nt++)
                *(uint2*)b[nt] = Bu[(kbl * 32 + nwarp * 8 + nt) * 32 + tg * 8 + g];
            #pragma unroll
            for (int mt = 0; mt < 4; mt++)
                #pragma unroll
                for (int nt = 0; nt < 8; nt++)
                    mma8(d[mt][nt], a[mt], b[nt]);
        }
        __syncthreads();
    }

    #pragma unroll 4
    for (int i = 0; i < 128; i++)
        S[tid * 133 + i] = g_x1[(size_t)(t0 + i) * 256 + tid];
    __syncthreads();

    #pragma unroll
    for (int mt = 0; mt < 4; mt++) {
        #pragma unroll
        for (int nt = 0; nt < 8; nt++) {
            int row0 = mwarp * 64 + mt * 16 + g;
            int col0 = nwarp * 64 + nt * 8 + 2 * tg;
            #pragma unroll
            for (int q = 0; q < 4; q++) {
                int col = col0 + (q & 1);
                int row = row0 + (q >> 1) * 8;
                float v = d[mt][nt][q] + b2o[col]
                        + x[(size_t)col * HW + t0 + row] + S[col * 133 + row];
                out[(size_t)col * HW + t0 + row] = v;
            }
        }
    }
}

// ---------------------------------------------------------------------------
extern "C" void kernel_launch(void* const* d_in, const int* in_sizes, int n_in,
                              void* d_out, int out_size) {
    const float* x        = (const float*)d_in[0];
    const float* norm1_g  = (const float*)d_in[1];
    const float* norm1_b  = (const float*)d_in[2];
    const float* qkv_r    = (const float*)d_in[3];
    const float* proj_r_w = (const float*)d_in[4];
    const float* proj_r_b = (const float*)d_in[5];
    const float* table_r  = (const float*)d_in[6];
    const float* qkv_a    = (const float*)d_in[7];
    const float* proj_a_w = (const float*)d_in[8];
    const float* proj_a_b = (const float*)d_in[9];
    const float* table_a  = (const float*)d_in[10];
    const float* norm2_g  = (const float*)d_in[11];
    const float* norm2_b  = (const float*)d_in[12];
    const float* mlp_w1   = (const float*)d_in[13];
    const float* mlp_b1   = (const float*)d_in[14];
    const float* mlp_w2   = (const float*)d_in[15];
    const float* mlp_b2   = (const float*)d_in[16];
    float* out = (float*)d_out;

    cudaFuncSetAttribute(attn_kernel, cudaFuncAttributeMaxDynamicSharedMemorySize, ATTN_SMEM);
    cudaFuncSetAttribute(mlp1_kernel, cudaFuncAttributeMaxDynamicSharedMemorySize, M1_SMEM);
    cudaFuncSetAttribute(mlp2_kernel, cudaFuncAttributeMaxDynamicSharedMemorySize, M2_SMEM);

    ln1_kernel<<<2048, 256>>>(x, norm1_g, norm1_b);
    bias_kernel<<<1, 256>>>(table_r, table_a);
    wfmt_kernel<<<2048, 256>>>(mlp_w1, mlp_w2);
    wfmt2_kernel<<<512, 256>>>(qkv_r, proj_r_w, qkv_a, proj_a_w);
    attn_kernel<<<dim3(512, 2), 256, ATTN_SMEM>>>(proj_r_b, proj_a_b);
    mlp1_kernel<<<512, 256, M1_SMEM>>>(x, norm2_g, norm2_b, mlp_b1);
    mlp2_kernel<<<512, 256, M2_SMEM>>>(x, mlp_b2, out);
}

// round 10
// speedup vs baseline: 4.0076x; 1.0052x over previous
#include <cuda_runtime.h>
#include <cstdint>

#define HW 65536

__device__ float g_xn[HW * 256];
__device__ float g_x1[HW * 256];
__device__ float g_bias[2 * 2 * 64 * 64];
__device__ float g_hf[512 * 32 * 4096];   // H scratch, frag order [tblk][kc][4096]
__device__ float g_w1f[4 * 8 * 8192];     // W1 tf32, frag order [jb][kc][8192]
__device__ float g_w2f[32 * 8192];        // W2 tf32, frag order [kc][8192]
__device__ float g_wqkvf[2 * 3 * 4 * 4096]; // Wqkv tf32 frag order [br][nb][kc][4096]
__device__ float g_wpf[2 * 4 * 4096];       // Wproj tf32 frag order [br][kc][4096]

__device__ __forceinline__ uint32_t f2tf32(float v) {
    uint32_t u; asm("cvt.rna.tf32.f32 %0, %1;" : "=r"(u) : "f"(v)); return u;
}
__device__ __forceinline__ uint32_t smem_u32(const void* p) {
    uint32_t a;
    asm("{ .reg .u64 t; cvta.to.shared.u64 t, %1; cvt.u32.u64 %0, t; }" : "=r"(a) : "l"(p));
    return a;
}
__device__ __forceinline__ void cp16(uint32_t dst, const void* src) {
    asm volatile("cp.async.cg.shared.global [%0], [%1], 16;" :: "r"(dst), "l"(src));
}
#define CP_COMMIT() asm volatile("cp.async.commit_group;" ::: "memory")
#define CP_WAIT2()  asm volatile("cp.async.wait_group 2;" ::: "memory")
#define CP_WAIT1()  asm volatile("cp.async.wait_group 1;" ::: "memory")
#define CP_WAIT0()  asm volatile("cp.async.wait_group 0;" ::: "memory")

__device__ __forceinline__ void mma8(float* d, const uint32_t* a, const uint32_t* b) {
    asm volatile("mma.sync.aligned.m16n8k8.row.col.f32.tf32.tf32.f32 "
        "{%0,%1,%2,%3}, {%4,%5,%6,%7}, {%8,%9}, {%0,%1,%2,%3};"
        : "+f"(d[0]), "+f"(d[1]), "+f"(d[2]), "+f"(d[3])
        : "r"(a[0]), "r"(a[1]), "r"(a[2]), "r"(a[3]), "r"(b[0]), "r"(b[1]));
}
__device__ __forceinline__ float gelu(float v) {
    return 0.5f * v * (1.f + erff(v * 0.70710678118f));
}
// A fragment float offset: rows (tok), k (c)
__device__ __forceinline__ int a_off(int tok, int c) {
    return ((c >> 3) * 8 + (tok >> 4)) * 128 + ((c & 3) * 8 + (tok & 7)) * 4
         + ((tok >> 3) & 1) + 2 * ((c >> 2) & 1);
}
__device__ __forceinline__ int a_slot(int tok, int c) { return a_off(tok, c); }
// B fragment float offset for N=128 tiles: k (kk), col (n)
__device__ __forceinline__ int b16_off(int kk, int n) {
    return (((kk >> 3) * 16 + (n >> 3)) * 4 + (kk & 3)) * 16 + (n & 7) * 2 + ((kk >> 2) & 1);
}

// ---------------- LN1 ----------------
__global__ void __launch_bounds__(256) ln1_kernel(const float* __restrict__ x,
                                                  const float* __restrict__ g,
                                                  const float* __restrict__ b) {
    __shared__ float s[256][33];
    __shared__ float mu[32], rs[32];
    int t0 = blockIdx.x * 32;
    int tid = threadIdx.x, lane = tid & 31, wid = tid >> 5;
    #pragma unroll
    for (int c = wid; c < 256; c += 8) s[c][lane] = x[c * HW + t0 + lane];
    __syncthreads();
    for (int it = 0; it < 4; it++) {
        int tok = wid * 4 + it;
        float sum = 0.f, sq = 0.f;
        #pragma unroll
        for (int j = 0; j < 8; j++) { float v = s[lane + 32 * j][tok]; sum += v; sq += v * v; }
        #pragma unroll
        for (int o = 16; o; o >>= 1) { sum += __shfl_down_sync(~0u, sum, o); sq += __shfl_down_sync(~0u, sq, o); }
        if (lane == 0) {
            float m = sum * (1.f / 256.f);
            mu[tok] = m; rs[tok] = rsqrtf(sq * (1.f / 256.f) - m * m + 1e-5f);
        }
    }
    __syncthreads();
    float gc = g[tid], bc = b[tid];
    for (int k = 0; k < 32; k++)
        g_xn[(t0 + k) * 256 + tid] = (s[tid][k] - mu[k]) * rs[k] * gc + bc;
}

// ---------------- bias tables ----------------
__global__ void bias_kernel(const float* __restrict__ tr, const float* __restrict__ ta) {
    for (int idx = threadIdx.x; idx < 16384; idx += blockDim.x) {
        int br = idx >> 13, rem = idx & 8191;
        int h = rem >> 12, n = (rem >> 6) & 63, m = rem & 63;
        int Wh = br ? 4 : 16, Ww = br ? 16 : 4, lg = br ? 4 : 2;
        int ridx = ((n >> lg) - (m >> lg) + Wh - 1) * (2 * Ww - 1) + ((n & (Ww - 1)) - (m & (Ww - 1)) + Ww - 1);
        g_bias[idx] = (br ? ta : tr)[ridx * 2 + h];
    }
}

// ---------------- MLP weight pre-format ----------------
__global__ void __launch_bounds__(256) wfmt_kernel(const float* __restrict__ W1,
                                                   const float* __restrict__ W2) {
    int idx = blockIdx.x * 256 + threadIdx.x;
    int r = idx & 8191;
    int hf = r & 1, g = (r >> 1) & 7, tig = (r >> 4) & 3, nt = (r >> 6) & 31, kb = r >> 11;
    int kk = kb * 8 + hf * 4 + tig, n = nt * 8 + g;
    if (idx < 262144) {
        int jb = idx >> 16, kc = (idx >> 13) & 7;
        g_w1f[idx] = __uint_as_float(f2tf32(W1[(size_t)(kc * 32 + kk) * 1024 + jb * 256 + n]));
    } else {
        int j = idx - 262144;
        int kc = j >> 13;
        g_w2f[j] = __uint_as_float(f2tf32(W2[(size_t)(kc * 32 + kk) * 256 + n]));
    }
}

// ---------------- attention weight pre-format (b16 tiles, N=128) ----------------
__global__ void __launch_bounds__(256) wfmt2_kernel(
    const float* __restrict__ Wq_r, const float* __restrict__ Wp_r,
    const float* __restrict__ Wq_a, const float* __restrict__ Wp_a)
{
    int idx = blockIdx.x * 256 + threadIdx.x;      // 0..131071
    int r = idx & 4095;
    int hf = r & 1, gg = (r >> 1) & 7, tig = (r >> 4) & 3, nt = (r >> 6) & 15, kb = r >> 10;
    int kk = kb * 8 + hf * 4 + tig, n = nt * 8 + gg;
    if (idx < 98304) {
        int br = idx / 49152;
        int r0 = idx % 49152;
        int nb = r0 >> 14, kc = (r0 >> 12) & 3;
        const float* W = br ? Wq_a : Wq_r;
        g_wqkvf[idx] = __uint_as_float(f2tf32(W[(size_t)(kc * 32 + kk) * 384 + nb * 128 + n]));
    } else {
        int j = idx - 98304;
        int br = j >> 14, kc = (j >> 12) & 3;
        const float* W = br ? Wp_a : Wp_r;
        g_wpf[j] = __uint_as_float(f2tf32(W[(size_t)(kc * 32 + kk) * 128 + n]));
    }
}

// ===========================================================================
// Tensor-core window attention (unchanged from R9).
// ===========================================================================
#define ATTN_SMEM 229376
__device__ __forceinline__ int tok_t(int pair, int n, int lg, int nWb, int Wh, int Ww) {
    int w = n >> 6, nl = n & 63;
    int wi = pair * 2 + w;
    int hb = wi / nWb, wb = wi - hb * nWb;
    return ((hb * Wh + (nl >> lg)) << 8) + wb * Ww + (nl & (Ww - 1));
}

__global__ void __launch_bounds__(256, 1) attn_kernel(
    const float* __restrict__ bp_r, const float* __restrict__ bp_a)
{
    extern __shared__ float sm[];
    float* AX = sm;
    float* QA = sm + 16384;
    float* KB = sm + 32768;
    float* BB = sm + 49152;
    float* red_max = KB;
    float* red_sum = KB + 512;

    int br = blockIdx.y;
    int co = br ? 128 : 0, lg = br ? 4 : 2;
    int Ww = 1 << lg, nWb = br ? 16 : 64, Wh = br ? 4 : 16;
    const float* bp = br ? bp_a : bp_r;
    int pair = blockIdx.x;
    int tid = threadIdx.x, wid = tid >> 5, lane = tid & 31;
    int g = lane >> 2, tg = lane & 3;
    uint32_t bb_addr = smem_u32(sm) + 49152 * 4;

    {
        int k = tid & 127;
        #pragma unroll 2
        for (int it = 0; it < 64; it++) {
            int idx = it * 256 + tid;
            int n = idx >> 7;
            int t = tok_t(pair, n, lg, nWb, Wh, Ww);
            QA[k * 130 + n] = g_xn[t * 256 + co + k];
        }
    }
    __syncthreads();
    {
        #pragma unroll
        for (int i = 0; i < 16; i++) {
            int p = wid * 16 + i;
            int kb = p >> 3, mt = p & 7;
            int k0 = kb * 8 + tg, row = mt * 16 + g;
            uint4 u;
            u.x = f2tf32(QA[k0 * 130 + row]);
            u.y = f2tf32(QA[k0 * 130 + row + 8]);
            u.z = f2tf32(QA[(k0 + 4) * 130 + row]);
            u.w = f2tf32(QA[(k0 + 4) * 130 + row + 8]);
            ((uint4*)AX)[(kb * 8 + mt) * 32 + tg * 8 + g] = u;
        }
    }
    __syncthreads();

    int mwarp = wid >> 2, nwarp = wid & 3;
    float d[4][4][4];
    #pragma unroll
    for (int mt = 0; mt < 4; mt++)
        #pragma unroll
        for (int nt = 0; nt < 4; nt++)
            #pragma unroll
            for (int q = 0; q < 4; q++) d[mt][nt][q] = 0.f;

    const float* wsrc = g_wqkvf + (size_t)(br * 12) * 4096;
    {
        const float4* s4 = (const float4*)wsrc;
        #pragma unroll
        for (int i = 0; i < 4; i++) cp16(bb_addr + (i * 256 + tid) * 16, s4 + i * 256 + tid);
        CP_COMMIT();
    }
    for (int s = 0; s < 12; s++) {
        if (s < 11) {
            const float4* s4 = (const float4*)(wsrc + (s + 1) * 4096);
            uint32_t db = bb_addr + ((s + 1) & 1) * 16384;
            #pragma unroll
            for (int i = 0; i < 4; i++) cp16(db + (i * 256 + tid) * 16, s4 + i * 256 + tid);
            CP_COMMIT();
            CP_WAIT1();
        } else CP_WAIT0();
        __syncthreads();
        int kc = s & 3;
        const uint2* Bu = (const uint2*)(BB + (s & 1) * 4096);
        const uint4* Au = (const uint4*)AX;
        #pragma unroll
        for (int kbl = 0; kbl < 4; kbl++) {
            uint32_t a[4][4], b[4][2];
            #pragma unroll
            for (int mt = 0; mt < 4; mt++)
                *(uint4*)a[mt] = Au[((kc * 4 + kbl) * 8 + mwarp * 4 + mt) * 32 + tg * 8 + g];
            #pragma unroll
            for (int nt = 0; nt < 4; nt++)
                *(uint2*)b[nt] = Bu[((kbl * 16 + nwarp * 4 + nt) * 4 + tg) * 8 + g];
            #pragma unroll
            for (int mt = 0; mt < 4; mt++)
                #pragma unroll
                for (int nt = 0; nt < 4; nt++)
                    mma8(d[mt][nt], a[mt], b[nt]);
        }
        __syncthreads();
        if (kc == 3) {
            int nb = s >> 2;
            #pragma unroll
            for (int mt = 0; mt < 4; mt++) {
                #pragma unroll
                for (int nt = 0; nt < 4; nt++) {
                    #pragma unroll
                    for (int q = 0; q < 4; q++) {
                        int row = mwarp * 64 + mt * 16 + g + (q >> 1) * 8;
                        int col = nwarp * 32 + nt * 8 + 2 * tg + (q & 1);
                        uint32_t v = f2tf32(d[mt][nt][q]);
                        if (nb == 0)      QA[a_off(row, col)] = __uint_as_float(v);
                        else if (nb == 1) KB[b16_off(col, row)] = __uint_as_float(v);
                        else              AX[b16_off(row, col)] = __uint_as_float(v);
                        d[mt][nt][q] = 0.f;
                    }
                }
            }
            __syncthreads();
        }
    }

    int w = wid >> 2, h = (wid >> 1) & 1, half = wid & 1;
    {
        const uint4* Qa = (const uint4*)QA;
        const uint2* Kb = (const uint2*)KB;
        #pragma unroll
        for (int kbl = 0; kbl < 8; kbl++) {
            uint32_t a[4][4], b[4][2];
            #pragma unroll
            for (int mt = 0; mt < 4; mt++)
                *(uint4*)a[mt] = Qa[((h * 8 + kbl) * 8 + w * 4 + mt) * 32 + tg * 8 + g];
            #pragma unroll
            for (int nt = 0; nt < 4; nt++)
                *(uint2*)b[nt] = Kb[(((h * 8 + kbl) * 16 + w * 8 + half * 4 + nt) * 4 + tg) * 8 + g];
            #pragma unroll
            for (int mt = 0; mt < 4; mt++)
                #pragma unroll
                for (int nt = 0; nt < 4; nt++)
                    mma8(d[mt][nt], a[mt], b[nt]);
        }
    }
    __syncthreads();

    const float* bias = g_bias + (br * 2 + h) * 4096;
    #pragma unroll
    for (int mt = 0; mt < 4; mt++) {
        #pragma unroll
        for (int nt = 0; nt < 4; nt++) {
            int rr = mt * 16 + g, cc = half * 32 + nt * 8 + 2 * tg;
            float2 b0 = *(const float2*)(bias + rr * 64 + cc);
            float2 b1 = *(const float2*)(bias + (rr + 8) * 64 + cc);
            d[mt][nt][0] = d[mt][nt][0] * 0.125f + b0.x;
            d[mt][nt][1] = d[mt][nt][1] * 0.125f + b0.y;
            d[mt][nt][2] = d[mt][nt][2] * 0.125f + b1.x;
            d[mt][nt][3] = d[mt][nt][3] * 0.125f + b1.y;
        }
    }
    int whb = ((w * 2 + h) * 2 + half) * 64;
    #pragma unroll
    for (int mt = 0; mt < 4; mt++) {
        float m0 = -1e30f, m1 = -1e30f;
        #pragma unroll
        for (int nt = 0; nt < 4; nt++) {
            m0 = fmaxf(m0, fmaxf(d[mt][nt][0], d[mt][nt][1]));
            m1 = fmaxf(m1, fmaxf(d[mt][nt][2], d[mt][nt][3]));
        }
        m0 = fmaxf(m0, __shfl_xor_sync(~0u, m0, 1)); m0 = fmaxf(m0, __shfl_xor_sync(~0u, m0, 2));
        m1 = fmaxf(m1, __shfl_xor_sync(~0u, m1, 1)); m1 = fmaxf(m1, __shfl_xor_sync(~0u, m1, 2));
        red_max[whb + mt * 16 + g] = m0;
        red_max[whb + mt * 16 + g + 8] = m1;
    }
    __syncthreads();
    int whb0 = ((w * 2 + h) * 2) * 64;
    #pragma unroll
    for (int mt = 0; mt < 4; mt++) {
        float M0 = fmaxf(red_max[whb0 + mt * 16 + g], red_max[whb0 + 64 + mt * 16 + g]);
        float M1 = fmaxf(red_max[whb0 + mt * 16 + g + 8], red_max[whb0 + 64 + mt * 16 + g + 8]);
        float s0 = 0.f, s1 = 0.f;
        #pragma unroll
        for (int nt = 0; nt < 4; nt++) {
            d[mt][nt][0] = expf(d[mt][nt][0] - M0); s0 += d[mt][nt][0];
            d[mt][nt][1] = expf(d[mt][nt][1] - M0); s0 += d[mt][nt][1];
            d[mt][nt][2] = expf(d[mt][nt][2] - M1); s1 += d[mt][nt][2];
            d[mt][nt][3] = expf(d[mt][nt][3] - M1); s1 += d[mt][nt][3];
        }
        s0 += __shfl_xor_sync(~0u, s0, 1); s0 += __shfl_xor_sync(~0u, s0, 2);
        s1 += __shfl_xor_sync(~0u, s1, 1); s1 += __shfl_xor_sync(~0u, s1, 2);
        red_sum[whb + mt * 16 + g] = s0;
        red_sum[whb + mt * 16 + g + 8] = s1;
    }
    __syncthreads();
    #pragma unroll
    for (int mt = 0; mt < 4; mt++) {
        float i0 = 1.f / (red_sum[whb0 + mt * 16 + g] + red_sum[whb0 + 64 + mt * 16 + g]);
        float i1 = 1.f / (red_sum[whb0 + mt * 16 + g + 8] + red_sum[whb0 + 64 + mt * 16 + g + 8]);
        #pragma unroll
        for (int nt = 0; nt < 4; nt++) {
            #pragma unroll
            for (int q = 0; q < 4; q++) {
                int row = w * 64 + mt * 16 + g + (q >> 1) * 8;
                int m = half * 32 + nt * 8 + 2 * tg + (q & 1);
                float p = d[mt][nt][q] * ((q >> 1) ? i1 : i0);
                QA[a_off(row, h * 64 + m)] = __uint_as_float(f2tf32(p));
                d[mt][nt][q] = 0.f;
            }
        }
    }
    __syncthreads();

    {
        const uint4* Pa = (const uint4*)QA;
        const uint2* Vb = (const uint2*)AX;
        #pragma unroll
        for (int kbl = 0; kbl < 8; kbl++) {
            uint32_t a[4][4], b[4][2];
            #pragma unroll
            for (int mt = 0; mt < 4; mt++)
                *(uint4*)a[mt] = Pa[((h * 8 + kbl) * 8 + w * 4 + mt) * 32 + tg * 8 + g];
            #pragma unroll
            for (int nt = 0; nt < 4; nt++)
                *(uint2*)b[nt] = Vb[(((w * 8 + kbl) * 16 + h * 8 + half * 4 + nt) * 4 + tg) * 8 + g];
            #pragma unroll
            for (int mt = 0; mt < 4; mt++)
                #pragma unroll
                for (int nt = 0; nt < 4; nt++)
                    mma8(d[mt][nt], a[mt], b[nt]);
        }
        #pragma unroll
        for (int mt = 0; mt < 4; mt++) {
            #pragma unroll
            for (int nt = 0; nt < 4; nt++) {
                #pragma unroll
                for (int q = 0; q < 4; q++) {
                    int row = w * 64 + mt * 16 + g + (q >> 1) * 8;
                    int col = h * 64 + half * 32 + nt * 8 + 2 * tg + (q & 1);
                    KB[a_off(row, col)] = __uint_as_float(f2tf32(d[mt][nt][q]));
                    d[mt][nt][q] = 0.f;
                }
            }
        }
    }
    __syncthreads();

    const float* psrc = g_wpf + (size_t)(br * 4) * 4096;
    {
        const float4* s4 = (const float4*)psrc;
        #pragma unroll
        for (int i = 0; i < 4; i++) cp16(bb_addr + (i * 256 + tid) * 16, s4 + i * 256 + tid);
        CP_COMMIT();
    }
    for (int kc = 0; kc < 4; kc++) {
        if (kc < 3) {
            const float4* s4 = (const float4*)(psrc + (kc + 1) * 4096);
            uint32_t db = bb_addr + ((kc + 1) & 1) * 16384;
            #pragma unroll
            for (int i = 0; i < 4; i++) cp16(db + (i * 256 + tid) * 16, s4 + i * 256 + tid);
            CP_COMMIT();
            CP_WAIT1();
        } else CP_WAIT0();
        __syncthreads();
        const uint2* Bu = (const uint2*)(BB + (kc & 1) * 4096);
        const uint4* Au = (const uint4*)KB;
        #pragma unroll
        for (int kbl = 0; kbl < 4; kbl++) {
            uint32_t a[4][4], b[4][2];
            #pragma unroll
            for (int mt = 0; mt < 4; mt++)
                *(uint4*)a[mt] = Au[((kc * 4 + kbl) * 8 + mwarp * 4 + mt) * 32 + tg * 8 + g];
            #pragma unroll
            for (int nt = 0; nt < 4; nt++)
                *(uint2*)b[nt] = Bu[((kbl * 16 + nwarp * 4 + nt) * 4 + tg) * 8 + g];
            #pragma unroll
            for (int mt = 0; mt < 4; mt++)
                #pragma unroll
                for (int nt = 0; nt < 4; nt++)
                    mma8(d[mt][nt], a[mt], b[nt]);
        }
        __syncthreads();
    }

    float* Sx = QA;
    #pragma unroll
    for (int mt = 0; mt < 4; mt++) {
        #pragma unroll
        for (int nt = 0; nt < 4; nt++) {
            #pragma unroll
            for (int q = 0; q < 4; q++) {
                int row = mwarp * 64 + mt * 16 + g + (q >> 1) * 8;
                int col = nwarp * 32 + nt * 8 + 2 * tg + (q & 1);
                Sx[row * 132 + col] = d[mt][nt][q] + bp[col];
            }
        }
    }
    __syncthreads();
    {
        int c = tid & 127;
        #pragma unroll 2
        for (int it = 0; it < 64; it++) {
            int idx = it * 256 + tid;
            int n = idx >> 7;
            int t = tok_t(pair, n, lg, nWb, Wh, Ww);
            g_x1[t * 256 + co + c] = Sx[n * 132 + c] + g_xn[t * 256 + co + c];
        }
    }
}

// ===========================================================================
// MLP1: LN2 + GEMM1 + GELU -> g_hf (frag order). 3-slot B ring, 1 bar/chunk.
// Smem floats: A 32768 @0 | B 3x8192 @32768 (LN overlay S @32768, stats @49280)
// ===========================================================================
#define M1_SMEM 229376
__global__ void __launch_bounds__(256, 1) mlp1_kernel(
    const float* __restrict__ x, const float* __restrict__ g2, const float* __restrict__ b2,
    const float* __restrict__ b1)
{
    extern __shared__ float sm[];
    float* A    = sm;
    float* S    = sm + 32768;
    float* tmpS = sm + 49280;
    float* tmpQ = sm + 49536;
    float* tsum = sm + 49792;
    float* tsq  = sm + 49920;
    float* mu   = sm + 50048;
    float* rs   = sm + 50176;

    int tid = threadIdx.x, wid = tid >> 5, lane = tid & 31;
    int t0 = blockIdx.x * 128;
    int tblk = blockIdx.x;
    uint32_t bbase = smem_u32(sm) + 131072;

    if (tid < 128) { tsum[tid] = 0.f; tsq[tid] = 0.f; }
    for (int h = 0; h < 2; h++) {
        __syncthreads();
        #pragma unroll 4
        for (int it = 0; it < 64; it++) {
            int idx = it * 256 + tid;
            int n = idx & 127, cl = idx >> 7;
            S[cl * 129 + n] = x[(size_t)(h * 128 + cl) * HW + t0 + n];
        }
        __syncthreads();
        #pragma unroll 4
        for (int it = 0; it < 64; it++) {
            int idx = it * 256 + tid;
            int cl = idx & 127, n = idx >> 7;
            S[cl * 129 + n] += g_x1[(size_t)(t0 + n) * 256 + h * 128 + cl];
        }
        __syncthreads();
        {
            int n = tid & 127, part = tid >> 7;
            float s1 = 0.f, s2 = 0.f;
            for (int cl = part * 64; cl < part * 64 + 64; cl++) {
                float v = S[cl * 129 + n];
                s1 += v; s2 += v * v;
                A[a_slot(n, h * 128 + cl)] = v;
            }
            tmpS[part * 128 + n] = s1; tmpQ[part * 128 + n] = s2;
        }
        __syncthreads();
        if (tid < 128) {
            tsum[tid] += tmpS[tid] + tmpS[128 + tid];
            tsq[tid]  += tmpQ[tid] + tmpQ[128 + tid];
        }
    }
    __syncthreads();
    if (tid < 128) {
        float m = tsum[tid] * (1.f / 256.f);
        mu[tid] = m;
        rs[tid] = rsqrtf(tsq[tid] * (1.f / 256.f) - m * m + 1e-5f);
    }
    __syncthreads();
    {
        int tok = tid & 127, half = tid >> 7;
        float m = mu[tok], r = rs[tok];
        for (int c = half * 128; c < half * 128 + 128; c++) {
            int idx = a_slot(tok, c);
            A[idx] = __uint_as_float(f2tf32((A[idx] - m) * r * g2[c] + b2[c]));
        }
    }
    __syncthreads();

    int mwarp = wid >> 2, nwarp = wid & 3;
    int g = lane >> 2, tg = lane & 3;

    for (int jb = 0; jb < 4; jb++) {
        float d[4][8][4];
        #pragma unroll
        for (int mt = 0; mt < 4; mt++)
            #pragma unroll
            for (int nt = 0; nt < 8; nt++)
                #pragma unroll
                for (int q = 0; q < 4; q++) d[mt][nt][q] = 0.f;

        {   // prologue: chunk 0 -> slot 0
            const float4* src = (const float4*)(g_w1f + (size_t)(jb * 8) * 8192);
            #pragma unroll
            for (int i = 0; i < 8; i++) cp16(bbase + (i * 256 + tid) * 16, src + i * 256 + tid);
            CP_COMMIT();
        }
        for (int kc = 0; kc < 8; kc++) {
            if (kc + 1 < 8) {
                const float4* src = (const float4*)(g_w1f + (size_t)(jb * 8 + kc + 1) * 8192);
                uint32_t db = bbase + (uint32_t)(((kc + 1) % 3) * 32768);
                #pragma unroll
                for (int i = 0; i < 8; i++) cp16(db + (i * 256 + tid) * 16, src + i * 256 + tid);
            }
            CP_COMMIT();
            CP_WAIT1();
            __syncthreads();
            const float* Bc = sm + 32768 + (kc % 3) * 8192;
            #pragma unroll
            for (int kbl = 0; kbl < 4; kbl++) {
                uint32_t a[4][4], b[8][2];
                const uint4* Au = (const uint4*)A;
                #pragma unroll
                for (int mt = 0; mt < 4; mt++)
                    *(uint4*)a[mt] = Au[((kc * 4 + kbl) * 8 + mwarp * 4 + mt) * 32 + tg * 8 + g];
                const uint2* Bu = (const uint2*)Bc;
                #pragma unroll
                for (int nt = 0; nt < 8; nt++)
                    *(uint2*)b[nt] = Bu[(kbl * 32 + nwarp * 8 + nt) * 32 + tg * 8 + g];
                #pragma unroll
                for (int mt = 0; mt < 4; mt++)
                    #pragma unroll
                    for (int nt = 0; nt < 8; nt++)
                        mma8(d[mt][nt], a[mt], b[nt]);
            }
        }
        __syncthreads();   // all mma done before next jb prologue reuses slot 0
        // epilogue: bias + GELU + tf32 -> g_hf frag order
        #pragma unroll
        for (int mt = 0; mt < 4; mt++) {
            #pragma unroll
            for (int nt = 0; nt < 8; nt++) {
                int row0 = mwarp * 64 + mt * 16 + g;
                int col0 = jb * 256 + nwarp * 64 + nt * 8 + 2 * tg;
                float b0v = b1[col0], b1v = b1[col0 + 1];
                float v0 = gelu(d[mt][nt][0] + b0v);
                float v1 = gelu(d[mt][nt][1] + b1v);
                float v2 = gelu(d[mt][nt][2] + b0v);
                float v3 = gelu(d[mt][nt][3] + b1v);
                float* dst0 = g_hf + (size_t)(tblk * 32 + (col0 >> 5)) * 4096;
                int kk0 = col0 & 31;
                dst0[a_slot(row0, kk0)]          = __uint_as_float(f2tf32(v0));
                dst0[a_slot(row0, kk0 + 1)]      = __uint_as_float(f2tf32(v1));
                dst0[a_slot(row0 + 8, kk0)]      = __uint_as_float(f2tf32(v2));
                dst0[a_slot(row0 + 8, kk0 + 1)]  = __uint_as_float(f2tf32(v3));
            }
        }
    }
}

// ===========================================================================
// MLP2: GEMM2 + residual -> out (NCHW). 4-slot A/B rings, 1 bar/chunk.
// Smem floats: A 4x4096 @0 | B 4x8192 @16384 | epilogue overlay S[256][133] @0
// ===========================================================================
#define M2_SMEM 196608
__global__ void __launch_bounds__(256, 1) mlp2_kernel(
    const float* __restrict__ x, const float* __restrict__ b2o, float* __restrict__ out)
{
    extern __shared__ float sm[];
    float* S = sm;

    int tid = threadIdx.x, wid = tid >> 5, lane = tid & 31;
    int t0 = blockIdx.x * 128;
    int tblk = blockIdx.x;
    int mwarp = wid >> 2, nwarp = wid & 3;
    int g = lane >> 2, tg = lane & 3;
    uint32_t abase = smem_u32(sm);
    uint32_t bbase = abase + 65536;

    float d[4][8][4];
    #pragma unroll
    for (int mt = 0; mt < 4; mt++)
        #pragma unroll
        for (int nt = 0; nt < 8; nt++)
            #pragma unroll
            for (int q = 0; q < 4; q++) d[mt][nt][q] = 0.f;

    // prologue: chunks 0,1 into slots 0,1
    #pragma unroll
    for (int p = 0; p < 2; p++) {
        const float4* asrc = (const float4*)(g_hf + (size_t)(tblk * 32 + p) * 4096);
        uint32_t da = abase + (uint32_t)(p * 16384);
        #pragma unroll
        for (int i = 0; i < 4; i++) cp16(da + (i * 256 + tid) * 16, asrc + i * 256 + tid);
        const float4* bsrc = (const float4*)(g_w2f + (size_t)p * 8192);
        uint32_t db = bbase + (uint32_t)(p * 32768);
        #pragma unroll
        for (int i = 0; i < 8; i++) cp16(db + (i * 256 + tid) * 16, bsrc + i * 256 + tid);
        CP_COMMIT();
    }
    for (int kc = 0; kc < 32; kc++) {
        if (kc + 2 < 32) {
            int nx = kc + 2, slot = nx & 3;
            const float4* asrc = (const float4*)(g_hf + (size_t)(tblk * 32 + nx) * 4096);
            uint32_t da = abase + (uint32_t)(slot * 16384);
            #pragma unroll
            for (int i = 0; i < 4; i++) cp16(da + (i * 256 + tid) * 16, asrc + i * 256 + tid);
            const float4* bsrc = (const float4*)(g_w2f + (size_t)nx * 8192);
            uint32_t db = bbase + (uint32_t)(slot * 32768);
            #pragma unroll
            for (int i = 0; i < 8; i++) cp16(db + (i * 256 + tid) * 16, bsrc + i * 256 + tid);
        }
        CP_COMMIT();
        CP_WAIT2();
        __syncthreads();
        const float* Ac = sm + (kc & 3) * 4096;
        const float* Bc = sm + 16384 + (kc & 3) * 8192;
        #pragma unroll
        for (int kbl = 0; kbl < 4; kbl++) {
            uint32_t a[4][4], b[8][2];
            const uint4* Au = (const uint4*)Ac;
            #pragma unroll
            for (int mt = 0; mt < 4; mt++)
                *(uint4*)a[mt] = Au[(kbl * 8 + mwarp * 4 + mt) * 32 + tg * 8 + g];
            const uint2* Bu = (const uint2*)Bc;
            #pragma unroll
            for (int nt = 0; nt < 8; nt++)
                *(uint2*)b[nt] = Bu[(kbl * 32 + nwarp * 8 + nt) * 32 + tg * 8 + g];
            #pragma unroll
            for (int mt = 0; mt < 4; mt++)
                #pragma unroll
                for (int nt = 0; nt < 8; nt++)
                    mma8(d[mt][nt], a[mt], b[nt]);
        }
    }
    __syncthreads();

    #pragma unroll 4
    for (int i = 0; i < 128; i++)
        S[tid * 133 + i] = g_x1[(size_t)(t0 + i) * 256 + tid];
    __syncthreads();

    #pragma unroll
    for (int mt = 0; mt < 4; mt++) {
        #pragma unroll
        for (int nt = 0; nt < 8; nt++) {
            int row0 = mwarp * 64 + mt * 16 + g;
            int col0 = nwarp * 64 + nt * 8 + 2 * tg;
            #pragma unroll
            for (int q = 0; q < 4; q++) {
                int col = col0 + (q & 1);
                int row = row0 + (q >> 1) * 8;
                float v = d[mt][nt][q] + b2o[col]
                        + x[(size_t)col * HW + t0 + row] + S[col * 133 + row];
                out[(size_t)col * HW + t0 + row] = v;
            }
        }
    }
}

// ---------------------------------------------------------------------------
extern "C" void kernel_launch(void* const* d_in, const int* in_sizes, int n_in,
                              void* d_out, int out_size) {
    const float* x        = (const float*)d_in[0];
    const float* norm1_g  = (const float*)d_in[1];
    const float* norm1_b  = (const float*)d_in[2];
    const float* qkv_r    = (const float*)d_in[3];
    const float* proj_r_w = (const float*)d_in[4];
    const float* proj_r_b = (const float*)d_in[5];
    const float* table_r  = (const float*)d_in[6];
    const float* qkv_a    = (const float*)d_in[7];
    const float* proj_a_w = (const float*)d_in[8];
    const float* proj_a_b = (const float*)d_in[9];
    const float* table_a  = (const float*)d_in[10];
    const float* norm2_g  = (const float*)d_in[11];
    const float* norm2_b  = (const float*)d_in[12];
    const float* mlp_w1   = (const float*)d_in[13];
    const float* mlp_b1   = (const float*)d_in[14];
    const float* mlp_w2   = (const float*)d_in[15];
    const float* mlp_b2   = (const float*)d_in[16];
    float* out = (float*)d_out;

    cudaFuncSetAttribute(attn_kernel, cudaFuncAttributeMaxDynamicSharedMemorySize, ATTN_SMEM);
    cudaFuncSetAttribute(mlp1_kernel, cudaFuncAttributeMaxDynamicSharedMemorySize, M1_SMEM);
    cudaFuncSetAttribute(mlp2_kernel, cudaFuncAttributeMaxDynamicSharedMemorySize, M2_SMEM);

    ln1_kernel<<<2048, 256>>>(x, norm1_g, norm1_b);
    bias_kernel<<<1, 256>>>(table_r, table_a);
    wfmt_kernel<<<2048, 256>>>(mlp_w1, mlp_w2);
    wfmt2_kernel<<<512, 256>>>(qkv_r, proj_r_w, qkv_a, proj_a_w);
    attn_kernel<<<dim3(512, 2), 256, ATTN_SMEM>>>(proj_r_b, proj_a_b);
    mlp1_kernel<<<512, 256, M1_SMEM>>>(x, norm2_g, norm2_b, mlp_b1);
    mlp2_kernel<<<512, 256, M2_SMEM>>>(x, mlp_b2, out);
}

// round 11
// speedup vs baseline: 5.1114x; 1.2754x over previous
#include <cuda_runtime.h>
#include <cuda_fp16.h>
#include <cstdint>

#define HW 65536

__device__ float g_xn[HW * 256];
__device__ float g_x1[HW * 256];
__device__ float g_bias[2 * 2 * 64 * 64];
__device__ uint32_t g_hh[512 * 32 * 2048];  // H fp16 frags [tblk][kc][2048 u32]
__device__ uint2 g_w1h[65536];              // W1 fp16 frag chunks [jb*8+kc][2048]
__device__ uint2 g_w2h[65536];              // W2 fp16 frag chunks [kc][2048]
__device__ float g_wqkvf[2 * 3 * 4 * 4096]; // Wqkv tf32 frag order (attn)
__device__ float g_wpf[2 * 4 * 4096];       // Wproj tf32 frag order (attn)

__device__ __forceinline__ uint32_t f2tf32(float v) {
    uint32_t u; asm("cvt.rna.tf32.f32 %0, %1;" : "=r"(u) : "f"(v)); return u;
}
__device__ __forceinline__ uint32_t smem_u32(const void* p) {
    uint32_t a;
    asm("{ .reg .u64 t; cvta.to.shared.u64 t, %1; cvt.u32.u64 %0, t; }" : "=r"(a) : "l"(p));
    return a;
}
__device__ __forceinline__ void cp16(uint32_t dst, const void* src) {
    asm volatile("cp.async.cg.shared.global [%0], [%1], 16;" :: "r"(dst), "l"(src));
}
#define CP_COMMIT() asm volatile("cp.async.commit_group;" ::: "memory")
#define CP_WAIT2()  asm volatile("cp.async.wait_group 2;" ::: "memory")
#define CP_WAIT1()  asm volatile("cp.async.wait_group 1;" ::: "memory")
#define CP_WAIT0()  asm volatile("cp.async.wait_group 0;" ::: "memory")

__device__ __forceinline__ void mma8(float* d, const uint32_t* a, const uint32_t* b) {
    asm volatile("mma.sync.aligned.m16n8k8.row.col.f32.tf32.tf32.f32 "
        "{%0,%1,%2,%3}, {%4,%5,%6,%7}, {%8,%9}, {%0,%1,%2,%3};"
        : "+f"(d[0]), "+f"(d[1]), "+f"(d[2]), "+f"(d[3])
        : "r"(a[0]), "r"(a[1]), "r"(a[2]), "r"(a[3]), "r"(b[0]), "r"(b[1]));
}
__device__ __forceinline__ void mma16(float* d, const uint32_t* a, const uint32_t* b) {
    asm volatile("mma.sync.aligned.m16n8k16.row.col.f32.f16.f16.f32 "
        "{%0,%1,%2,%3}, {%4,%5,%6,%7}, {%8,%9}, {%0,%1,%2,%3};"
        : "+f"(d[0]), "+f"(d[1]), "+f"(d[2]), "+f"(d[3])
        : "r"(a[0]), "r"(a[1]), "r"(a[2]), "r"(a[3]), "r"(b[0]), "r"(b[1]));
}
__device__ __forceinline__ uint32_t packh2(float lo, float hi) {
    __half2 h = __floats2half2_rn(lo, hi);
    return *(uint32_t*)&h;
}
__device__ __forceinline__ float gelu(float v) {
    return 0.5f * v * (1.f + erff(v * 0.70710678118f));
}
// tf32 fragment offsets (attn only)
__device__ __forceinline__ int a_off(int tok, int c) {
    return ((c >> 3) * 8 + (tok >> 4)) * 128 + ((c & 3) * 8 + (tok & 7)) * 4
         + ((tok >> 3) & 1) + 2 * ((c >> 2) & 1);
}
__device__ __forceinline__ int b16_off(int kk, int n) {
    return (((kk >> 3) * 16 + (n >> 3)) * 4 + (kk & 3)) * 16 + (n & 7) * 2 + ((kk >> 2) & 1);
}
// fp16 A-fragment half-index: element (tok, k) of a [*,16kb] tile set
__device__ __forceinline__ int a16h(int tok, int c) {
    return ((((c >> 4) * 8 + (tok >> 4)) * 32 + ((c & 7) >> 1) * 8 + (tok & 7)) * 4
            + ((tok >> 3) & 1) + 2 * ((c >> 3) & 1)) * 2 + (c & 1);
}

// ---------------- LN1 ----------------
__global__ void __launch_bounds__(256) ln1_kernel(const float* __restrict__ x,
                                                  const float* __restrict__ g,
                                                  const float* __restrict__ b) {
    __shared__ float s[256][33];
    __shared__ float mu[32], rs[32];
    int t0 = blockIdx.x * 32;
    int tid = threadIdx.x, lane = tid & 31, wid = tid >> 5;
    #pragma unroll
    for (int c = wid; c < 256; c += 8) s[c][lane] = x[c * HW + t0 + lane];
    __syncthreads();
    for (int it = 0; it < 4; it++) {
        int tok = wid * 4 + it;
        float sum = 0.f, sq = 0.f;
        #pragma unroll
        for (int j = 0; j < 8; j++) { float v = s[lane + 32 * j][tok]; sum += v; sq += v * v; }
        #pragma unroll
        for (int o = 16; o; o >>= 1) { sum += __shfl_down_sync(~0u, sum, o); sq += __shfl_down_sync(~0u, sq, o); }
        if (lane == 0) {
            float m = sum * (1.f / 256.f);
            mu[tok] = m; rs[tok] = rsqrtf(sq * (1.f / 256.f) - m * m + 1e-5f);
        }
    }
    __syncthreads();
    float gc = g[tid], bc = b[tid];
    for (int k = 0; k < 32; k++)
        g_xn[(t0 + k) * 256 + tid] = (s[tid][k] - mu[k]) * rs[k] * gc + bc;
}

// ---------------- bias tables ----------------
__global__ void bias_kernel(const float* __restrict__ tr, const float* __restrict__ ta) {
    for (int idx = threadIdx.x; idx < 16384; idx += blockDim.x) {
        int br = idx >> 13, rem = idx & 8191;
        int h = rem >> 12, n = (rem >> 6) & 63, m = rem & 63;
        int Wh = br ? 4 : 16, Ww = br ? 16 : 4, lg = br ? 4 : 2;
        int ridx = ((n >> lg) - (m >> lg) + Wh - 1) * (2 * Ww - 1) + ((n & (Ww - 1)) - (m & (Ww - 1)) + Ww - 1);
        g_bias[idx] = (br ? ta : tr)[ridx * 2 + h];
    }
}

// ---------------- MLP weight pre-format (fp16 fragment order) ----------------
__global__ void __launch_bounds__(256) wfmt_kernel(const float* __restrict__ W1,
                                                   const float* __restrict__ W2) {
    int idx = blockIdx.x * 256 + threadIdx.x;      // 0..131071
    const float* W; int ld, col, kbase; uint2* dst; int out;
    if (idx < 65536) {
        int g = idx & 7, tg = (idx >> 3) & 3, nt = (idx >> 5) & 31;
        int kb2 = (idx >> 10) & 1, kc = (idx >> 11) & 7, jb = idx >> 14;
        W = W1; ld = 1024;
        col = jb * 256 + nt * 8 + g;
        kbase = kc * 32 + kb2 * 16 + 2 * tg;
        out = (jb * 8 + kc) * 2048 + ((kb2 * 32 + nt) * 4 + tg) * 8 + g;
        dst = g_w1h;
    } else {
        int u = idx - 65536;
        int g = u & 7, tg = (u >> 3) & 3, nt = (u >> 5) & 31;
        int kb2 = (u >> 10) & 1, kc = u >> 11;
        W = W2; ld = 256;
        col = nt * 8 + g;
        kbase = kc * 32 + kb2 * 16 + 2 * tg;
        out = kc * 2048 + ((kb2 * 32 + nt) * 4 + tg) * 8 + g;
        dst = g_w2h;
    }
    float w0 = W[(size_t)kbase * ld + col];
    float w1 = W[(size_t)(kbase + 1) * ld + col];
    float w2 = W[(size_t)(kbase + 8) * ld + col];
    float w3 = W[(size_t)(kbase + 9) * ld + col];
    dst[out] = make_uint2(packh2(w0, w1), packh2(w2, w3));
}

// ---------------- attention weight pre-format (tf32, unchanged) ----------------
__global__ void __launch_bounds__(256) wfmt2_kernel(
    const float* __restrict__ Wq_r, const float* __restrict__ Wp_r,
    const float* __restrict__ Wq_a, const float* __restrict__ Wp_a)
{
    int idx = blockIdx.x * 256 + threadIdx.x;      // 0..131071
    int r = idx & 4095;
    int hf = r & 1, gg = (r >> 1) & 7, tig = (r >> 4) & 3, nt = (r >> 6) & 15, kb = r >> 10;
    int kk = kb * 8 + hf * 4 + tig, n = nt * 8 + gg;
    if (idx < 98304) {
        int br = idx / 49152;
        int r0 = idx % 49152;
        int nb = r0 >> 14, kc = (r0 >> 12) & 3;
        const float* W = br ? Wq_a : Wq_r;
        g_wqkvf[idx] = __uint_as_float(f2tf32(W[(size_t)(kc * 32 + kk) * 384 + nb * 128 + n]));
    } else {
        int j = idx - 98304;
        int br = j >> 14, kc = (j >> 12) & 3;
        const float* W = br ? Wp_a : Wp_r;
        g_wpf[j] = __uint_as_float(f2tf32(W[(size_t)(kc * 32 + kk) * 128 + n]));
    }
}

// ===========================================================================
// Tensor-core window attention (tf32, unchanged from R9/R10).
// ===========================================================================
#define ATTN_SMEM 229376
__device__ __forceinline__ int tok_t(int pair, int n, int lg, int nWb, int Wh, int Ww) {
    int w = n >> 6, nl = n & 63;
    int wi = pair * 2 + w;
    int hb = wi / nWb, wb = wi - hb * nWb;
    return ((hb * Wh + (nl >> lg)) << 8) + wb * Ww + (nl & (Ww - 1));
}

__global__ void __launch_bounds__(256, 1) attn_kernel(
    const float* __restrict__ bp_r, const float* __restrict__ bp_a)
{
    extern __shared__ float sm[];
    float* AX = sm;
    float* QA = sm + 16384;
    float* KB = sm + 32768;
    float* BB = sm + 49152;
    float* red_max = KB;
    float* red_sum = KB + 512;

    int br = blockIdx.y;
    int co = br ? 128 : 0, lg = br ? 4 : 2;
    int Ww = 1 << lg, nWb = br ? 16 : 64, Wh = br ? 4 : 16;
    const float* bp = br ? bp_a : bp_r;
    int pair = blockIdx.x;
    int tid = threadIdx.x, wid = tid >> 5, lane = tid & 31;
    int g = lane >> 2, tg = lane & 3;
    uint32_t bb_addr = smem_u32(sm) + 49152 * 4;

    {
        int k = tid & 127;
        #pragma unroll 2
        for (int it = 0; it < 64; it++) {
            int idx = it * 256 + tid;
            int n = idx >> 7;
            int t = tok_t(pair, n, lg, nWb, Wh, Ww);
            QA[k * 130 + n] = g_xn[t * 256 + co + k];
        }
    }
    __syncthreads();
    {
        #pragma unroll
        for (int i = 0; i < 16; i++) {
            int p = wid * 16 + i;
            int kb = p >> 3, mt = p & 7;
            int k0 = kb * 8 + tg, row = mt * 16 + g;
            uint4 u;
            u.x = f2tf32(QA[k0 * 130 + row]);
            u.y = f2tf32(QA[k0 * 130 + row + 8]);
            u.z = f2tf32(QA[(k0 + 4) * 130 + row]);
            u.w = f2tf32(QA[(k0 + 4) * 130 + row + 8]);
            ((uint4*)AX)[(kb * 8 + mt) * 32 + tg * 8 + g] = u;
        }
    }
    __syncthreads();

    int mwarp = wid >> 2, nwarp = wid & 3;
    float d[4][4][4];
    #pragma unroll
    for (int mt = 0; mt < 4; mt++)
        #pragma unroll
        for (int nt = 0; nt < 4; nt++)
            #pragma unroll
            for (int q = 0; q < 4; q++) d[mt][nt][q] = 0.f;

    const float* wsrc = g_wqkvf + (size_t)(br * 12) * 4096;
    {
        const float4* s4 = (const float4*)wsrc;
        #pragma unroll
        for (int i = 0; i < 4; i++) cp16(bb_addr + (i * 256 + tid) * 16, s4 + i * 256 + tid);
        CP_COMMIT();
    }
    for (int s = 0; s < 12; s++) {
        if (s < 11) {
            const float4* s4 = (const float4*)(wsrc + (s + 1) * 4096);
            uint32_t db = bb_addr + ((s + 1) & 1) * 16384;
            #pragma unroll
            for (int i = 0; i < 4; i++) cp16(db + (i * 256 + tid) * 16, s4 + i * 256 + tid);
            CP_COMMIT();
            CP_WAIT1();
        } else CP_WAIT0();
        __syncthreads();
        int kc = s & 3;
        const uint2* Bu = (const uint2*)(BB + (s & 1) * 4096);
        const uint4* Au = (const uint4*)AX;
        #pragma unroll
        for (int kbl = 0; kbl < 4; kbl++) {
            uint32_t a[4][4], b[4][2];
            #pragma unroll
            for (int mt = 0; mt < 4; mt++)
                *(uint4*)a[mt] = Au[((kc * 4 + kbl) * 8 + mwarp * 4 + mt) * 32 + tg * 8 + g];
            #pragma unroll
            for (int nt = 0; nt < 4; nt++)
                *(uint2*)b[nt] = Bu[((kbl * 16 + nwarp * 4 + nt) * 4 + tg) * 8 + g];
            #pragma unroll
            for (int mt = 0; mt < 4; mt++)
                #pragma unroll
                for (int nt = 0; nt < 4; nt++)
                    mma8(d[mt][nt], a[mt], b[nt]);
        }
        __syncthreads();
        if (kc == 3) {
            int nb = s >> 2;
            #pragma unroll
            for (int mt = 0; mt < 4; mt++) {
                #pragma unroll
                for (int nt = 0; nt < 4; nt++) {
                    #pragma unroll
                    for (int q = 0; q < 4; q++) {
                        int row = mwarp * 64 + mt * 16 + g + (q >> 1) * 8;
                        int col = nwarp * 32 + nt * 8 + 2 * tg + (q & 1);
                        uint32_t v = f2tf32(d[mt][nt][q]);
                        if (nb == 0)      QA[a_off(row, col)] = __uint_as_float(v);
                        else if (nb == 1) KB[b16_off(col, row)] = __uint_as_float(v);
                        else              AX[b16_off(row, col)] = __uint_as_float(v);
                        d[mt][nt][q] = 0.f;
                    }
                }
            }
            __syncthreads();
        }
    }

    int w = wid >> 2, h = (wid >> 1) & 1, half = wid & 1;
    {
        const uint4* Qa = (const uint4*)QA;
        const uint2* Kb = (const uint2*)KB;
        #pragma unroll
        for (int kbl = 0; kbl < 8; kbl++) {
            uint32_t a[4][4], b[4][2];
            #pragma unroll
            for (int mt = 0; mt < 4; mt++)
                *(uint4*)a[mt] = Qa[((h * 8 + kbl) * 8 + w * 4 + mt) * 32 + tg * 8 + g];
            #pragma unroll
            for (int nt = 0; nt < 4; nt++)
                *(uint2*)b[nt] = Kb[(((h * 8 + kbl) * 16 + w * 8 + half * 4 + nt) * 4 + tg) * 8 + g];
            #pragma unroll
            for (int mt = 0; mt < 4; mt++)
                #pragma unroll
                for (int nt = 0; nt < 4; nt++)
                    mma8(d[mt][nt], a[mt], b[nt]);
        }
    }
    __syncthreads();

    const float* bias = g_bias + (br * 2 + h) * 4096;
    #pragma unroll
    for (int mt = 0; mt < 4; mt++) {
        #pragma unroll
        for (int nt = 0; nt < 4; nt++) {
            int rr = mt * 16 + g, cc = half * 32 + nt * 8 + 2 * tg;
            float2 b0 = *(const float2*)(bias + rr * 64 + cc);
            float2 b1 = *(const float2*)(bias + (rr + 8) * 64 + cc);
            d[mt][nt][0] = d[mt][nt][0] * 0.125f + b0.x;
            d[mt][nt][1] = d[mt][nt][1] * 0.125f + b0.y;
            d[mt][nt][2] = d[mt][nt][2] * 0.125f + b1.x;
            d[mt][nt][3] = d[mt][nt][3] * 0.125f + b1.y;
        }
    }
    int whb = ((w * 2 + h) * 2 + half) * 64;
    #pragma unroll
    for (int mt = 0; mt < 4; mt++) {
        float m0 = -1e30f, m1 = -1e30f;
        #pragma unroll
        for (int nt = 0; nt < 4; nt++) {
            m0 = fmaxf(m0, fmaxf(d[mt][nt][0], d[mt][nt][1]));
            m1 = fmaxf(m1, fmaxf(d[mt][nt][2], d[mt][nt][3]));
        }
        m0 = fmaxf(m0, __shfl_xor_sync(~0u, m0, 1)); m0 = fmaxf(m0, __shfl_xor_sync(~0u, m0, 2));
        m1 = fmaxf(m1, __shfl_xor_sync(~0u, m1, 1)); m1 = fmaxf(m1, __shfl_xor_sync(~0u, m1, 2));
        red_max[whb + mt * 16 + g] = m0;
        red_max[whb + mt * 16 + g + 8] = m1;
    }
    __syncthreads();
    int whb0 = ((w * 2 + h) * 2) * 64;
    #pragma unroll
    for (int mt = 0; mt < 4; mt++) {
        float M0 = fmaxf(red_max[whb0 + mt * 16 + g], red_max[whb0 + 64 + mt * 16 + g]);
        float M1 = fmaxf(red_max[whb0 + mt * 16 + g + 8], red_max[whb0 + 64 + mt * 16 + g + 8]);
        float s0 = 0.f, s1 = 0.f;
        #pragma unroll
        for (int nt = 0; nt < 4; nt++) {
            d[mt][nt][0] = expf(d[mt][nt][0] - M0); s0 += d[mt][nt][0];
            d[mt][nt][1] = expf(d[mt][nt][1] - M0); s0 += d[mt][nt][1];
            d[mt][nt][2] = expf(d[mt][nt][2] - M1); s1 += d[mt][nt][2];
            d[mt][nt][3] = expf(d[mt][nt][3] - M1); s1 += d[mt][nt][3];
        }
        s0 += __shfl_xor_sync(~0u, s0, 1); s0 += __shfl_xor_sync(~0u, s0, 2);
        s1 += __shfl_xor_sync(~0u, s1, 1); s1 += __shfl_xor_sync(~0u, s1, 2);
        red_sum[whb + mt * 16 + g] = s0;
        red_sum[whb + mt * 16 + g + 8] = s1;
    }
    __syncthreads();
    #pragma unroll
    for (int mt = 0; mt < 4; mt++) {
        float i0 = 1.f / (red_sum[whb0 + mt * 16 + g] + red_sum[whb0 + 64 + mt * 16 + g]);
        float i1 = 1.f / (red_sum[whb0 + mt * 16 + g + 8] + red_sum[whb0 + 64 + mt * 16 + g + 8]);
        #pragma unroll
        for (int nt = 0; nt < 4; nt++) {
            #pragma unroll
            for (int q = 0; q < 4; q++) {
                int row = w * 64 + mt * 16 + g + (q >> 1) * 8;
                int m = half * 32 + nt * 8 + 2 * tg + (q & 1);
                float p = d[mt][nt][q] * ((q >> 1) ? i1 : i0);
                QA[a_off(row, h * 64 + m)] = __uint_as_float(f2tf32(p));
                d[mt][nt][q] = 0.f;
            }
        }
    }
    __syncthreads();

    {
        const uint4* Pa = (const uint4*)QA;
        const uint2* Vb = (const uint2*)AX;
        #pragma unroll
        for (int kbl = 0; kbl < 8; kbl++) {
            uint32_t a[4][4], b[4][2];
            #pragma unroll
            for (int mt = 0; mt < 4; mt++)
                *(uint4*)a[mt] = Pa[((h * 8 + kbl) * 8 + w * 4 + mt) * 32 + tg * 8 + g];
            #pragma unroll
            for (int nt = 0; nt < 4; nt++)
                *(uint2*)b[nt] = Vb[(((w * 8 + kbl) * 16 + h * 8 + half * 4 + nt) * 4 + tg) * 8 + g];
            #pragma unroll
            for (int mt = 0; mt < 4; mt++)
                #pragma unroll
                for (int nt = 0; nt < 4; nt++)
                    mma8(d[mt][nt], a[mt], b[nt]);
        }
        #pragma unroll
        for (int mt = 0; mt < 4; mt++) {
            #pragma unroll
            for (int nt = 0; nt < 4; nt++) {
                #pragma unroll
                for (int q = 0; q < 4; q++) {
                    int row = w * 64 + mt * 16 + g + (q >> 1) * 8;
                    int col = h * 64 + half * 32 + nt * 8 + 2 * tg + (q & 1);
                    KB[a_off(row, col)] = __uint_as_float(f2tf32(d[mt][nt][q]));
                    d[mt][nt][q] = 0.f;
                }
            }
        }
    }
    __syncthreads();

    const float* psrc = g_wpf + (size_t)(br * 4) * 4096;
    {
        const float4* s4 = (const float4*)psrc;
        #pragma unroll
        for (int i = 0; i < 4; i++) cp16(bb_addr + (i * 256 + tid) * 16, s4 + i * 256 + tid);
        CP_COMMIT();
    }
    for (int kc = 0; kc < 4; kc++) {
        if (kc < 3) {
            const float4* s4 = (const float4*)(psrc + (kc + 1) * 4096);
            uint32_t db = bb_addr + ((kc + 1) & 1) * 16384;
            #pragma unroll
            for (int i = 0; i < 4; i++) cp16(db + (i * 256 + tid) * 16, s4 + i * 256 + tid);
            CP_COMMIT();
            CP_WAIT1();
        } else CP_WAIT0();
        __syncthreads();
        const uint2* Bu = (const uint2*)(BB + (kc & 1) * 4096);
        const uint4* Au = (const uint4*)KB;
        #pragma unroll
        for (int kbl = 0; kbl < 4; kbl++) {
            uint32_t a[4][4], b[4][2];
            #pragma unroll
            for (int mt = 0; mt < 4; mt++)
                *(uint4*)a[mt] = Au[((kc * 4 + kbl) * 8 + mwarp * 4 + mt) * 32 + tg * 8 + g];
            #pragma unroll
            for (int nt = 0; nt < 4; nt++)
                *(uint2*)b[nt] = Bu[((kbl * 16 + nwarp * 4 + nt) * 4 + tg) * 8 + g];
            #pragma unroll
            for (int mt = 0; mt < 4; mt++)
                #pragma unroll
                for (int nt = 0; nt < 4; nt++)
                    mma8(d[mt][nt], a[mt], b[nt]);
        }
        __syncthreads();
    }

    float* Sx = QA;
    #pragma unroll
    for (int mt = 0; mt < 4; mt++) {
        #pragma unroll
        for (int nt = 0; nt < 4; nt++) {
            #pragma unroll
            for (int q = 0; q < 4; q++) {
                int row = mwarp * 64 + mt * 16 + g + (q >> 1) * 8;
                int col = nwarp * 32 + nt * 8 + 2 * tg + (q & 1);
                Sx[row * 132 + col] = d[mt][nt][q] + bp[col];
            }
        }
    }
    __syncthreads();
    {
        int c = tid & 127;
        #pragma unroll 2
        for (int it = 0; it < 64; it++) {
            int idx = it * 256 + tid;
            int n = idx >> 7;
            int t = tok_t(pair, n, lg, nWb, Wh, Ww);
            g_x1[t * 256 + co + c] = Sx[n * 132 + c] + g_xn[t * 256 + co + c];
        }
    }
}

// ===========================================================================
// MLP1 (fp16): LN2 + GEMM1 + GELU -> g_hh frag order.
// smem bytes: A halves 65536 @0 | B ring 3x16384 @65536 (LN overlay inside ring)
// ===========================================================================
#define M1_SMEM 114688
__global__ void __launch_bounds__(256, 1) mlp1_kernel(
    const float* __restrict__ x, const float* __restrict__ g2, const float* __restrict__ b2,
    const float* __restrict__ b1)
{
    extern __shared__ float sm[];
    __half* Ah   = (__half*)sm;          // 32768 halves (64KB)
    float* S32   = sm + 16384;           // [32][129] floats, overlay on B ring
    float* tmpS  = sm + 16384 + 4160;
    float* tmpQ  = tmpS + 256;
    float* mu    = tmpQ + 256;
    float* rs    = mu + 128;

    int tid = threadIdx.x, wid = tid >> 5, lane = tid & 31;
    int t0 = blockIdx.x * 128;
    int tblk = blockIdx.x;
    uint32_t bbase = smem_u32(sm) + 65536;

    // ---- LN2: stats + raw fp16 stash, 8 channel-blocks of 32 ----
    float accS = 0.f, accQ = 0.f;
    int nrole = tid & 127, part = tid >> 7;
    for (int cb = 0; cb < 8; cb++) {
        __syncthreads();
        #pragma unroll
        for (int it = 0; it < 16; it++) {
            int idx = it * 256 + tid;
            int n = idx & 127, cl = idx >> 7;
            S32[cl * 129 + n] = x[(size_t)(cb * 32 + cl) * HW + t0 + n];
        }
        __syncthreads();
        #pragma unroll
        for (int it = 0; it < 16; it++) {
            int idx = it * 256 + tid;
            int c = idx & 31, n = idx >> 5;
            S32[c * 129 + n] += g_x1[(size_t)(t0 + n) * 256 + cb * 32 + c];
        }
        __syncthreads();
        #pragma unroll
        for (int i = 0; i < 16; i++) {
            int cl = part * 16 + i;
            float v = S32[cl * 129 + nrole];
            accS += v; accQ += v * v;
            Ah[a16h(nrole, cb * 32 + cl)] = __float2half_rn(v);
        }
    }
    __syncthreads();
    tmpS[part * 128 + nrole] = accS;
    tmpQ[part * 128 + nrole] = accQ;
    __syncthreads();
    if (tid < 128) {
        float m = (tmpS[tid] + tmpS[128 + tid]) * (1.f / 256.f);
        mu[tid] = m;
        rs[tid] = rsqrtf((tmpQ[tid] + tmpQ[128 + tid]) * (1.f / 256.f) - m * m + 1e-5f);
    }
    __syncthreads();
    {
        int tok = tid & 127, hf2 = tid >> 7;
        float m = mu[tok], r = rs[tok];
        for (int c = hf2 * 128; c < hf2 * 128 + 128; c++) {
            int hi = a16h(tok, c);
            float v = __half2float(Ah[hi]);
            Ah[hi] = __float2half_rn((v - m) * r * __ldg(g2 + c) + __ldg(b2 + c));
        }
    }
    __syncthreads();

    // ---- GEMM1 (fp16), 3-slot B ring ----
    int mwarp = wid >> 2, nwarp = wid & 3;
    int g = lane >> 2, tg = lane & 3;
    const uint4* Au = (const uint4*)Ah;

    for (int jb = 0; jb < 4; jb++) {
        float d[4][8][4];
        #pragma unroll
        for (int mt = 0; mt < 4; mt++)
            #pragma unroll
            for (int nt = 0; nt < 8; nt++)
                #pragma unroll
                for (int q = 0; q < 4; q++) d[mt][nt][q] = 0.f;

        {
            const uint4* src = (const uint4*)g_w1h + (size_t)(jb * 8) * 1024;
            #pragma unroll
            for (int i = 0; i < 4; i++) cp16(bbase + (i * 256 + tid) * 16, src + i * 256 + tid);
            CP_COMMIT();
        }
        for (int kc = 0; kc < 8; kc++) {
            if (kc + 1 < 8) {
                const uint4* src = (const uint4*)g_w1h + (size_t)(jb * 8 + kc + 1) * 1024;
                uint32_t db = bbase + (uint32_t)(((kc + 1) % 3) * 16384);
                #pragma unroll
                for (int i = 0; i < 4; i++) cp16(db + (i * 256 + tid) * 16, src + i * 256 + tid);
            }
            CP_COMMIT();
            CP_WAIT1();
            __syncthreads();
            const uint2* Bu = (const uint2*)((char*)sm + 65536 + (kc % 3) * 16384);
            #pragma unroll
            for (int kb2 = 0; kb2 < 2; kb2++) {
                uint32_t a[4][4], b[8][2];
                #pragma unroll
                for (int mt = 0; mt < 4; mt++)
                    *(uint4*)a[mt] = Au[((kc * 2 + kb2) * 8 + mwarp * 4 + mt) * 32 + tg * 8 + g];
                #pragma unroll
                for (int nt = 0; nt < 8; nt++)
                    *(uint2*)b[nt] = Bu[((kb2 * 32 + nwarp * 8 + nt) * 4 + tg) * 8 + g];
                #pragma unroll
                for (int mt = 0; mt < 4; mt++)
                    #pragma unroll
                    for (int nt = 0; nt < 8; nt++)
                        mma16(d[mt][nt], a[mt], b[nt]);
            }
        }
        __syncthreads();
        // epilogue: bias + GELU -> g_hh fp16 frags
        #pragma unroll
        for (int mt = 0; mt < 4; mt++) {
            #pragma unroll
            for (int nt = 0; nt < 8; nt++) {
                int row0 = mwarp * 64 + mt * 16 + g;
                int col0 = jb * 256 + nwarp * 64 + nt * 8 + 2 * tg;
                float b0v = b1[col0], b1v = b1[col0 + 1];
                float v0 = gelu(d[mt][nt][0] + b0v);
                float v1 = gelu(d[mt][nt][1] + b1v);
                float v2 = gelu(d[mt][nt][2] + b0v);
                float v3 = gelu(d[mt][nt][3] + b1v);
                int chunk = tblk * 32 + (col0 >> 5);
                int slotu = (((col0 >> 4) & 1) * 8 + mwarp * 4 + mt) * 32 + tg * 8 + g;
                int base = chunk * 2048 + slotu * 4 + 2 * (nt & 1);
                g_hh[base]     = packh2(v0, v1);
                g_hh[base + 1] = packh2(v2, v3);
            }
        }
    }
}

// ===========================================================================
// MLP2 (fp16): GEMM2 + residual -> out (NCHW).
// smem bytes: A ring 4x8192 @0 | B ring 4x16384 @32768 | epi overlay S[256][69] @0
// ===========================================================================
#define M2_SMEM 98304
__global__ void __launch_bounds__(256, 1) mlp2_kernel(
    const float* __restrict__ x, const float* __restrict__ b2o, float* __restrict__ out)
{
    extern __shared__ float sm[];
    float* S = sm;

    int tid = threadIdx.x, wid = tid >> 5, lane = tid & 31;
    int t0 = blockIdx.x * 128;
    int tblk = blockIdx.x;
    int mwarp = wid >> 2, nwarp = wid & 3;
    int g = lane >> 2, tg = lane & 3;
    uint32_t abase = smem_u32(sm);
    uint32_t bbase = abase + 32768;

    float d[4][8][4];
    #pragma unroll
    for (int mt = 0; mt < 4; mt++)
        #pragma unroll
        for (int nt = 0; nt < 8; nt++)
            #pragma unroll
            for (int q = 0; q < 4; q++) d[mt][nt][q] = 0.f;

    // prologue: chunks 0,1
    #pragma unroll
    for (int p = 0; p < 2; p++) {
        const uint4* asrc = (const uint4*)g_hh + (size_t)(tblk * 32 + p) * 512;
        uint32_t da = abase + (uint32_t)(p * 8192);
        #pragma unroll
        for (int i = 0; i < 2; i++) cp16(da + (i * 256 + tid) * 16, asrc + i * 256 + tid);
        const uint4* bsrc = (const uint4*)g_w2h + (size_t)p * 1024;
        uint32_t db = bbase + (uint32_t)(p * 16384);
        #pragma unroll
        for (int i = 0; i < 4; i++) cp16(db + (i * 256 + tid) * 16, bsrc + i * 256 + tid);
        CP_COMMIT();
    }
    for (int kc = 0; kc < 32; kc++) {
        if (kc + 2 < 32) {
            int nx = kc + 2, slot = nx & 3;
            const uint4* asrc = (const uint4*)g_hh + (size_t)(tblk * 32 + nx) * 512;
            uint32_t da = abase + (uint32_t)(slot * 8192);
            #pragma unroll
            for (int i = 0; i < 2; i++) cp16(da + (i * 256 + tid) * 16, asrc + i * 256 + tid);
            const uint4* bsrc = (const uint4*)g_w2h + (size_t)nx * 1024;
            uint32_t db = bbase + (uint32_t)(slot * 16384);
            #pragma unroll
            for (int i = 0; i < 4; i++) cp16(db + (i * 256 + tid) * 16, bsrc + i * 256 + tid);
        }
        CP_COMMIT();
        CP_WAIT2();
        __syncthreads();
        const uint4* Au = (const uint4*)((char*)sm + (kc & 3) * 8192);
        const uint2* Bu = (const uint2*)((char*)sm + 32768 + (kc & 3) * 16384);
        #pragma unroll
        for (int kb2 = 0; kb2 < 2; kb2++) {
            uint32_t a[4][4], b[8][2];
            #pragma unroll
            for (int mt = 0; mt < 4; mt++)
                *(uint4*)a[mt] = Au[(kb2 * 8 + mwarp * 4 + mt) * 32 + tg * 8 + g];
            #pragma unroll
            for (int nt = 0; nt < 8; nt++)
                *(uint2*)b[nt] = Bu[((kb2 * 32 + nwarp * 8 + nt) * 4 + tg) * 8 + g];
            #pragma unroll
            for (int mt = 0; mt < 4; mt++)
                #pragma unroll
                for (int nt = 0; nt < 8; nt++)
                    mma16(d[mt][nt], a[mt], b[nt]);
        }
    }
    __syncthreads();

    // epilogue: 2 passes of 64 tokens, float staging of g_x1
    for (int p = 0; p < 2; p++) {
        __syncthreads();
        #pragma unroll 4
        for (int it = 0; it < 64; it++) {
            int idx = it * 256 + tid;
            int c = idx & 255, nl = idx >> 8;
            S[c * 69 + nl] = g_x1[(size_t)(t0 + p * 64 + nl) * 256 + c];
        }
        __syncthreads();
        if (mwarp == p) {
            #pragma unroll
            for (int mt = 0; mt < 4; mt++) {
                #pragma unroll
                for (int nt = 0; nt < 8; nt++) {
                    int row0 = mwarp * 64 + mt * 16 + g;
                    int col0 = nwarp * 64 + nt * 8 + 2 * tg;
                    #pragma unroll
                    for (int q = 0; q < 4; q++) {
                        int col = col0 + (q & 1);
                        int row = row0 + (q >> 1) * 8;
                        float v = d[mt][nt][q] + b2o[col]
                                + x[(size_t)col * HW + t0 + row] + S[col * 69 + (row - p * 64)];
                        out[(size_t)col * HW + t0 + row] = v;
                    }
                }
            }
        }
    }
}

// ---------------------------------------------------------------------------
extern "C" void kernel_launch(void* const* d_in, const int* in_sizes, int n_in,
                              void* d_out, int out_size) {
    const float* x        = (const float*)d_in[0];
    const float* norm1_g  = (const float*)d_in[1];
    const float* norm1_b  = (const float*)d_in[2];
    const float* qkv_r    = (const float*)d_in[3];
    const float* proj_r_w = (const float*)d_in[4];
    const float* proj_r_b = (const float*)d_in[5];
    const float* table_r  = (const float*)d_in[6];
    const float* qkv_a    = (const float*)d_in[7];
    const float* proj_a_w = (const float*)d_in[8];
    const float* proj_a_b = (const float*)d_in[9];
    const float* table_a  = (const float*)d_in[10];
    const float* norm2_g  = (const float*)d_in[11];
    const float* norm2_b  = (const float*)d_in[12];
    const float* mlp_w1   = (const float*)d_in[13];
    const float* mlp_b1   = (const float*)d_in[14];
    const float* mlp_w2   = (const float*)d_in[15];
    const float* mlp_b2   = (const float*)d_in[16];
    float* out = (float*)d_out;

    cudaFuncSetAttribute(attn_kernel, cudaFuncAttributeMaxDynamicSharedMemorySize, ATTN_SMEM);
    cudaFuncSetAttribute(mlp1_kernel, cudaFuncAttributeMaxDynamicSharedMemorySize, M1_SMEM);
    cudaFuncSetAttribute(mlp2_kernel, cudaFuncAttributeMaxDynamicSharedMemorySize, M2_SMEM);

    ln1_kernel<<<2048, 256>>>(x, norm1_g, norm1_b);
    bias_kernel<<<1, 256>>>(table_r, table_a);
    wfmt_kernel<<<512, 256>>>(mlp_w1, mlp_w2);
    wfmt2_kernel<<<512, 256>>>(qkv_r, proj_r_w, qkv_a, proj_a_w);
    attn_kernel<<<dim3(512, 2), 256, ATTN_SMEM>>>(proj_r_b, proj_a_b);
    mlp1_kernel<<<512, 256, M1_SMEM>>>(x, norm2_g, norm2_b, mlp_b1);
    mlp2_kernel<<<512, 256, M2_SMEM>>>(x, mlp_b2, out);
}

// round 12
// speedup vs baseline: 6.4729x; 1.2664x over previous
#include <cuda_runtime.h>
#include <cuda_fp16.h>
#include <cstdint>

#define HW 65536

__device__ float g_xn[HW * 256];
__device__ float g_x1[HW * 256];
__device__ float g_bias[2 * 2 * 64 * 64];
__device__ uint32_t g_hh[512 * 32 * 2048];  // H fp16 frags [tblk][kc][2048 u32]
__device__ uint2 g_w1h[65536];              // W1 fp16 frag chunks [jb*8+kc][2048]
__device__ uint2 g_w2h[65536];              // W2 fp16 frag chunks [kc][2048]
__device__ uint2 g_wqkvh[24576];            // Wqkv fp16 frags [br][nb][kc][1024]
__device__ uint2 g_wph[8192];               // Wproj fp16 frags [br][kc][1024]

__device__ __forceinline__ uint32_t smem_u32(const void* p) {
    uint32_t a;
    asm("{ .reg .u64 t; cvta.to.shared.u64 t, %1; cvt.u32.u64 %0, t; }" : "=r"(a) : "l"(p));
    return a;
}
__device__ __forceinline__ void cp16(uint32_t dst, const void* src) {
    asm volatile("cp.async.cg.shared.global [%0], [%1], 16;" :: "r"(dst), "l"(src));
}
#define CP_COMMIT() asm volatile("cp.async.commit_group;" ::: "memory")
#define CP_WAIT2()  asm volatile("cp.async.wait_group 2;" ::: "memory")
#define CP_WAIT1()  asm volatile("cp.async.wait_group 1;" ::: "memory")
#define CP_WAIT0()  asm volatile("cp.async.wait_group 0;" ::: "memory")

__device__ __forceinline__ void mma16(float* d, const uint32_t* a, const uint32_t* b) {
    asm volatile("mma.sync.aligned.m16n8k16.row.col.f32.f16.f16.f32 "
        "{%0,%1,%2,%3}, {%4,%5,%6,%7}, {%8,%9}, {%0,%1,%2,%3};"
        : "+f"(d[0]), "+f"(d[1]), "+f"(d[2]), "+f"(d[3])
        : "r"(a[0]), "r"(a[1]), "r"(a[2]), "r"(a[3]), "r"(b[0]), "r"(b[1]));
}
__device__ __forceinline__ uint32_t packh2(float lo, float hi) {
    __half2 h = __floats2half2_rn(lo, hi);
    return *(uint32_t*)&h;
}
__device__ __forceinline__ float gelu(float v) {
    return 0.5f * v * (1.f + erff(v * 0.70710678118f));
}
// fp16 A-fragment half-index (verified in mlp1): element (tok, k=c)
__device__ __forceinline__ int a16h(int tok, int c) {
    return ((((c >> 4) * 8 + (tok >> 4)) * 32 + ((c & 7) >> 1) * 8 + (tok & 7)) * 4
            + ((tok >> 3) & 1) + 2 * ((c >> 3) & 1)) * 2 + (c & 1);
}
// fp16 B-fragment half-index, N=128 region of k32 chunks (mirrors verified wfmt layout)
__device__ __forceinline__ int bfh(int k, int n) {
    return (k >> 5) * 4096
         + (((((k >> 4) & 1) * 16 + (n >> 3)) * 4 + ((k & 7) >> 1)) * 8 + (n & 7)) * 4
         + ((k >> 3) & 1) * 2 + (k & 1);
}

// ---------------- LN1 ----------------
__global__ void __launch_bounds__(256) ln1_kernel(const float* __restrict__ x,
                                                  const float* __restrict__ g,
                                                  const float* __restrict__ b) {
    __shared__ float s[256][33];
    __shared__ float mu[32], rs[32];
    int t0 = blockIdx.x * 32;
    int tid = threadIdx.x, lane = tid & 31, wid = tid >> 5;
    #pragma unroll
    for (int c = wid; c < 256; c += 8) s[c][lane] = x[c * HW + t0 + lane];
    __syncthreads();
    for (int it = 0; it < 4; it++) {
        int tok = wid * 4 + it;
        float sum = 0.f, sq = 0.f;
        #pragma unroll
        for (int j = 0; j < 8; j++) { float v = s[lane + 32 * j][tok]; sum += v; sq += v * v; }
        #pragma unroll
        for (int o = 16; o; o >>= 1) { sum += __shfl_down_sync(~0u, sum, o); sq += __shfl_down_sync(~0u, sq, o); }
        if (lane == 0) {
            float m = sum * (1.f / 256.f);
            mu[tok] = m; rs[tok] = rsqrtf(sq * (1.f / 256.f) - m * m + 1e-5f);
        }
    }
    __syncthreads();
    float gc = g[tid], bc = b[tid];
    for (int k = 0; k < 32; k++)
        g_xn[(t0 + k) * 256 + tid] = (s[tid][k] - mu[k]) * rs[k] * gc + bc;
}

// ---------------- bias tables ----------------
__global__ void bias_kernel(const float* __restrict__ tr, const float* __restrict__ ta) {
    for (int idx = threadIdx.x; idx < 16384; idx += blockDim.x) {
        int br = idx >> 13, rem = idx & 8191;
        int h = rem >> 12, n = (rem >> 6) & 63, m = rem & 63;
        int Wh = br ? 4 : 16, Ww = br ? 16 : 4, lg = br ? 4 : 2;
        int ridx = ((n >> lg) - (m >> lg) + Wh - 1) * (2 * Ww - 1) + ((n & (Ww - 1)) - (m & (Ww - 1)) + Ww - 1);
        g_bias[idx] = (br ? ta : tr)[ridx * 2 + h];
    }
}

// ---------------- MLP weight pre-format (fp16 frag order, verified) ----------------
__global__ void __launch_bounds__(256) wfmt_kernel(const float* __restrict__ W1,
                                                   const float* __restrict__ W2) {
    int idx = blockIdx.x * 256 + threadIdx.x;      // 0..131071
    const float* W; int ld, col, kbase; uint2* dst; int out;
    if (idx < 65536) {
        int g = idx & 7, tg = (idx >> 3) & 3, nt = (idx >> 5) & 31;
        int kb2 = (idx >> 10) & 1, kc = (idx >> 11) & 7, jb = idx >> 14;
        W = W1; ld = 1024;
        col = jb * 256 + nt * 8 + g;
        kbase = kc * 32 + kb2 * 16 + 2 * tg;
        out = (jb * 8 + kc) * 2048 + ((kb2 * 32 + nt) * 4 + tg) * 8 + g;
        dst = g_w1h;
    } else {
        int u = idx - 65536;
        int g = u & 7, tg = (u >> 3) & 3, nt = (u >> 5) & 31;
        int kb2 = (u >> 10) & 1, kc = u >> 11;
        W = W2; ld = 256;
        col = nt * 8 + g;
        kbase = kc * 32 + kb2 * 16 + 2 * tg;
        out = kc * 2048 + ((kb2 * 32 + nt) * 4 + tg) * 8 + g;
        dst = g_w2h;
    }
    float w0 = W[(size_t)kbase * ld + col];
    float w1 = W[(size_t)(kbase + 1) * ld + col];
    float w2 = W[(size_t)(kbase + 8) * ld + col];
    float w3 = W[(size_t)(kbase + 9) * ld + col];
    dst[out] = make_uint2(packh2(w0, w1), packh2(w2, w3));
}

// ---------------- attention weight pre-format (fp16 frags, N=128 chunks) ----------------
__global__ void __launch_bounds__(256) wfmt2h_kernel(
    const float* __restrict__ Wq_r, const float* __restrict__ Wp_r,
    const float* __restrict__ Wq_a, const float* __restrict__ Wp_a)
{
    int idx = blockIdx.x * 256 + threadIdx.x;      // 0..32767 (uint2 units)
    int i = idx & 1023;
    int g = i & 7, tg = (i >> 3) & 3, nt = (i >> 5) & 15, kb2 = i >> 9;
    const float* W; int ld, col, kc; uint2* dst; int out;
    if (idx < 24576) {
        int br = idx / 12288, r = idx % 12288;
        int nb = r >> 12; kc = (r >> 10) & 3;
        W = br ? Wq_a : Wq_r; ld = 384;
        col = nb * 128 + nt * 8 + g;
        dst = g_wqkvh; out = idx;
    } else {
        int j = idx - 24576;
        int br = j >> 12; kc = (j >> 10) & 3;
        W = br ? Wp_a : Wp_r; ld = 128;
        col = nt * 8 + g;
        dst = g_wph; out = j;
    }
    int kbase = kc * 32 + kb2 * 16 + 2 * tg;
    float w0 = W[(size_t)kbase * ld + col];
    float w1 = W[(size_t)(kbase + 1) * ld + col];
    float w2 = W[(size_t)(kbase + 8) * ld + col];
    float w3 = W[(size_t)(kbase + 9) * ld + col];
    dst[out] = make_uint2(packh2(w0, w1), packh2(w2, w3));
}

// ===========================================================================
// fp16 tensor-core window attention. CTA = 2 windows (128 tok), 2 CTA/SM.
// smem bytes: AXh (X a-frags -> V b-frags) [0,32768)
//             QAh (X plain / Q a-frags -> P a-frags) [32768,65536)
//             KBh (K b-frags -> red -> O a-frags) [65536,98304)
//             BB  (weight staging 2x8192) [98304,114688)
// ===========================================================================
#define ATTN_SMEM 114688
__device__ __forceinline__ int tok_t(int pair, int n, int lg, int nWb, int Wh, int Ww) {
    int w = n >> 6, nl = n & 63;
    int wi = pair * 2 + w;
    int hb = wi / nWb, wb = wi - hb * nWb;
    return ((hb * Wh + (nl >> lg)) << 8) + wb * Ww + (nl & (Ww - 1));
}

__global__ void __launch_bounds__(256, 2) attn_kernel(
    const float* __restrict__ bp_r, const float* __restrict__ bp_a)
{
    extern __shared__ float sm[];
    __half*  AXh = (__half*)sm;
    __half*  QAh = (__half*)((char*)sm + 32768);
    __half*  KBh = (__half*)((char*)sm + 65536);
    uint32_t bb_addr = smem_u32(sm) + 98304;
    float* red_max = (float*)KBh;
    float* red_sum = (float*)KBh + 512;

    int br = blockIdx.y;
    int co = br ? 128 : 0, lg = br ? 4 : 2;
    int Ww = 1 << lg, nWb = br ? 16 : 64, Wh = br ? 4 : 16;
    const float* bp = br ? bp_a : bp_r;
    int pair = blockIdx.x;
    int tid = threadIdx.x, wid = tid >> 5, lane = tid & 31;
    int g = lane >> 2, tg = lane & 3;

    // ---- phase 0a: X plain half tile (pitch 130) into QAh ----
    {
        int k = tid & 127;
        #pragma unroll 2
        for (int it = 0; it < 64; it++) {
            int idx = it * 256 + tid;
            int n = idx >> 7;
            int t = tok_t(pair, n, lg, nWb, Wh, Ww);
            QAh[k * 130 + n] = __float2half_rn(g_xn[t * 256 + co + k]);
        }
    }
    __syncthreads();
    // ---- phase 0b: scatter to fp16 a-frags in AXh ----
    {
        uint4* AXu4 = (uint4*)AXh;
        #pragma unroll
        for (int i = 0; i < 8; i++) {
            int p = wid * 8 + i;
            int kb = p >> 3, mt = p & 7;
            int c0 = kb * 16 + 2 * tg, row = mt * 16 + g;
            uint4 u;
            u.x = packh2(__half2float(QAh[c0 * 130 + row]),       __half2float(QAh[(c0 + 1) * 130 + row]));
            u.y = packh2(__half2float(QAh[c0 * 130 + row + 8]),   __half2float(QAh[(c0 + 1) * 130 + row + 8]));
            u.z = packh2(__half2float(QAh[(c0 + 8) * 130 + row]), __half2float(QAh[(c0 + 9) * 130 + row]));
            u.w = packh2(__half2float(QAh[(c0 + 8) * 130 + row + 8]), __half2float(QAh[(c0 + 9) * 130 + row + 8]));
            AXu4[(kb * 8 + mt) * 32 + tg * 8 + g] = u;
        }
    }
    __syncthreads();

    // ---- phase 1: QKV GEMM, 12 chunks (k32 x n128, 8KB fp16) ----
    int mwarp = wid >> 2, nwarp = wid & 3;
    float d[4][4][4];
    #pragma unroll
    for (int mt = 0; mt < 4; mt++)
        #pragma unroll
        for (int nt = 0; nt < 4; nt++)
            #pragma unroll
            for (int q = 0; q < 4; q++) d[mt][nt][q] = 0.f;

    const uint4* wsrc = (const uint4*)(g_wqkvh + (size_t)(br * 12) * 1024);
    {
        #pragma unroll
        for (int i = 0; i < 2; i++) cp16(bb_addr + (i * 256 + tid) * 16, wsrc + i * 256 + tid);
        CP_COMMIT();
    }
    for (int s = 0; s < 12; s++) {
        if (s < 11) {
            const uint4* s4 = wsrc + (s + 1) * 512;
            uint32_t db = bb_addr + ((s + 1) & 1) * 8192;
            #pragma unroll
            for (int i = 0; i < 2; i++) cp16(db + (i * 256 + tid) * 16, s4 + i * 256 + tid);
            CP_COMMIT();
            CP_WAIT1();
        } else CP_WAIT0();
        __syncthreads();
        int kc = s & 3;
        const uint2* Bu = (const uint2*)((char*)sm + 98304 + (s & 1) * 8192);
        const uint4* Au = (const uint4*)AXh;
        #pragma unroll
        for (int kb2 = 0; kb2 < 2; kb2++) {
            uint32_t a[4][4], b[4][2];
            #pragma unroll
            for (int mt = 0; mt < 4; mt++)
                *(uint4*)a[mt] = Au[((kc * 2 + kb2) * 8 + mwarp * 4 + mt) * 32 + tg * 8 + g];
            #pragma unroll
            for (int nt = 0; nt < 4; nt++)
                *(uint2*)b[nt] = Bu[((kb2 * 16 + nwarp * 4 + nt) * 4 + tg) * 8 + g];
            #pragma unroll
            for (int mt = 0; mt < 4; mt++)
                #pragma unroll
                for (int nt = 0; nt < 4; nt++)
                    mma16(d[mt][nt], a[mt], b[nt]);
        }
        __syncthreads();
        if (kc == 3) {
            int nb = s >> 2;
            uint32_t* Qw = (uint32_t*)QAh;
            uint32_t* Kw = (uint32_t*)KBh;
            #pragma unroll
            for (int mt = 0; mt < 4; mt++) {
                #pragma unroll
                for (int nt = 0; nt < 4; nt++) {
                    int row = mwarp * 64 + mt * 16 + g;
                    int col0 = nwarp * 32 + nt * 8 + 2 * tg;
                    if (nb == 0) {
                        Qw[a16h(row, col0) >> 1]     = packh2(d[mt][nt][0], d[mt][nt][1]);
                        Qw[a16h(row + 8, col0) >> 1] = packh2(d[mt][nt][2], d[mt][nt][3]);
                    } else if (nb == 1) {
                        Kw[bfh(col0, row) >> 1]      = packh2(d[mt][nt][0], d[mt][nt][1]);
                        Kw[bfh(col0, row + 8) >> 1]  = packh2(d[mt][nt][2], d[mt][nt][3]);
                    } else {
                        AXh[bfh(row, col0)]         = __float2half_rn(d[mt][nt][0]);
                        AXh[bfh(row, col0 + 1)]     = __float2half_rn(d[mt][nt][1]);
                        AXh[bfh(row + 8, col0)]     = __float2half_rn(d[mt][nt][2]);
                        AXh[bfh(row + 8, col0 + 1)] = __float2half_rn(d[mt][nt][3]);
                    }
                    #pragma unroll
                    for (int q = 0; q < 4; q++) d[mt][nt][q] = 0.f;
                }
            }
            __syncthreads();
        }
    }

    // ---- phase 2: S = Q K^T (fp16), softmax ----
    int w = wid >> 2, h = (wid >> 1) & 1, half = wid & 1;
    {
        const uint4* Qa = (const uint4*)QAh;
        const uint2* Kb = (const uint2*)KBh;
        #pragma unroll
        for (int kbl = 0; kbl < 4; kbl++) {
            uint32_t a[4][4], b[4][2];
            #pragma unroll
            for (int mt = 0; mt < 4; mt++)
                *(uint4*)a[mt] = Qa[((h * 4 + kbl) * 8 + w * 4 + mt) * 32 + tg * 8 + g];
            int kc2 = h * 2 + (kbl >> 1), kb2 = kbl & 1;
            #pragma unroll
            for (int nt = 0; nt < 4; nt++)
                *(uint2*)b[nt] = Kb[kc2 * 1024 + ((kb2 * 16 + w * 8 + half * 4 + nt) * 4 + tg) * 8 + g];
            #pragma unroll
            for (int mt = 0; mt < 4; mt++)
                #pragma unroll
                for (int nt = 0; nt < 4; nt++)
                    mma16(d[mt][nt], a[mt], b[nt]);
        }
    }
    __syncthreads();   // K reads done; KBh start reusable for red

    const float* bias = g_bias + (br * 2 + h) * 4096;
    #pragma unroll
    for (int mt = 0; mt < 4; mt++) {
        #pragma unroll
        for (int nt = 0; nt < 4; nt++) {
            int rr = mt * 16 + g, cc = half * 32 + nt * 8 + 2 * tg;
            float2 b0 = *(const float2*)(bias + rr * 64 + cc);
            float2 b1 = *(const float2*)(bias + (rr + 8) * 64 + cc);
            d[mt][nt][0] = d[mt][nt][0] * 0.125f + b0.x;
            d[mt][nt][1] = d[mt][nt][1] * 0.125f + b0.y;
            d[mt][nt][2] = d[mt][nt][2] * 0.125f + b1.x;
            d[mt][nt][3] = d[mt][nt][3] * 0.125f + b1.y;
        }
    }
    int whb = ((w * 2 + h) * 2 + half) * 64;
    #pragma unroll
    for (int mt = 0; mt < 4; mt++) {
        float m0 = -1e30f, m1 = -1e30f;
        #pragma unroll
        for (int nt = 0; nt < 4; nt++) {
            m0 = fmaxf(m0, fmaxf(d[mt][nt][0], d[mt][nt][1]));
            m1 = fmaxf(m1, fmaxf(d[mt][nt][2], d[mt][nt][3]));
        }
        m0 = fmaxf(m0, __shfl_xor_sync(~0u, m0, 1)); m0 = fmaxf(m0, __shfl_xor_sync(~0u, m0, 2));
        m1 = fmaxf(m1, __shfl_xor_sync(~0u, m1, 1)); m1 = fmaxf(m1, __shfl_xor_sync(~0u, m1, 2));
        red_max[whb + mt * 16 + g] = m0;
        red_max[whb + mt * 16 + g + 8] = m1;
    }
    __syncthreads();
    int whb0 = ((w * 2 + h) * 2) * 64;
    #pragma unroll
    for (int mt = 0; mt < 4; mt++) {
        float M0 = fmaxf(red_max[whb0 + mt * 16 + g], red_max[whb0 + 64 + mt * 16 + g]);
        float M1 = fmaxf(red_max[whb0 + mt * 16 + g + 8], red_max[whb0 + 64 + mt * 16 + g + 8]);
        float s0 = 0.f, s1 = 0.f;
        #pragma unroll
        for (int nt = 0; nt < 4; nt++) {
            d[mt][nt][0] = expf(d[mt][nt][0] - M0); s0 += d[mt][nt][0];
            d[mt][nt][1] = expf(d[mt][nt][1] - M0); s0 += d[mt][nt][1];
            d[mt][nt][2] = expf(d[mt][nt][2] - M1); s1 += d[mt][nt][2];
            d[mt][nt][3] = expf(d[mt][nt][3] - M1); s1 += d[mt][nt][3];
        }
        s0 += __shfl_xor_sync(~0u, s0, 1); s0 += __shfl_xor_sync(~0u, s0, 2);
        s1 += __shfl_xor_sync(~0u, s1, 1); s1 += __shfl_xor_sync(~0u, s1, 2);
        red_sum[whb + mt * 16 + g] = s0;
        red_sum[whb + mt * 16 + g + 8] = s1;
    }
    __syncthreads();
    {
        uint32_t* Pw = (uint32_t*)QAh;
        #pragma unroll
        for (int mt = 0; mt < 4; mt++) {
            float i0 = 1.f / (red_sum[whb0 + mt * 16 + g] + red_sum[whb0 + 64 + mt * 16 + g]);
            float i1 = 1.f / (red_sum[whb0 + mt * 16 + g + 8] + red_sum[whb0 + 64 + mt * 16 + g + 8]);
            #pragma unroll
            for (int nt = 0; nt < 4; nt++) {
                int row = w * 64 + mt * 16 + g;
                int m0 = half * 32 + nt * 8 + 2 * tg;
                Pw[a16h(row, h * 64 + m0) >> 1]     = packh2(d[mt][nt][0] * i0, d[mt][nt][1] * i0);
                Pw[a16h(row + 8, h * 64 + m0) >> 1] = packh2(d[mt][nt][2] * i1, d[mt][nt][3] * i1);
                #pragma unroll
                for (int q = 0; q < 4; q++) d[mt][nt][q] = 0.f;
            }
        }
    }
    __syncthreads();

    // ---- phase 3: O = P V (fp16) ----
    {
        const uint4* Pa = (const uint4*)QAh;
        const uint2* Vb = (const uint2*)AXh;
        #pragma unroll
        for (int kbl = 0; kbl < 4; kbl++) {
            uint32_t a[4][4], b[4][2];
            #pragma unroll
            for (int mt = 0; mt < 4; mt++)
                *(uint4*)a[mt] = Pa[((h * 4 + kbl) * 8 + w * 4 + mt) * 32 + tg * 8 + g];
            int kc2 = w * 2 + (kbl >> 1), kb2 = kbl & 1;
            #pragma unroll
            for (int nt = 0; nt < 4; nt++)
                *(uint2*)b[nt] = Vb[kc2 * 1024 + ((kb2 * 16 + h * 8 + half * 4 + nt) * 4 + tg) * 8 + g];
            #pragma unroll
            for (int mt = 0; mt < 4; mt++)
                #pragma unroll
                for (int nt = 0; nt < 4; nt++)
                    mma16(d[mt][nt], a[mt], b[nt]);
        }
    }
    __syncthreads();   // P/V reads done
    {
        uint32_t* Ow = (uint32_t*)KBh;
        #pragma unroll
        for (int mt = 0; mt < 4; mt++) {
            #pragma unroll
            for (int nt = 0; nt < 4; nt++) {
                int row = w * 64 + mt * 16 + g;
                int col0 = h * 64 + half * 32 + nt * 8 + 2 * tg;
                Ow[a16h(row, col0) >> 1]     = packh2(d[mt][nt][0], d[mt][nt][1]);
                Ow[a16h(row + 8, col0) >> 1] = packh2(d[mt][nt][2], d[mt][nt][3]);
                #pragma unroll
                for (int q = 0; q < 4; q++) d[mt][nt][q] = 0.f;
            }
        }
    }
    __syncthreads();

    // ---- phase 4: proj = O @ Wp, 4 chunks (k32 x n128) ----
    const uint4* psrc = (const uint4*)(g_wph + (size_t)(br * 4) * 1024);
    {
        #pragma unroll
        for (int i = 0; i < 2; i++) cp16(bb_addr + (i * 256 + tid) * 16, psrc + i * 256 + tid);
        CP_COMMIT();
    }
    for (int kc = 0; kc < 4; kc++) {
        if (kc < 3) {
            const uint4* s4 = psrc + (kc + 1) * 512;
            uint32_t db = bb_addr + ((kc + 1) & 1) * 8192;
            #pragma unroll
            for (int i = 0; i < 2; i++) cp16(db + (i * 256 + tid) * 16, s4 + i * 256 + tid);
            CP_COMMIT();
            CP_WAIT1();
        } else CP_WAIT0();
        __syncthreads();
        const uint2* Bu = (const uint2*)((char*)sm + 98304 + (kc & 1) * 8192);
        const uint4* Au = (const uint4*)KBh;
        #pragma unroll
        for (int kb2 = 0; kb2 < 2; kb2++) {
            uint32_t a[4][4], b[4][2];
            #pragma unroll
            for (int mt = 0; mt < 4; mt++)
                *(uint4*)a[mt] = Au[((kc * 2 + kb2) * 8 + mwarp * 4 + mt) * 32 + tg * 8 + g];
            #pragma unroll
            for (int nt = 0; nt < 4; nt++)
                *(uint2*)b[nt] = Bu[((kb2 * 16 + nwarp * 4 + nt) * 4 + tg) * 8 + g];
            #pragma unroll
            for (int mt = 0; mt < 4; mt++)
                #pragma unroll
                for (int nt = 0; nt < 4; nt++)
                    mma16(d[mt][nt], a[mt], b[nt]);
        }
        __syncthreads();
    }

    // ---- epilogue: two 64-token passes, stage in AXh (floats) ----
    float* Sf = (float*)AXh;
    for (int p = 0; p < 2; p++) {
        __syncthreads();
        if (mwarp == p) {
            #pragma unroll
            for (int mt = 0; mt < 4; mt++) {
                #pragma unroll
                for (int nt = 0; nt < 4; nt++) {
                    #pragma unroll
                    for (int q = 0; q < 4; q++) {
                        int row = mt * 16 + g + (q >> 1) * 8;
                        int col = nwarp * 32 + nt * 8 + 2 * tg + (q & 1);
                        Sf[row * 132 + col] = d[mt][nt][q] + bp[col];
                    }
                }
            }
        }
        __syncthreads();
        int c = tid & 127;
        #pragma unroll
        for (int it = 0; it < 32; it++) {
            int idx = it * 256 + tid;
            int nl = idx >> 7;
            int n = p * 64 + nl;
            int t = tok_t(pair, n, lg, nWb, Wh, Ww);
            g_x1[t * 256 + co + c] = Sf[nl * 132 + c] + g_xn[t * 256 + co + c];
        }
    }
}

// ===========================================================================
// MLP1 (fp16): LN2 + GEMM1 + GELU -> g_hh frag order. (unchanged R11)
// ===========================================================================
#define M1_SMEM 114688
__global__ void __launch_bounds__(256, 1) mlp1_kernel(
    const float* __restrict__ x, const float* __restrict__ g2, const float* __restrict__ b2,
    const float* __restrict__ b1)
{
    extern __shared__ float sm[];
    __half* Ah   = (__half*)sm;
    float* S32   = sm + 16384;
    float* tmpS  = sm + 16384 + 4160;
    float* tmpQ  = tmpS + 256;
    float* mu    = tmpQ + 256;
    float* rs    = mu + 128;

    int tid = threadIdx.x, wid = tid >> 5, lane = tid & 31;
    int t0 = blockIdx.x * 128;
    int tblk = blockIdx.x;
    uint32_t bbase = smem_u32(sm) + 65536;

    float accS = 0.f, accQ = 0.f;
    int nrole = tid & 127, part = tid >> 7;
    for (int cb = 0; cb < 8; cb++) {
        __syncthreads();
        #pragma unroll
        for (int it = 0; it < 16; it++) {
            int idx = it * 256 + tid;
            int n = idx & 127, cl = idx >> 7;
            S32[cl * 129 + n] = x[(size_t)(cb * 32 + cl) * HW + t0 + n];
        }
        __syncthreads();
        #pragma unroll
        for (int it = 0; it < 16; it++) {
            int idx = it * 256 + tid;
            int c = idx & 31, n = idx >> 5;
            S32[c * 129 + n] += g_x1[(size_t)(t0 + n) * 256 + cb * 32 + c];
        }
        __syncthreads();
        #pragma unroll
        for (int i = 0; i < 16; i++) {
            int cl = part * 16 + i;
            float v = S32[cl * 129 + nrole];
            accS += v; accQ += v * v;
            Ah[a16h(nrole, cb * 32 + cl)] = __float2half_rn(v);
        }
    }
    __syncthreads();
    tmpS[part * 128 + nrole] = accS;
    tmpQ[part * 128 + nrole] = accQ;
    __syncthreads();
    if (tid < 128) {
        float m = (tmpS[tid] + tmpS[128 + tid]) * (1.f / 256.f);
        mu[tid] = m;
        rs[tid] = rsqrtf((tmpQ[tid] + tmpQ[128 + tid]) * (1.f / 256.f) - m * m + 1e-5f);
    }
    __syncthreads();
    {
        int tok = tid & 127, hf2 = tid >> 7;
        float m = mu[tok], r = rs[tok];
        for (int c = hf2 * 128; c < hf2 * 128 + 128; c++) {
            int hi = a16h(tok, c);
            float v = __half2float(Ah[hi]);
            Ah[hi] = __float2half_rn((v - m) * r * __ldg(g2 + c) + __ldg(b2 + c));
        }
    }
    __syncthreads();

    int mwarp = wid >> 2, nwarp = wid & 3;
    int g = lane >> 2, tg = lane & 3;
    const uint4* Au = (const uint4*)Ah;

    for (int jb = 0; jb < 4; jb++) {
        float d[4][8][4];
        #pragma unroll
        for (int mt = 0; mt < 4; mt++)
            #pragma unroll
            for (int nt = 0; nt < 8; nt++)
                #pragma unroll
                for (int q = 0; q < 4; q++) d[mt][nt][q] = 0.f;

        {
            const uint4* src = (const uint4*)g_w1h + (size_t)(jb * 8) * 1024;
            #pragma unroll
            for (int i = 0; i < 4; i++) cp16(bbase + (i * 256 + tid) * 16, src + i * 256 + tid);
            CP_COMMIT();
        }
        for (int kc = 0; kc < 8; kc++) {
            if (kc + 1 < 8) {
                const uint4* src = (const uint4*)g_w1h + (size_t)(jb * 8 + kc + 1) * 1024;
                uint32_t db = bbase + (uint32_t)(((kc + 1) % 3) * 16384);
                #pragma unroll
                for (int i = 0; i < 4; i++) cp16(db + (i * 256 + tid) * 16, src + i * 256 + tid);
            }
            CP_COMMIT();
            CP_WAIT1();
            __syncthreads();
            const uint2* Bu = (const uint2*)((char*)sm + 65536 + (kc % 3) * 16384);
            #pragma unroll
            for (int kb2 = 0; kb2 < 2; kb2++) {
                uint32_t a[4][4], b[8][2];
                #pragma unroll
                for (int mt = 0; mt < 4; mt++)
                    *(uint4*)a[mt] = Au[((kc * 2 + kb2) * 8 + mwarp * 4 + mt) * 32 + tg * 8 + g];
                #pragma unroll
                for (int nt = 0; nt < 8; nt++)
                    *(uint2*)b[nt] = Bu[((kb2 * 32 + nwarp * 8 + nt) * 4 + tg) * 8 + g];
                #pragma unroll
                for (int mt = 0; mt < 4; mt++)
                    #pragma unroll
                    for (int nt = 0; nt < 8; nt++)
                        mma16(d[mt][nt], a[mt], b[nt]);
            }
        }
        __syncthreads();
        #pragma unroll
        for (int mt = 0; mt < 4; mt++) {
            #pragma unroll
            for (int nt = 0; nt < 8; nt++) {
                int row0 = mwarp * 64 + mt * 16 + g;
                int col0 = jb * 256 + nwarp * 64 + nt * 8 + 2 * tg;
                float b0v = b1[col0], b1v = b1[col0 + 1];
                float v0 = gelu(d[mt][nt][0] + b0v);
                float v1 = gelu(d[mt][nt][1] + b1v);
                float v2 = gelu(d[mt][nt][2] + b0v);
                float v3 = gelu(d[mt][nt][3] + b1v);
                int chunk = tblk * 32 + (col0 >> 5);
                int slotu = (((col0 >> 4) & 1) * 8 + mwarp * 4 + mt) * 32 + tg * 8 + g;
                int base = chunk * 2048 + slotu * 4 + 2 * (nt & 1);
                g_hh[base]     = packh2(v0, v1);
                g_hh[base + 1] = packh2(v2, v3);
            }
        }
    }
}

// ===========================================================================
// MLP2 (fp16): GEMM2 + residual -> out (NCHW). (unchanged R11)
// ===========================================================================
#define M2_SMEM 98304
__global__ void __launch_bounds__(256, 1) mlp2_kernel(
    const float* __restrict__ x, const float* __restrict__ b2o, float* __restrict__ out)
{
    extern __shared__ float sm[];
    float* S = sm;

    int tid = threadIdx.x, wid = tid >> 5, lane = tid & 31;
    int t0 = blockIdx.x * 128;
    int tblk = blockIdx.x;
    int mwarp = wid >> 2, nwarp = wid & 3;
    int g = lane >> 2, tg = lane & 3;
    uint32_t abase = smem_u32(sm);
    uint32_t bbase = abase + 32768;

    float d[4][8][4];
    #pragma unroll
    for (int mt = 0; mt < 4; mt++)
        #pragma unroll
        for (int nt = 0; nt < 8; nt++)
            #pragma unroll
            for (int q = 0; q < 4; q++) d[mt][nt][q] = 0.f;

    #pragma unroll
    for (int p = 0; p < 2; p++) {
        const uint4* asrc = (const uint4*)g_hh + (size_t)(tblk * 32 + p) * 512;
        uint32_t da = abase + (uint32_t)(p * 8192);
        #pragma unroll
        for (int i = 0; i < 2; i++) cp16(da + (i * 256 + tid) * 16, asrc + i * 256 + tid);
        const uint4* bsrc = (const uint4*)g_w2h + (size_t)p * 1024;
        uint32_t db = bbase + (uint32_t)(p * 16384);
        #pragma unroll
        for (int i = 0; i < 4; i++) cp16(db + (i * 256 + tid) * 16, bsrc + i * 256 + tid);
        CP_COMMIT();
    }
    for (int kc = 0; kc < 32; kc++) {
        if (kc + 2 < 32) {
            int nx = kc + 2, slot = nx & 3;
            const uint4* asrc = (const uint4*)g_hh + (size_t)(tblk * 32 + nx) * 512;
            uint32_t da = abase + (uint32_t)(slot * 8192);
            #pragma unroll
            for (int i = 0; i < 2; i++) cp16(da + (i * 256 + tid) * 16, asrc + i * 256 + tid);
            const uint4* bsrc = (const uint4*)g_w2h + (size_t)nx * 1024;
            uint32_t db = bbase + (uint32_t)(slot * 16384);
            #pragma unroll
            for (int i = 0; i < 4; i++) cp16(db + (i * 256 + tid) * 16, bsrc + i * 256 + tid);
        }
        CP_COMMIT();
        CP_WAIT2();
        __syncthreads();
        const uint4* Au = (const uint4*)((char*)sm + (kc & 3) * 8192);
        const uint2* Bu = (const uint2*)((char*)sm + 32768 + (kc & 3) * 16384);
        #pragma unroll
        for (int kb2 = 0; kb2 < 2; kb2++) {
            uint32_t a[4][4], b[8][2];
            #pragma unroll
            for (int mt = 0; mt < 4; mt++)
                *(uint4*)a[mt] = Au[(kb2 * 8 + mwarp * 4 + mt) * 32 + tg * 8 + g];
            #pragma unroll
            for (int nt = 0; nt < 8; nt++)
                *(uint2*)b[nt] = Bu[((kb2 * 32 + nwarp * 8 + nt) * 4 + tg) * 8 + g];
            #pragma unroll
            for (int mt = 0; mt < 4; mt++)
                #pragma unroll
                for (int nt = 0; nt < 8; nt++)
                    mma16(d[mt][nt], a[mt], b[nt]);
        }
    }
    __syncthreads();

    for (int p = 0; p < 2; p++) {
        __syncthreads();
        #pragma unroll 4
        for (int it = 0; it < 64; it++) {
            int idx = it * 256 + tid;
            int c = idx & 255, nl = idx >> 8;
            S[c * 69 + nl] = g_x1[(size_t)(t0 + p * 64 + nl) * 256 + c];
        }
        __syncthreads();
        if (mwarp == p) {
            #pragma unroll
            for (int mt = 0; mt < 4; mt++) {
                #pragma unroll
                for (int nt = 0; nt < 8; nt++) {
                    int row0 = mwarp * 64 + mt * 16 + g;
                    int col0 = nwarp * 64 + nt * 8 + 2 * tg;
                    #pragma unroll
                    for (int q = 0; q < 4; q++) {
                        int col = col0 + (q & 1);
                        int row = row0 + (q >> 1) * 8;
                        float v = d[mt][nt][q] + b2o[col]
                                + x[(size_t)col * HW + t0 + row] + S[col * 69 + (row - p * 64)];
                        out[(size_t)col * HW + t0 + row] = v;
                    }
                }
            }
        }
    }
}

// ---------------------------------------------------------------------------
extern "C" void kernel_launch(void* const* d_in, const int* in_sizes, int n_in,
                              void* d_out, int out_size) {
    const float* x        = (const float*)d_in[0];
    const float* norm1_g  = (const float*)d_in[1];
    const float* norm1_b  = (const float*)d_in[2];
    const float* qkv_r    = (const float*)d_in[3];
    const float* proj_r_w = (const float*)d_in[4];
    const float* proj_r_b = (const float*)d_in[5];
    const float* table_r  = (const float*)d_in[6];
    const float* qkv_a    = (const float*)d_in[7];
    const float* proj_a_w = (const float*)d_in[8];
    const float* proj_a_b = (const float*)d_in[9];
    const float* table_a  = (const float*)d_in[10];
    const float* norm2_g  = (const float*)d_in[11];
    const float* norm2_b  = (const float*)d_in[12];
    const float* mlp_w1   = (const float*)d_in[13];
    const float* mlp_b1   = (const float*)d_in[14];
    const float* mlp_w2   = (const float*)d_in[15];
    const float* mlp_b2   = (const float*)d_in[16];
    float* out = (float*)d_out;

    cudaFuncSetAttribute(attn_kernel, cudaFuncAttributeMaxDynamicSharedMemorySize, ATTN_SMEM);
    cudaFuncSetAttribute(mlp1_kernel, cudaFuncAttributeMaxDynamicSharedMemorySize, M1_SMEM);
    cudaFuncSetAttribute(mlp2_kernel, cudaFuncAttributeMaxDynamicSharedMemorySize, M2_SMEM);

    ln1_kernel<<<2048, 256>>>(x, norm1_g, norm1_b);
    bias_kernel<<<1, 256>>>(table_r, table_a);
    wfmt_kernel<<<512, 256>>>(mlp_w1, mlp_w2);
    wfmt2h_kernel<<<128, 256>>>(qkv_r, proj_r_w, qkv_a, proj_a_w);
    attn_kernel<<<dim3(512, 2), 256, ATTN_SMEM>>>(proj_r_b, proj_a_b);
    mlp1_kernel<<<512, 256, M1_SMEM>>>(x, norm2_g, norm2_b, mlp_b1);
    mlp2_kernel<<<512, 256, M2_SMEM>>>(x, mlp_b2, out);
}